// round 2
// baseline (speedup 1.0000x reference)
#include <cuda_runtime.h>
#include <math.h>

// Problem constants
#define BB   16
#define NN_  768
#define FF   512
#define NBB  256
#define HH   8
#define DD   64

// ---------------------------------------------------------------------------
// Scratch: single __device__ global (allocation-free per harness rules)
// offsets in floats
// ---------------------------------------------------------------------------
static const long long OFF_QKVB = 0;                      // [256,1536]
static const long long OFF_KVI  = OFF_QKVB + 256LL*1536;  // [16*768,1024] (k|v)
static const long long OFF_QJ   = OFF_KVI  + 16LL*768*1024;   // [16*768,512]
static const long long OFF_S1   = OFF_QJ   + 16LL*768*512;    // [16,256,768]
static const long long OFF_AIB1 = OFF_S1   + 16LL*256*768;    // [16,256,512]
static const long long OFF_S2   = OFF_AIB1 + 16LL*256*512;    // [16,768,256]
static const long long OFF_ABJ  = OFF_S2   + 16LL*768*256;    // [16,768,512]
static const long long OFF_S3   = OFF_ABJ  + 16LL*768*512;    // [16,768,256]
static const long long OFF_AIJ  = OFF_S3   + 16LL*768*256;    // [16,768,512]
static const long long OFF_F    = OFF_AIJ  + 16LL*768*512;    // [16,768,512]
static const long long OFF_M    = OFF_F    + 16LL*768*512;    // [16,768,512]
static const long long OFF_H    = OFF_M    + 16LL*768*512;    // [16,768,512]
static const long long OFF_QKV  = OFF_H    + 16LL*768*512;    // [16*768,1536]
static const long long OFF_Q    = OFF_QKV  + 16LL*768*1536;   // [16,8,768,64]
static const long long OFF_K2   = OFF_Q    + 16LL*8*768*64;
static const long long OFF_V2   = OFF_K2   + 16LL*8*768*64;
static const long long OFF_S4   = OFF_V2   + 16LL*8*768*64;   // [128,768,768]
static const long long OFF_HH2  = OFF_S4   + 128LL*768*768;   // [16,8,768,64]
static const long long OFF_HC   = OFF_HH2  + 16LL*8*768*64;   // [16*768,512]
static const long long TOTAL_FL = OFF_HC   + 16LL*768*512;

__device__ float g_buf[TOTAL_FL];

// ---------------------------------------------------------------------------
// Tiled fp32 GEMM: C[bz] = alpha * A[bz] @ op(B[bz]) (+C if beta) (+bias) (act)
// 64x64 tile, KT=16, 256 threads, 4x4 per thread.
// All M,N multiples of 64; K multiple of 16 (guaranteed by problem shapes).
// ---------------------------------------------------------------------------
#define TILE 64
#define KT   16

template<bool TRANSB>
__global__ void __launch_bounds__(256)
gemm_kernel(int M, int N, int K,
            const float* __restrict__ A, int lda, long long sA,
            const float* __restrict__ B, int ldb, long long sB,
            float* __restrict__ C, int ldc, long long sC,
            float alpha, const float* __restrict__ bias,
            int beta, int act)
{
    __shared__ float As[KT][TILE];
    __shared__ float Bs[KT][TILE];

    const int bz = blockIdx.z;
    A += bz * sA; B += bz * sB; C += bz * sC;

    const int m0 = blockIdx.y * TILE;
    const int n0 = blockIdx.x * TILE;
    const int tid = threadIdx.x;
    const int tx = tid & 15;       // col group
    const int ty = tid >> 4;       // row group

    const int arow = tid >> 2;         // 0..63
    const int akq  = (tid & 3) * 4;    // 0,4,8,12

    float acc[4][4] = {};

    for (int k0 = 0; k0 < K; k0 += KT) {
        // A tile: [m][k] -> As[k][m]
        float4 av = *(const float4*)(A + (size_t)(m0 + arow) * lda + (k0 + akq));
        As[akq + 0][arow] = av.x;
        As[akq + 1][arow] = av.y;
        As[akq + 2][arow] = av.z;
        As[akq + 3][arow] = av.w;
        if (TRANSB) {
            // B is [N,K]: tile rows n, cols k -> Bs[k][n]
            float4 bv = *(const float4*)(B + (size_t)(n0 + arow) * ldb + (k0 + akq));
            Bs[akq + 0][arow] = bv.x;
            Bs[akq + 1][arow] = bv.y;
            Bs[akq + 2][arow] = bv.z;
            Bs[akq + 3][arow] = bv.w;
        } else {
            // B is [K,N]: Bs[k][n]
            const int bk  = tid >> 4;
            const int bnq = (tid & 15) * 4;
            float4 bv = *(const float4*)(B + (size_t)(k0 + bk) * ldb + (n0 + bnq));
            *(float4*)&Bs[bk][bnq] = bv;
        }
        __syncthreads();

        #pragma unroll
        for (int k = 0; k < KT; ++k) {
            float4 a = *(const float4*)&As[k][ty * 4];
            float4 b = *(const float4*)&Bs[k][tx * 4];
            acc[0][0] = fmaf(a.x, b.x, acc[0][0]);
            acc[0][1] = fmaf(a.x, b.y, acc[0][1]);
            acc[0][2] = fmaf(a.x, b.z, acc[0][2]);
            acc[0][3] = fmaf(a.x, b.w, acc[0][3]);
            acc[1][0] = fmaf(a.y, b.x, acc[1][0]);
            acc[1][1] = fmaf(a.y, b.y, acc[1][1]);
            acc[1][2] = fmaf(a.y, b.z, acc[1][2]);
            acc[1][3] = fmaf(a.y, b.w, acc[1][3]);
            acc[2][0] = fmaf(a.z, b.x, acc[2][0]);
            acc[2][1] = fmaf(a.z, b.y, acc[2][1]);
            acc[2][2] = fmaf(a.z, b.z, acc[2][2]);
            acc[2][3] = fmaf(a.z, b.w, acc[2][3]);
            acc[3][0] = fmaf(a.w, b.x, acc[3][0]);
            acc[3][1] = fmaf(a.w, b.y, acc[3][1]);
            acc[3][2] = fmaf(a.w, b.z, acc[3][2]);
            acc[3][3] = fmaf(a.w, b.w, acc[3][3]);
        }
        __syncthreads();
    }

    #pragma unroll
    for (int i = 0; i < 4; ++i) {
        const int m = m0 + ty * 4 + i;
        #pragma unroll
        for (int j = 0; j < 4; ++j) {
            const int n = n0 + tx * 4 + j;
            float v = acc[i][j] * alpha;
            const size_t idx = (size_t)m * ldc + n;
            if (beta) v += C[idx];
            if (bias) v += bias[n];
            if (act == 1) v = 1.0f / (1.0f + __expf(-v));
            C[idx] = v;
        }
    }
}

// ---------------------------------------------------------------------------
// Row softmax (one block per row)
// ---------------------------------------------------------------------------
__global__ void __launch_bounds__(256)
softmax_kernel(float* __restrict__ data, int L)
{
    __shared__ float red[256];
    float* p = data + (size_t)blockIdx.x * L;
    const int t = threadIdx.x;

    float mx = -1e30f;
    for (int i = t; i < L; i += 256) mx = fmaxf(mx, p[i]);
    red[t] = mx; __syncthreads();
    for (int s = 128; s > 0; s >>= 1) {
        if (t < s) red[t] = fmaxf(red[t], red[t + s]);
        __syncthreads();
    }
    mx = red[0]; __syncthreads();

    float sum = 0.0f;
    for (int i = t; i < L; i += 256) {
        float e = __expf(p[i] - mx);
        p[i] = e;
        sum += e;
    }
    red[t] = sum; __syncthreads();
    for (int s = 128; s > 0; s >>= 1) {
        if (t < s) red[t] += red[t + s];
        __syncthreads();
    }
    const float inv = 1.0f / red[0];
    for (int i = t; i < L; i += 256) p[i] *= inv;
}

// ---------------------------------------------------------------------------
// Elementwise kernels (float4)
// ---------------------------------------------------------------------------
__global__ void combine_avg_kernel(float4* __restrict__ x, const float4* __restrict__ y, int n4)
{
    int i = blockIdx.x * blockDim.x + threadIdx.x;
    if (i >= n4) return;
    float4 a = x[i], b = y[i];
    a.x = 0.5f * (a.x + b.x);
    a.y = 0.5f * (a.y + b.y);
    a.z = 0.5f * (a.z + b.z);
    a.w = 0.5f * (a.w + b.w);
    x[i] = a;
}

__global__ void gated_relu_kernel(float4* __restrict__ out, const float4* __restrict__ z,
                                  const float4* __restrict__ m, const float4* __restrict__ f, int n4)
{
    int i = blockIdx.x * blockDim.x + threadIdx.x;
    if (i >= n4) return;
    float4 zv = z[i], mv = m[i], fv = f[i];
    float4 o;
    o.x = fmaxf(0.0f, zv.x + mv.x * fv.x);
    o.y = fmaxf(0.0f, zv.y + mv.y * fv.y);
    o.z = fmaxf(0.0f, zv.z + mv.z * fv.z);
    o.w = fmaxf(0.0f, zv.w + mv.w * fv.w);
    out[i] = o;
}

// QKV [B,N,3,H,D] -> Q,K,V [B,H,N,D]  (float4 over D)
__global__ void split_heads_kernel(const float4* __restrict__ qkv,
                                   float4* __restrict__ Q, float4* __restrict__ K,
                                   float4* __restrict__ V)
{
    int i = blockIdx.x * blockDim.x + threadIdx.x;       // over B*H*N*(D/4)
    const int D4 = DD / 4;                                // 16
    const int total = BB * HH * NN_ * D4;
    if (i >= total) return;
    int d4 = i % D4;
    int n  = (i / D4) % NN_;
    int h  = (i / (D4 * NN_)) % HH;
    int b  = i / (D4 * NN_ * HH);
    size_t srcbase = ((size_t)(b * NN_ + n) * 1536 + h * DD) / 4 + d4;  // t=0
    size_t dst = (((size_t)(b * HH + h) * NN_ + n) * DD) / 4 + d4;
    Q[dst] = qkv[srcbase];
    K[dst] = qkv[srcbase + 512 / 4];
    V[dst] = qkv[srcbase + 1024 / 4];
}

// Hh [B,H,N,D] -> Hc [B,N,H*D]
__global__ void merge_heads_kernel(const float4* __restrict__ Hh, float4* __restrict__ Hc)
{
    int i = blockIdx.x * blockDim.x + threadIdx.x;
    const int D4 = DD / 4;
    const int total = BB * HH * NN_ * D4;
    if (i >= total) return;
    int d4 = i % D4;
    int n  = (i / D4) % NN_;
    int h  = (i / (D4 * NN_)) % HH;
    int b  = i / (D4 * NN_ * HH);
    size_t src = (((size_t)(b * HH + h) * NN_ + n) * DD) / 4 + d4;
    size_t dst = ((size_t)(b * NN_ + n) * FF + h * DD) / 4 + d4;
    Hc[dst] = Hh[src];
}

// ---------------------------------------------------------------------------
// Host-side launch helpers
// ---------------------------------------------------------------------------
static void gemm(bool transB, int M, int N, int K,
                 const float* A, int lda, long long sA,
                 const float* B, int ldb, long long sB,
                 float* C, int ldc, long long sC,
                 int batch, float alpha,
                 const float* bias, int beta, int act)
{
    dim3 grid(N / TILE, M / TILE, batch);
    if (transB)
        gemm_kernel<true><<<grid, 256>>>(M, N, K, A, lda, sA, B, ldb, sB, C, ldc, sC,
                                         alpha, bias, beta, act);
    else
        gemm_kernel<false><<<grid, 256>>>(M, N, K, A, lda, sA, B, ldb, sB, C, ldc, sC,
                                          alpha, bias, beta, act);
}

extern "C" void kernel_launch(void* const* d_in, const int* in_sizes, int n_in,
                              void* d_out, int out_size)
{
    (void)in_sizes; (void)n_in; (void)out_size;

    float* buf = nullptr;
    cudaGetSymbolAddress((void**)&buf, g_buf);

    const float* x1     = (const float*)d_in[0];   // z_i  [16,768,512]
    const float* x2     = (const float*)d_in[1];   // z_j
    const float* zb     = (const float*)d_in[2];   // [256,512]
    const float* Wqkv_i = (const float*)d_in[3];   // [512,1536]
    const float* Wqkv_j = (const float*)d_in[4];
    const float* Wqkv_b = (const float*)d_in[5];
    const float* W_f    = (const float*)d_in[6];   // [1024,512]
    const float* b_f    = (const float*)d_in[7];
    const float* W_m    = (const float*)d_in[8];   // [512,512]
    const float* b_m    = (const float*)d_in[9];
    const float* W_QKV  = (const float*)d_in[10];  // [512,1536]
    const float* W_proj = (const float*)d_in[11];  // [512,512]
    const float* b_proj = (const float*)d_in[12];
    float* out = (float*)d_out;                    // [16,768,512]

    float* g_qkvb = buf + OFF_QKVB;
    float* g_kvi  = buf + OFF_KVI;
    float* g_qj   = buf + OFF_QJ;
    float* g_S1   = buf + OFF_S1;
    float* g_aib1 = buf + OFF_AIB1;
    float* g_S2   = buf + OFF_S2;
    float* g_abj  = buf + OFF_ABJ;
    float* g_S3   = buf + OFF_S3;
    float* g_aij  = buf + OFF_AIJ;
    float* g_f    = buf + OFF_F;
    float* g_m    = buf + OFF_M;
    float* g_h    = buf + OFF_H;
    float* g_qkv  = buf + OFF_QKV;
    float* g_Q    = buf + OFF_Q;
    float* g_K2   = buf + OFF_K2;
    float* g_V2   = buf + OFF_V2;
    float* g_S4   = buf + OFF_S4;
    float* g_Hh   = buf + OFF_HH2;
    float* g_Hc   = buf + OFF_HC;

    const float scale  = 0.044194173824159216f;   // 512^-0.5
    const float Scale  = 0.125f;                  // 64^-0.5
    const int   BN     = BB * NN_;                // 12288

    // qkv_b = 0.2 * (z_b @ Wqkv_b)   [256,1536]
    gemm(false, NBB, 1536, FF, zb, FF, 0, Wqkv_b, 1536, 0,
         g_qkvb, 1536, 0, 1, 0.2f, nullptr, 0, 0);

    // kv_i = z_i @ Wqkv_i[:, 512:1536]   [12288,1024]
    gemm(false, BN, 1024, FF, x1, FF, 0, Wqkv_i + 512, 1536, 0,
         g_kvi, 1024, 0, 1, 1.0f, nullptr, 0, 0);

    // q_j = z_j @ Wqkv_j[:, 0:512]   [12288,512]
    gemm(false, BN, FF, FF, x2, FF, 0, Wqkv_j, 1536, 0,
         g_qj, FF, 0, 1, 1.0f, nullptr, 0, 0);

    // S1[b] = scale * q_b @ k_i[b]^T   [16,256,768]
    gemm(true, NBB, NN_, FF, g_qkvb, 1536, 0,
         g_kvi, 1024, (long long)NN_ * 1024,
         g_S1, NN_, (long long)NBB * NN_, BB, scale, nullptr, 0, 0);
    softmax_kernel<<<BB * NBB, 256>>>(g_S1, NN_);

    // a_ib1[b] = S1[b] @ v_i[b]   [16,256,512]
    gemm(false, NBB, FF, NN_, g_S1, NN_, (long long)NBB * NN_,
         g_kvi + 512, 1024, (long long)NN_ * 1024,
         g_aib1, FF, (long long)NBB * FF, BB, 1.0f, nullptr, 0, 0);

    // S2[b] = scale * q_j[b] @ k_b^T   [16,768,256]
    gemm(true, NN_, NBB, FF, g_qj, FF, (long long)NN_ * FF,
         g_qkvb + 512, 1536, 0,
         g_S2, NBB, (long long)NN_ * NBB, BB, scale, nullptr, 0, 0);
    softmax_kernel<<<BB * NN_, 256>>>(g_S2, NBB);

    // a_bj[b] = S2[b] @ v_b   [16,768,512]
    gemm(false, NN_, FF, NBB, g_S2, NBB, (long long)NN_ * NBB,
         g_qkvb + 1024, 1536, 0,
         g_abj, FF, (long long)NN_ * FF, BB, 1.0f, nullptr, 0, 0);

    // S3[b] = scale * z_i[b] @ a_ib1[b]^T   [16,768,256]
    gemm(true, NN_, NBB, FF, x1, FF, (long long)NN_ * FF,
         g_aib1, FF, (long long)NBB * FF,
         g_S3, NBB, (long long)NN_ * NBB, BB, scale, nullptr, 0, 0);
    softmax_kernel<<<BB * NN_, 256>>>(g_S3, NBB);

    // a_ij[b] = S3[b] @ a_ib1[b]   [16,768,512]
    gemm(false, NN_, FF, NBB, g_S3, NBB, (long long)NN_ * NBB,
         g_aib1, FF, (long long)NBB * FF,
         g_aij, FF, (long long)NN_ * FF, BB, 1.0f, nullptr, 0, 0);

    // a_ij = 0.5 * (a_ij + a_bj)
    {
        int n4 = BN * FF / 4;
        combine_avg_kernel<<<(n4 + 255) / 256, 256>>>((float4*)g_aij, (const float4*)g_abj, n4);
    }

    // f = sigmoid(a_ij @ W_f[0:512] + z_j @ W_f[512:1024] + b_f)
    gemm(false, BN, FF, FF, g_aij, FF, 0, W_f, FF, 0,
         g_f, FF, 0, 1, 1.0f, b_f, 0, 0);
    gemm(false, BN, FF, FF, x2, FF, 0, W_f + (size_t)512 * FF, FF, 0,
         g_f, FF, 0, 1, 1.0f, nullptr, 1, 1);

    // m = a_ij @ W_m + b_m
    gemm(false, BN, FF, FF, g_aij, FF, 0, W_m, FF, 0,
         g_m, FF, 0, 1, 1.0f, b_m, 0, 0);

    // h = relu(z_i + m * f)
    {
        int n4 = BN * FF / 4;
        gated_relu_kernel<<<(n4 + 255) / 256, 256>>>((float4*)g_h, (const float4*)x1,
                                                     (const float4*)g_m, (const float4*)g_f, n4);
    }

    // QKV = h @ W_QKV   [12288,1536]
    gemm(false, BN, 1536, FF, g_h, FF, 0, W_QKV, 1536, 0,
         g_qkv, 1536, 0, 1, 1.0f, nullptr, 0, 0);

    // split heads
    {
        int total = BB * HH * NN_ * (DD / 4);
        split_heads_kernel<<<(total + 255) / 256, 256>>>((const float4*)g_qkv,
                                                         (float4*)g_Q, (float4*)g_K2, (float4*)g_V2);
    }

    // S4[bh] = Scale * Q[bh] @ K[bh]^T   [128,768,768]
    gemm(true, NN_, NN_, DD, g_Q, DD, (long long)NN_ * DD,
         g_K2, DD, (long long)NN_ * DD,
         g_S4, NN_, (long long)NN_ * NN_, BB * HH, Scale, nullptr, 0, 0);
    softmax_kernel<<<BB * HH * NN_, 256>>>(g_S4, NN_);

    // Hh[bh] = S4[bh] @ V[bh]   [128,768,64]
    gemm(false, NN_, DD, NN_, g_S4, NN_, (long long)NN_ * NN_,
         g_V2, DD, (long long)NN_ * DD,
         g_Hh, DD, (long long)NN_ * DD, BB * HH, 1.0f, nullptr, 0, 0);

    // merge heads -> Hc [12288,512]
    {
        int total = BB * HH * NN_ * (DD / 4);
        merge_heads_kernel<<<(total + 255) / 256, 256>>>((const float4*)g_Hh, (float4*)g_Hc);
    }

    // out = Hc @ W_proj + b_proj
    gemm(false, BN, FF, FF, g_Hc, FF, 0, W_proj, FF, 0,
         out, FF, 0, 1, 1.0f, b_proj, 0, 0);
}

// round 3
// speedup vs baseline: 1.1660x; 1.1660x over previous
#include <cuda_runtime.h>
#include <math.h>

// Problem constants
#define BB   16
#define NN_  768
#define FF   512
#define NBB  256
#define HH   8
#define DD   64

// ---------------------------------------------------------------------------
// Scratch: single __device__ global (allocation-free per harness rules)
// ---------------------------------------------------------------------------
static const long long OFF_QKVB = 0;                      // [256,1536]
static const long long OFF_KVI  = OFF_QKVB + 256LL*1536;  // [16*768,1024] (k|v)
static const long long OFF_QJ   = OFF_KVI  + 16LL*768*1024;   // [16*768,512]
static const long long OFF_S1   = OFF_QJ   + 16LL*768*512;    // [16,256,768]
static const long long OFF_AIB1 = OFF_S1   + 16LL*256*768;    // [16,256,512]
static const long long OFF_S2   = OFF_AIB1 + 16LL*256*512;    // [16,768,256]
static const long long OFF_ABJ  = OFF_S2   + 16LL*768*256;    // [16,768,512]
static const long long OFF_S3   = OFF_ABJ  + 16LL*768*512;    // [16,768,256]
static const long long OFF_AIJ  = OFF_S3   + 16LL*768*256;    // [16,768,512]
static const long long OFF_F    = OFF_AIJ  + 16LL*768*512;    // [16,768,512]
static const long long OFF_M    = OFF_F    + 16LL*768*512;    // [16,768,512]
static const long long OFF_H    = OFF_M    + 16LL*768*512;    // [16,768,512]
static const long long OFF_QKV  = OFF_H    + 16LL*768*512;    // [16*768,1536]
static const long long OFF_Q    = OFF_QKV  + 16LL*768*1536;   // [16,8,768,64]
static const long long OFF_K2   = OFF_Q    + 16LL*8*768*64;
static const long long OFF_V2   = OFF_K2   + 16LL*8*768*64;
static const long long OFF_S4   = OFF_V2   + 16LL*8*768*64;   // [128,768,768]
static const long long OFF_HH2  = OFF_S4   + 128LL*768*768;   // [16,8,768,64]
static const long long OFF_HC   = OFF_HH2  + 16LL*8*768*64;   // [16*768,512]
static const long long TOTAL_FL = OFF_HC   + 16LL*768*512;

__device__ float g_buf[TOTAL_FL];

// ---------------------------------------------------------------------------
// Tiled fp32 GEMM, register-blocked.
// Block = 256 threads arranged 16x16 (tx, ty). Tile = TM x TN, KT=16.
// Per-thread tile = (TM/16) x (TN/16), as (TM/64)x(TN/64) chunks of 4x4,
// chunk stride 64 so LDS.128 reads are conflict-free.
// All M multiples of TM, N multiples of TN, K multiples of 16 (guaranteed).
// ---------------------------------------------------------------------------
#define KT 16

template<bool TRANSB, int TM, int TN>
__global__ void __launch_bounds__(256)
gemm_kernel(int M, int N, int K,
            const float* __restrict__ A, int lda, long long sA,
            const float* __restrict__ B, int ldb, long long sB,
            float* __restrict__ C, int ldc, long long sC,
            float alpha, const float* __restrict__ bias,
            int beta, int act)
{
    constexpr int MCH = TM / 64;
    constexpr int NCH = TN / 64;

    __shared__ float As[KT * TM];
    __shared__ float Bs[KT * TN];

    const int bz = blockIdx.z;
    const int m0 = blockIdx.y * TM;
    const int n0 = blockIdx.x * TN;
    const int tid = threadIdx.x;
    const int tx = tid & 15;
    const int ty = tid >> 4;

    const float* Atile = A + bz * sA + (size_t)m0 * lda;
    const float* Btile;
    if (TRANSB) Btile = B + bz * sB + (size_t)n0 * ldb;   // B is [N,K]
    else        Btile = B + bz * sB + n0;                 // B is [K,N]
    float* Ctile = C + bz * sC;

    float acc[MCH * 4][NCH * 4] = {};

    for (int k0 = 0; k0 < K; k0 += KT) {
        // ---- load A tile [TM x KT] -> As[k][m] (transposed store) ----
        #pragma unroll
        for (int i = 0; i < MCH; ++i) {
            int idx = tid + i * 256;
            int row = idx >> 2;              // 0..TM-1
            int kq  = (idx & 3) * 4;         // 0,4,8,12
            float4 v = *(const float4*)(Atile + (size_t)row * lda + k0 + kq);
            As[(kq + 0) * TM + row] = v.x;
            As[(kq + 1) * TM + row] = v.y;
            As[(kq + 2) * TM + row] = v.z;
            As[(kq + 3) * TM + row] = v.w;
        }
        // ---- load B tile -> Bs[k][n] ----
        if (TRANSB) {
            #pragma unroll
            for (int i = 0; i < NCH; ++i) {
                int idx = tid + i * 256;
                int row = idx >> 2;          // n index
                int kq  = (idx & 3) * 4;
                float4 v = *(const float4*)(Btile + (size_t)row * ldb + k0 + kq);
                Bs[(kq + 0) * TN + row] = v.x;
                Bs[(kq + 1) * TN + row] = v.y;
                Bs[(kq + 2) * TN + row] = v.z;
                Bs[(kq + 3) * TN + row] = v.w;
            }
        } else {
            #pragma unroll
            for (int i = 0; i < NCH; ++i) {
                int idx = tid + i * 256;
                int row = idx / (TN / 4);    // k index
                int col = (idx % (TN / 4)) * 4;
                float4 v = *(const float4*)(Btile + (size_t)(k0 + row) * ldb + col);
                *(float4*)&Bs[row * TN + col] = v;
            }
        }
        __syncthreads();

        #pragma unroll
        for (int k = 0; k < KT; ++k) {
            float a[MCH * 4], b[NCH * 4];
            #pragma unroll
            for (int mc = 0; mc < MCH; ++mc)
                *(float4*)&a[mc * 4] = *(const float4*)&As[k * TM + mc * 64 + ty * 4];
            #pragma unroll
            for (int nc = 0; nc < NCH; ++nc)
                *(float4*)&b[nc * 4] = *(const float4*)&Bs[k * TN + nc * 64 + tx * 4];
            #pragma unroll
            for (int i = 0; i < MCH * 4; ++i)
                #pragma unroll
                for (int j = 0; j < NCH * 4; ++j)
                    acc[i][j] = fmaf(a[i], b[j], acc[i][j]);
        }
        __syncthreads();
    }

    // ---- epilogue (float4 stores) ----
    #pragma unroll
    for (int mc = 0; mc < MCH; ++mc) {
        #pragma unroll
        for (int i = 0; i < 4; ++i) {
            const int m = m0 + mc * 64 + ty * 4 + i;
            #pragma unroll
            for (int nc = 0; nc < NCH; ++nc) {
                const int n = n0 + nc * 64 + tx * 4;
                float* cp = Ctile + (size_t)m * ldc + n;
                float4 v;
                v.x = acc[mc * 4 + i][nc * 4 + 0] * alpha;
                v.y = acc[mc * 4 + i][nc * 4 + 1] * alpha;
                v.z = acc[mc * 4 + i][nc * 4 + 2] * alpha;
                v.w = acc[mc * 4 + i][nc * 4 + 3] * alpha;
                if (beta) {
                    float4 c = *(const float4*)cp;
                    v.x += c.x; v.y += c.y; v.z += c.z; v.w += c.w;
                }
                if (bias) {
                    float4 bv = *(const float4*)(bias + n);
                    v.x += bv.x; v.y += bv.y; v.z += bv.z; v.w += bv.w;
                }
                if (act == 1) {
                    v.x = 1.0f / (1.0f + __expf(-v.x));
                    v.y = 1.0f / (1.0f + __expf(-v.y));
                    v.z = 1.0f / (1.0f + __expf(-v.z));
                    v.w = 1.0f / (1.0f + __expf(-v.w));
                }
                *(float4*)cp = v;
            }
        }
    }
}

// ---------------------------------------------------------------------------
// Row softmax (one block per row)
// ---------------------------------------------------------------------------
__global__ void __launch_bounds__(256)
softmax_kernel(float* __restrict__ data, int L)
{
    __shared__ float red[256];
    float* p = data + (size_t)blockIdx.x * L;
    const int t = threadIdx.x;

    float mx = -1e30f;
    for (int i = t; i < L; i += 256) mx = fmaxf(mx, p[i]);
    red[t] = mx; __syncthreads();
    for (int s = 128; s > 0; s >>= 1) {
        if (t < s) red[t] = fmaxf(red[t], red[t + s]);
        __syncthreads();
    }
    mx = red[0]; __syncthreads();

    float sum = 0.0f;
    for (int i = t; i < L; i += 256) {
        float e = __expf(p[i] - mx);
        p[i] = e;
        sum += e;
    }
    red[t] = sum; __syncthreads();
    for (int s = 128; s > 0; s >>= 1) {
        if (t < s) red[t] += red[t + s];
        __syncthreads();
    }
    const float inv = 1.0f / red[0];
    for (int i = t; i < L; i += 256) p[i] *= inv;
}

// ---------------------------------------------------------------------------
// Elementwise kernels (float4)
// ---------------------------------------------------------------------------
__global__ void combine_avg_kernel(float4* __restrict__ x, const float4* __restrict__ y, int n4)
{
    int i = blockIdx.x * blockDim.x + threadIdx.x;
    if (i >= n4) return;
    float4 a = x[i], b = y[i];
    a.x = 0.5f * (a.x + b.x);
    a.y = 0.5f * (a.y + b.y);
    a.z = 0.5f * (a.z + b.z);
    a.w = 0.5f * (a.w + b.w);
    x[i] = a;
}

__global__ void gated_relu_kernel(float4* __restrict__ out, const float4* __restrict__ z,
                                  const float4* __restrict__ m, const float4* __restrict__ f, int n4)
{
    int i = blockIdx.x * blockDim.x + threadIdx.x;
    if (i >= n4) return;
    float4 zv = z[i], mv = m[i], fv = f[i];
    float4 o;
    o.x = fmaxf(0.0f, zv.x + mv.x * fv.x);
    o.y = fmaxf(0.0f, zv.y + mv.y * fv.y);
    o.z = fmaxf(0.0f, zv.z + mv.z * fv.z);
    o.w = fmaxf(0.0f, zv.w + mv.w * fv.w);
    out[i] = o;
}

// QKV [B,N,3,H,D] -> Q,K,V [B,H,N,D]  (float4 over D)
__global__ void split_heads_kernel(const float4* __restrict__ qkv,
                                   float4* __restrict__ Q, float4* __restrict__ K,
                                   float4* __restrict__ V)
{
    int i = blockIdx.x * blockDim.x + threadIdx.x;
    const int D4 = DD / 4;
    const int total = BB * HH * NN_ * D4;
    if (i >= total) return;
    int d4 = i % D4;
    int n  = (i / D4) % NN_;
    int h  = (i / (D4 * NN_)) % HH;
    int b  = i / (D4 * NN_ * HH);
    size_t srcbase = ((size_t)(b * NN_ + n) * 1536 + h * DD) / 4 + d4;
    size_t dst = (((size_t)(b * HH + h) * NN_ + n) * DD) / 4 + d4;
    Q[dst] = qkv[srcbase];
    K[dst] = qkv[srcbase + 512 / 4];
    V[dst] = qkv[srcbase + 1024 / 4];
}

// Hh [B,H,N,D] -> Hc [B,N,H*D]
__global__ void merge_heads_kernel(const float4* __restrict__ Hh, float4* __restrict__ Hc)
{
    int i = blockIdx.x * blockDim.x + threadIdx.x;
    const int D4 = DD / 4;
    const int total = BB * HH * NN_ * D4;
    if (i >= total) return;
    int d4 = i % D4;
    int n  = (i / D4) % NN_;
    int h  = (i / (D4 * NN_)) % HH;
    int b  = i / (D4 * NN_ * HH);
    size_t src = (((size_t)(b * HH + h) * NN_ + n) * DD) / 4 + d4;
    size_t dst = ((size_t)(b * NN_ + n) * FF + h * DD) / 4 + d4;
    Hc[dst] = Hh[src];
}

// ---------------------------------------------------------------------------
// Host-side dispatcher. tm/tn select tile instantiation.
// ---------------------------------------------------------------------------
static void gemm(bool transB, int tm, int tn, int M, int N, int K,
                 const float* A, int lda, long long sA,
                 const float* B, int ldb, long long sB,
                 float* C, int ldc, long long sC,
                 int batch, float alpha,
                 const float* bias, int beta, int act)
{
    dim3 grid(N / tn, M / tm, batch);
    if (transB) {
        if (tm == 128 && tn == 128)
            gemm_kernel<true, 128, 128><<<grid, 256>>>(M, N, K, A, lda, sA, B, ldb, sB, C, ldc, sC, alpha, bias, beta, act);
        else
            gemm_kernel<true, 64, 128><<<grid, 256>>>(M, N, K, A, lda, sA, B, ldb, sB, C, ldc, sC, alpha, bias, beta, act);
    } else {
        if (tm == 128 && tn == 128)
            gemm_kernel<false, 128, 128><<<grid, 256>>>(M, N, K, A, lda, sA, B, ldb, sB, C, ldc, sC, alpha, bias, beta, act);
        else if (tm == 128 && tn == 64)
            gemm_kernel<false, 128, 64><<<grid, 256>>>(M, N, K, A, lda, sA, B, ldb, sB, C, ldc, sC, alpha, bias, beta, act);
        else
            gemm_kernel<false, 64, 128><<<grid, 256>>>(M, N, K, A, lda, sA, B, ldb, sB, C, ldc, sC, alpha, bias, beta, act);
    }
}

extern "C" void kernel_launch(void* const* d_in, const int* in_sizes, int n_in,
                              void* d_out, int out_size)
{
    (void)in_sizes; (void)n_in; (void)out_size;

    float* buf = nullptr;
    cudaGetSymbolAddress((void**)&buf, g_buf);

    const float* x1     = (const float*)d_in[0];
    const float* x2     = (const float*)d_in[1];
    const float* zb     = (const float*)d_in[2];
    const float* Wqkv_i = (const float*)d_in[3];
    const float* Wqkv_j = (const float*)d_in[4];
    const float* Wqkv_b = (const float*)d_in[5];
    const float* W_f    = (const float*)d_in[6];
    const float* b_f    = (const float*)d_in[7];
    const float* W_m    = (const float*)d_in[8];
    const float* b_m    = (const float*)d_in[9];
    const float* W_QKV  = (const float*)d_in[10];
    const float* W_proj = (const float*)d_in[11];
    const float* b_proj = (const float*)d_in[12];
    float* out = (float*)d_out;

    float* g_qkvb = buf + OFF_QKVB;
    float* g_kvi  = buf + OFF_KVI;
    float* g_qj   = buf + OFF_QJ;
    float* g_S1   = buf + OFF_S1;
    float* g_aib1 = buf + OFF_AIB1;
    float* g_S2   = buf + OFF_S2;
    float* g_abj  = buf + OFF_ABJ;
    float* g_S3   = buf + OFF_S3;
    float* g_aij  = buf + OFF_AIJ;
    float* g_f    = buf + OFF_F;
    float* g_m    = buf + OFF_M;
    float* g_h    = buf + OFF_H;
    float* g_qkv  = buf + OFF_QKV;
    float* g_Q    = buf + OFF_Q;
    float* g_K2   = buf + OFF_K2;
    float* g_V2   = buf + OFF_V2;
    float* g_S4   = buf + OFF_S4;
    float* g_Hh   = buf + OFF_HH2;
    float* g_Hc   = buf + OFF_HC;

    const float scale  = 0.044194173824159216f;   // 512^-0.5
    const float Scale  = 0.125f;                  // 64^-0.5
    const int   BN     = BB * NN_;

    // qkv_b = 0.2 * (z_b @ Wqkv_b)   [256,1536]
    gemm(false, 64, 128, NBB, 1536, FF, zb, FF, 0, Wqkv_b, 1536, 0,
         g_qkvb, 1536, 0, 1, 0.2f, nullptr, 0, 0);

    // kv_i = z_i @ Wqkv_i[:, 512:1536]   [12288,1024]
    gemm(false, 128, 128, BN, 1024, FF, x1, FF, 0, Wqkv_i + 512, 1536, 0,
         g_kvi, 1024, 0, 1, 1.0f, nullptr, 0, 0);

    // q_j = z_j @ Wqkv_j[:, 0:512]   [12288,512]
    gemm(false, 128, 128, BN, FF, FF, x2, FF, 0, Wqkv_j, 1536, 0,
         g_qj, FF, 0, 1, 1.0f, nullptr, 0, 0);

    // S1[b] = scale * q_b @ k_i[b]^T   [16,256,768]
    gemm(true, 64, 128, NBB, NN_, FF, g_qkvb, 1536, 0,
         g_kvi, 1024, (long long)NN_ * 1024,
         g_S1, NN_, (long long)NBB * NN_, BB, scale, nullptr, 0, 0);
    softmax_kernel<<<BB * NBB, 256>>>(g_S1, NN_);

    // a_ib1[b] = S1[b] @ v_i[b]   [16,256,512]
    gemm(false, 64, 128, NBB, FF, NN_, g_S1, NN_, (long long)NBB * NN_,
         g_kvi + 512, 1024, (long long)NN_ * 1024,
         g_aib1, FF, (long long)NBB * FF, BB, 1.0f, nullptr, 0, 0);

    // S2[b] = scale * q_j[b] @ k_b^T   [16,768,256]
    gemm(true, 128, 128, NN_, NBB, FF, g_qj, FF, (long long)NN_ * FF,
         g_qkvb + 512, 1536, 0,
         g_S2, NBB, (long long)NN_ * NBB, BB, scale, nullptr, 0, 0);
    softmax_kernel<<<BB * NN_, 256>>>(g_S2, NBB);

    // a_bj[b] = S2[b] @ v_b   [16,768,512]
    gemm(false, 128, 128, NN_, FF, NBB, g_S2, NBB, (long long)NN_ * NBB,
         g_qkvb + 1024, 1536, 0,
         g_abj, FF, (long long)NN_ * FF, BB, 1.0f, nullptr, 0, 0);

    // S3[b] = scale * z_i[b] @ a_ib1[b]^T   [16,768,256]
    gemm(true, 128, 128, NN_, NBB, FF, x1, FF, (long long)NN_ * FF,
         g_aib1, FF, (long long)NBB * FF,
         g_S3, NBB, (long long)NN_ * NBB, BB, scale, nullptr, 0, 0);
    softmax_kernel<<<BB * NN_, 256>>>(g_S3, NBB);

    // a_ij[b] = S3[b] @ a_ib1[b]   [16,768,512]
    gemm(false, 128, 128, NN_, FF, NBB, g_S3, NBB, (long long)NN_ * NBB,
         g_aib1, FF, (long long)NBB * FF,
         g_aij, FF, (long long)NN_ * FF, BB, 1.0f, nullptr, 0, 0);

    // a_ij = 0.5 * (a_ij + a_bj)
    {
        int n4 = BN * FF / 4;
        combine_avg_kernel<<<(n4 + 255) / 256, 256>>>((float4*)g_aij, (const float4*)g_abj, n4);
    }

    // f = sigmoid(a_ij @ W_f[0:512] + z_j @ W_f[512:1024] + b_f)
    gemm(false, 128, 128, BN, FF, FF, g_aij, FF, 0, W_f, FF, 0,
         g_f, FF, 0, 1, 1.0f, b_f, 0, 0);
    gemm(false, 128, 128, BN, FF, FF, x2, FF, 0, W_f + (size_t)512 * FF, FF, 0,
         g_f, FF, 0, 1, 1.0f, nullptr, 1, 1);

    // m = a_ij @ W_m + b_m
    gemm(false, 128, 128, BN, FF, FF, g_aij, FF, 0, W_m, FF, 0,
         g_m, FF, 0, 1, 1.0f, b_m, 0, 0);

    // h = relu(z_i + m * f)
    {
        int n4 = BN * FF / 4;
        gated_relu_kernel<<<(n4 + 255) / 256, 256>>>((float4*)g_h, (const float4*)x1,
                                                     (const float4*)g_m, (const float4*)g_f, n4);
    }

    // QKV = h @ W_QKV   [12288,1536]
    gemm(false, 128, 128, BN, 1536, FF, g_h, FF, 0, W_QKV, 1536, 0,
         g_qkv, 1536, 0, 1, 1.0f, nullptr, 0, 0);

    // split heads
    {
        int total = BB * HH * NN_ * (DD / 4);
        split_heads_kernel<<<(total + 255) / 256, 256>>>((const float4*)g_qkv,
                                                         (float4*)g_Q, (float4*)g_K2, (float4*)g_V2);
    }

    // S4[bh] = Scale * Q[bh] @ K[bh]^T   [128,768,768]
    gemm(true, 128, 128, NN_, NN_, DD, g_Q, DD, (long long)NN_ * DD,
         g_K2, DD, (long long)NN_ * DD,
         g_S4, NN_, (long long)NN_ * NN_, BB * HH, Scale, nullptr, 0, 0);
    softmax_kernel<<<BB * HH * NN_, 256>>>(g_S4, NN_);

    // Hh[bh] = S4[bh] @ V[bh]   [128,768,64]
    gemm(false, 128, 64, NN_, DD, NN_, g_S4, NN_, (long long)NN_ * NN_,
         g_V2, DD, (long long)NN_ * DD,
         g_Hh, DD, (long long)NN_ * DD, BB * HH, 1.0f, nullptr, 0, 0);

    // merge heads -> Hc [12288,512]
    {
        int total = BB * HH * NN_ * (DD / 4);
        merge_heads_kernel<<<(total + 255) / 256, 256>>>((const float4*)g_Hh, (float4*)g_Hc);
    }

    // out = Hc @ W_proj + b_proj
    gemm(false, 128, 128, BN, FF, FF, g_Hc, FF, 0, W_proj, FF, 0,
         out, FF, 0, 1, 1.0f, b_proj, 0, 0);
}

// round 5
// speedup vs baseline: 1.7815x; 1.5279x over previous
#include <cuda_runtime.h>
#include <cuda_bf16.h>
#include <math.h>
#include <stdint.h>

// Problem constants
#define BB   16
#define NN_  768
#define FF   512
#define NBB  256
#define HH   8
#define DD   64

typedef __nv_bfloat16 bf16;

__device__ __forceinline__ uint32_t smem_u32(const void* p) {
    uint32_t a;
    asm("{ .reg .u64 t; cvta.to.shared.u64 t, %1; cvt.u32.u64 %0, t; }" : "=r"(a) : "l"(p));
    return a;
}

__device__ __forceinline__ void ldsm4(uint32_t* r, uint32_t addr) {
    asm volatile("ldmatrix.sync.aligned.m8n8.x4.shared.b16 {%0,%1,%2,%3}, [%4];"
        : "=r"(r[0]), "=r"(r[1]), "=r"(r[2]), "=r"(r[3]) : "r"(addr));
}

__device__ __forceinline__ void mma16816(float* c, const uint32_t* a, const uint32_t* b) {
    asm volatile(
        "mma.sync.aligned.m16n8k16.row.col.f32.bf16.bf16.f32 "
        "{%0,%1,%2,%3}, {%4,%5,%6,%7}, {%8,%9}, {%0,%1,%2,%3};"
        : "+f"(c[0]), "+f"(c[1]), "+f"(c[2]), "+f"(c[3])
        : "r"(a[0]), "r"(a[1]), "r"(a[2]), "r"(a[3]), "r"(b[0]), "r"(b[1]));
}

__device__ __forceinline__ void split_hl(float v, bf16& h, bf16& l) {
    h = __float2bfloat16(v);
    l = __float2bfloat16(v - __bfloat162float(h));
}

// ===========================================================================
// Scratch buffers
// ===========================================================================
static const long long F_QKVB = 0;                           // 256x1536
static const long long F_KVI  = F_QKVB + 256LL*1536;         // 12288x1024
static const long long F_S1   = F_KVI  + 12288LL*1024;       // 16x256x768
static const long long F_AIB1 = F_S1   + 16LL*256*768;       // 16x256x512
static const long long F_S2   = F_AIB1 + 16LL*256*512;       // 16x768x256
static const long long F_ABJ  = F_S2   + 16LL*768*256;       // 12288x512
static const long long F_S3   = F_ABJ  + 12288LL*512;        // 16x768x256
static const long long F_AIJ  = F_S3   + 16LL*768*256;       // 12288x512
static const long long F_FG   = F_AIJ  + 12288LL*512;        // 12288x512
static const long long F_MG   = F_FG   + 12288LL*512;        // 12288x512
static const long long F_QKV  = F_MG   + 12288LL*512;        // 12288x1536
static const long long F_V    = F_QKV  + 12288LL*1536;       // 16x8x768x64
static const long long F_S4   = F_V    + 16LL*8*768*64;      // 128x768x768
static const long long F_HH   = F_S4   + 128LL*768*768;      // 16x8x768x64
static const long long F_TOT  = F_HH   + 16LL*8*768*64;

__device__ float g_f32[F_TOT];

static const long long B_X1    = 0;                             static const long long SZ_X1    = 12288LL*512;
static const long long B_X2    = B_X1    + 2*SZ_X1;             static const long long SZ_X2    = 12288LL*512;
static const long long B_ZB    = B_X2    + 2*SZ_X2;             static const long long SZ_ZB    = 256LL*512;
static const long long B_WB    = B_ZB    + 2*SZ_ZB;             static const long long SZ_WB    = 1536LL*512;
static const long long B_WI    = B_WB    + 2*SZ_WB;             static const long long SZ_WI    = 1024LL*512;
static const long long B_WJ    = B_WI    + 2*SZ_WI;             static const long long SZ_WJ    = 512LL*512;
static const long long B_WF1   = B_WJ    + 2*SZ_WJ;             static const long long SZ_WF1   = 512LL*512;
static const long long B_WF2   = B_WF1   + 2*SZ_WF1;            static const long long SZ_WF2   = 512LL*512;
static const long long B_WM    = B_WF2   + 2*SZ_WF2;            static const long long SZ_WM    = 512LL*512;
static const long long B_WQ    = B_WM    + 2*SZ_WM;             static const long long SZ_WQ    = 1536LL*512;
static const long long B_WP    = B_WQ    + 2*SZ_WQ;             static const long long SZ_WP    = 512LL*512;
static const long long B_QKVB  = B_WP    + 2*SZ_WP;             static const long long SZ_QKVB  = 256LL*1536;
static const long long B_KVI   = B_QKVB  + 2*SZ_QKVB;           static const long long SZ_KVI   = 12288LL*1024;
static const long long B_QJ    = B_KVI   + 2*SZ_KVI;            static const long long SZ_QJ    = 12288LL*512;
static const long long B_S1    = B_QJ    + 2*SZ_QJ;             static const long long SZ_S1    = 16LL*256*768;
static const long long B_VIT   = B_S1    + 2*SZ_S1;             static const long long SZ_VIT   = 16LL*512*768;
static const long long B_AIB1  = B_VIT   + 2*SZ_VIT;            static const long long SZ_AIB1  = 16LL*256*512;
static const long long B_AIB1T = B_AIB1  + 2*SZ_AIB1;           static const long long SZ_AIB1T = 16LL*512*256;
static const long long B_VBT   = B_AIB1T + 2*SZ_AIB1T;          static const long long SZ_VBT   = 512LL*256;
static const long long B_S2    = B_VBT   + 2*SZ_VBT;            static const long long SZ_S2    = 16LL*768*256;
static const long long B_S3    = B_S2    + 2*SZ_S2;             static const long long SZ_S3    = 16LL*768*256;
static const long long B_AIJ   = B_S3    + 2*SZ_S3;             static const long long SZ_AIJ   = 12288LL*512;
static const long long B_HB    = B_AIJ   + 2*SZ_AIJ;            static const long long SZ_HB    = 12288LL*512;
static const long long B_QH    = B_HB    + 2*SZ_HB;             static const long long SZ_QH    = 16LL*8*768*64;
static const long long B_KH    = B_QH    + 2*SZ_QH;             static const long long SZ_KH    = 16LL*8*768*64;
static const long long B_VT    = B_KH    + 2*SZ_KH;             static const long long SZ_VT    = 16LL*8*64*768;
static const long long B_S4    = B_VT    + 2*SZ_VT;             static const long long SZ_S4    = 128LL*768*768;
static const long long B_HC    = B_S4    + 2*SZ_S4;             static const long long SZ_HC    = 12288LL*512;
static const long long B_TOT   = B_HC    + 2*SZ_HC;

__device__ bf16 g_bf[B_TOT];

// ===========================================================================
// mma.sync GEMM: C[bz] = alpha * A[bz] @ B[bz]^T
// A [M,K] K-major (hi/lo), B [N,K] K-major (hi/lo). fp32 acc, 3 MMAs/k-step.
// Block 128x128, KT=32, 256 threads (8 warps, warptile 32x64).
// M % 128 == 0, K % 32 == 0; N arbitrary even (predicated).
// Smem rows padded to 40 bf16 (80B pitch) -> conflict-free ldmatrix.
// ===========================================================================
#define KT 32
#define SMP 40    // padded row stride in bf16

__global__ void __launch_bounds__(256)
mma_gemm(int M, int N, int K,
         const bf16* __restrict__ Ahi, const bf16* __restrict__ Alo, int lda, long long sA,
         const bf16* __restrict__ Bhi, const bf16* __restrict__ Blo, int ldb, long long sB,
         float* __restrict__ C, int ldc, long long sC,
         float alpha, const float* __restrict__ bias, int beta, int act,
         bf16* __restrict__ Chi, bf16* __restrict__ Clo, int wr_f32)
{
    __shared__ bf16 As[2][128 * SMP];   // [hi/lo][row*SMP + k]
    __shared__ bf16 Bs[2][128 * SMP];

    const int tid = threadIdx.x, lane = tid & 31, wid = tid >> 5;
    const int bz = blockIdx.z;
    const int m0 = blockIdx.y * 128, n0 = blockIdx.x * 128;
    const int wm = wid & 3, wn = wid >> 2;       // 4 x 2 warp grid
    const int m0w = wm * 32, n0w = wn * 64;

    const bf16* Ah = Ahi + bz * sA + (size_t)m0 * lda;
    const bf16* Al = Alo + bz * sA + (size_t)m0 * lda;
    const bf16* Bh = Bhi + bz * sB + (size_t)n0 * ldb;
    const bf16* Bl = Blo + bz * sB + (size_t)n0 * ldb;

    const uint32_t sa = smem_u32(As);
    const uint32_t sbm = smem_u32(Bs);
    const uint32_t HALF = 128 * SMP * 2;   // bytes between hi and lo planes

    float acc[2][8][4];
    #pragma unroll
    for (int i = 0; i < 2; ++i)
        #pragma unroll
        for (int j = 0; j < 8; ++j)
            #pragma unroll
            for (int q = 0; q < 4; ++q) acc[i][j][q] = 0.0f;

    for (int k0 = 0; k0 < K; k0 += KT) {
        // ---- global -> smem (8 bf16 per thread per chunk, 2 chunks) ----
        #pragma unroll
        for (int it = 0; it < 2; ++it) {
            int cid = tid + it * 256;        // 0..511
            int row = cid >> 2;              // 0..127
            int c   = (cid & 3) * 8;         // 0,8,16,24
            *(uint4*)&As[0][row * SMP + c] = *(const uint4*)(Ah + (size_t)row * lda + k0 + c);
            *(uint4*)&As[1][row * SMP + c] = *(const uint4*)(Al + (size_t)row * lda + k0 + c);
            uint4 bh = make_uint4(0u, 0u, 0u, 0u), bl = bh;
            if (n0 + row < N) {
                bh = *(const uint4*)(Bh + (size_t)row * ldb + k0 + c);
                bl = *(const uint4*)(Bl + (size_t)row * ldb + k0 + c);
            }
            *(uint4*)&Bs[0][row * SMP + c] = bh;
            *(uint4*)&Bs[1][row * SMP + c] = bl;
        }
        __syncthreads();

        #pragma unroll
        for (int kk = 0; kk < 2; ++kk) {     // two k16 steps
            uint32_t ah[2][4], al[2][4];
            #pragma unroll
            for (int mi = 0; mi < 2; ++mi) {
                uint32_t addr = sa + ((m0w + mi * 16 + (lane & 15)) * SMP
                                      + kk * 16 + (lane >> 4) * 8) * 2;
                ldsm4(ah[mi], addr);
                ldsm4(al[mi], addr + HALF);
            }
            #pragma unroll
            for (int g = 0; g < 4; ++g) {    // n16 groups
                uint32_t bh[4], bl[4];
                int q = lane >> 3;
                int row = n0w + g * 16 + ((q >> 1) << 3) + (lane & 7);
                int kc  = kk * 16 + (q & 1) * 8;
                uint32_t addr = sbm + (row * SMP + kc) * 2;
                ldsm4(bh, addr);
                ldsm4(bl, addr + HALF);
                #pragma unroll
                for (int mi = 0; mi < 2; ++mi) {
                    mma16816(acc[mi][g * 2 + 0], ah[mi], bh + 0);
                    mma16816(acc[mi][g * 2 + 0], ah[mi], bl + 0);
                    mma16816(acc[mi][g * 2 + 0], al[mi], bh + 0);
                    mma16816(acc[mi][g * 2 + 1], ah[mi], bh + 2);
                    mma16816(acc[mi][g * 2 + 1], ah[mi], bl + 2);
                    mma16816(acc[mi][g * 2 + 1], al[mi], bh + 2);
                }
            }
        }
        __syncthreads();
    }

    // ---- epilogue: direct from accumulators ----
    float* Cb = C + bz * sC;
    bf16* Chb = Chi ? Chi + bz * sC : nullptr;
    bf16* Clb = Clo ? Clo + bz * sC : nullptr;
    const int rb = m0 + m0w + (lane >> 2);
    const int cb = n0 + n0w + (lane & 3) * 2;

    #pragma unroll
    for (int mi = 0; mi < 2; ++mi) {
        #pragma unroll
        for (int ni = 0; ni < 8; ++ni) {
            const int col = cb + ni * 8;
            if (col >= N) continue;
            float b0 = bias ? bias[col] : 0.0f;
            float b1 = bias ? bias[col + 1] : 0.0f;
            #pragma unroll
            for (int h = 0; h < 2; ++h) {
                const int row = rb + mi * 16 + h * 8;
                size_t ix = (size_t)row * ldc + col;
                float v0 = acc[mi][ni][h * 2 + 0] * alpha + b0;
                float v1 = acc[mi][ni][h * 2 + 1] * alpha + b1;
                if (beta) { v0 += Cb[ix]; v1 += Cb[ix + 1]; }
                if (act == 1) {
                    v0 = 1.0f / (1.0f + __expf(-v0));
                    v1 = 1.0f / (1.0f + __expf(-v1));
                }
                if (wr_f32) { Cb[ix] = v0; Cb[ix + 1] = v1; }
                if (Chb) {
                    bf16 hh, ll;
                    split_hl(v0, hh, ll); Chb[ix] = hh; Clb[ix] = ll;
                    split_hl(v1, hh, ll); Chb[ix + 1] = hh; Clb[ix + 1] = ll;
                }
            }
        }
    }
}

// ===========================================================================
// Conversion / transform kernels
// ===========================================================================
__global__ void conv_hilo(const float* __restrict__ src, int lds,
                          bf16* __restrict__ hi, bf16* __restrict__ lo, int ldd,
                          int R, int C)
{
    long long i = (long long)blockIdx.x * blockDim.x + threadIdx.x;
    int c4 = C / 4;
    if (i >= (long long)R * c4) return;
    int r = (int)(i / c4), c = (int)(i % c4) * 4;
    float4 v = *(const float4*)(src + (size_t)r * lds + c);
    bf16 h0, h1, h2, h3, l0, l1, l2, l3;
    split_hl(v.x, h0, l0); split_hl(v.y, h1, l1);
    split_hl(v.z, h2, l2); split_hl(v.w, h3, l3);
    size_t o = (size_t)r * ldd + c;
    hi[o] = h0; hi[o+1] = h1; hi[o+2] = h2; hi[o+3] = h3;
    lo[o] = l0; lo[o+1] = l1; lo[o+2] = l2; lo[o+3] = l3;
}

__global__ void tconv_hilo(const float* __restrict__ src, int lds, long long sS,
                           bf16* __restrict__ hi, bf16* __restrict__ lo, int ldd, long long sD,
                           int R, int C)
{
    __shared__ float t[32][33];
    const float* s = src + blockIdx.z * sS;
    int r0 = blockIdx.y * 32, c0 = blockIdx.x * 32;
    int tx = threadIdx.x, ty = threadIdx.y;   // 32 x 8
    #pragma unroll
    for (int i = 0; i < 32; i += 8) {
        int r = r0 + ty + i, c = c0 + tx;
        if (r < R && c < C) t[ty + i][tx] = s[(size_t)r * lds + c];
    }
    __syncthreads();
    bf16* hb = hi + blockIdx.z * sD;
    bf16* lb = lo + blockIdx.z * sD;
    #pragma unroll
    for (int i = 0; i < 32; i += 8) {
        int c = c0 + ty + i, r = r0 + tx;
        if (r < R && c < C) {
            bf16 h, l; split_hl(t[tx][ty + i], h, l);
            hb[(size_t)c * ldd + r] = h;
            lb[(size_t)c * ldd + r] = l;
        }
    }
}

__global__ void __launch_bounds__(256)
softmax_hilo(const float* __restrict__ src, bf16* __restrict__ hi, bf16* __restrict__ lo, int L)
{
    __shared__ float red[256];
    const float* p = src + (size_t)blockIdx.x * L;
    bf16* ph = hi + (size_t)blockIdx.x * L;
    bf16* pl = lo + (size_t)blockIdx.x * L;
    const int t = threadIdx.x;

    float mx = -1e30f;
    for (int i = t; i < L; i += 256) mx = fmaxf(mx, p[i]);
    red[t] = mx; __syncthreads();
    for (int s = 128; s > 0; s >>= 1) { if (t < s) red[t] = fmaxf(red[t], red[t + s]); __syncthreads(); }
    mx = red[0]; __syncthreads();

    float sum = 0.0f;
    for (int i = t; i < L; i += 256) sum += __expf(p[i] - mx);
    red[t] = sum; __syncthreads();
    for (int s = 128; s > 0; s >>= 1) { if (t < s) red[t] += red[t + s]; __syncthreads(); }
    const float inv = 1.0f / red[0];
    for (int i = t; i < L; i += 256) {
        float v = __expf(p[i] - mx) * inv;
        bf16 h, l; split_hl(v, h, l);
        ph[i] = h; pl[i] = l;
    }
}

__global__ void combine_hilo(const float* __restrict__ a, const float* __restrict__ b,
                             bf16* __restrict__ hi, bf16* __restrict__ lo, long long n)
{
    long long i = (long long)blockIdx.x * blockDim.x + threadIdx.x;
    if (i >= n) return;
    float v = 0.5f * (a[i] + b[i]);
    bf16 h, l; split_hl(v, h, l);
    hi[i] = h; lo[i] = l;
}

__global__ void gated_hilo(const float* __restrict__ z, const float* __restrict__ m,
                           const float* __restrict__ f,
                           bf16* __restrict__ hi, bf16* __restrict__ lo, long long n)
{
    long long i = (long long)blockIdx.x * blockDim.x + threadIdx.x;
    if (i >= n) return;
    float v = fmaxf(0.0f, z[i] + m[i] * f[i]);
    bf16 h, l; split_hl(v, h, l);
    hi[i] = h; lo[i] = l;
}

__global__ void split_heads(const float* __restrict__ qkv,
                            bf16* __restrict__ Qh, bf16* __restrict__ Ql,
                            bf16* __restrict__ Kh, bf16* __restrict__ Kl,
                            float* __restrict__ V)
{
    int i = blockIdx.x * blockDim.x + threadIdx.x;
    const int D4 = DD / 4;
    const int total = BB * HH * NN_ * D4;
    if (i >= total) return;
    int d4 = i % D4;
    int n  = (i / D4) % NN_;
    int h  = (i / (D4 * NN_)) % HH;
    int b  = i / (D4 * NN_ * HH);
    size_t src = (size_t)(b * NN_ + n) * 1536 + h * DD + d4 * 4;
    size_t dst = (size_t)((b * HH + h) * NN_ + n) * DD + d4 * 4;
    float4 q = *(const float4*)(qkv + src);
    float4 k = *(const float4*)(qkv + src + 512);
    float4 v = *(const float4*)(qkv + src + 1024);
    bf16 h0, h1, h2, h3, l0, l1, l2, l3;
    split_hl(q.x, h0, l0); split_hl(q.y, h1, l1); split_hl(q.z, h2, l2); split_hl(q.w, h3, l3);
    Qh[dst] = h0; Qh[dst+1] = h1; Qh[dst+2] = h2; Qh[dst+3] = h3;
    Ql[dst] = l0; Ql[dst+1] = l1; Ql[dst+2] = l2; Ql[dst+3] = l3;
    split_hl(k.x, h0, l0); split_hl(k.y, h1, l1); split_hl(k.z, h2, l2); split_hl(k.w, h3, l3);
    Kh[dst] = h0; Kh[dst+1] = h1; Kh[dst+2] = h2; Kh[dst+3] = h3;
    Kl[dst] = l0; Kl[dst+1] = l1; Kl[dst+2] = l2; Kl[dst+3] = l3;
    *(float4*)(V + dst) = v;
}

__global__ void merge_heads(const float* __restrict__ Hh,
                            bf16* __restrict__ hi, bf16* __restrict__ lo)
{
    int i = blockIdx.x * blockDim.x + threadIdx.x;
    const int D4 = DD / 4;
    const int total = BB * HH * NN_ * D4;
    if (i >= total) return;
    int d4 = i % D4;
    int n  = (i / D4) % NN_;
    int h  = (i / (D4 * NN_)) % HH;
    int b  = i / (D4 * NN_ * HH);
    size_t src = (size_t)((b * HH + h) * NN_ + n) * DD + d4 * 4;
    size_t dst = (size_t)(b * NN_ + n) * FF + h * DD + d4 * 4;
    float4 v = *(const float4*)(Hh + src);
    bf16 h0, h1, h2, h3, l0, l1, l2, l3;
    split_hl(v.x, h0, l0); split_hl(v.y, h1, l1); split_hl(v.z, h2, l2); split_hl(v.w, h3, l3);
    hi[dst] = h0; hi[dst+1] = h1; hi[dst+2] = h2; hi[dst+3] = h3;
    lo[dst] = l0; lo[dst+1] = l1; lo[dst+2] = l2; lo[dst+3] = l3;
}

// ===========================================================================
// Host side
// ===========================================================================
static void tcg(int M, int N, int K,
                const bf16* Ah, const bf16* Al, int lda, long long sA,
                const bf16* Bh, const bf16* Bl, int ldb, long long sB,
                float* C, int ldc, long long sC, int batch,
                float alpha, const float* bias, int beta, int act,
                bf16* Chi, bf16* Clo, int wr_f32)
{
    dim3 grid((N + 127) / 128, M / 128, batch);
    mma_gemm<<<grid, 256>>>(M, N, K, Ah, Al, lda, sA, Bh, Bl, ldb, sB,
                            C, ldc, sC, alpha, bias, beta, act, Chi, Clo, wr_f32);
}

extern "C" void kernel_launch(void* const* d_in, const int* in_sizes, int n_in,
                              void* d_out, int out_size)
{
    (void)in_sizes; (void)n_in; (void)out_size;

    float* F = nullptr; bf16* Bf = nullptr;
    cudaGetSymbolAddress((void**)&F, g_f32);
    cudaGetSymbolAddress((void**)&Bf, g_bf);

    const float* x1     = (const float*)d_in[0];
    const float* x2     = (const float*)d_in[1];
    const float* zb     = (const float*)d_in[2];
    const float* Wqkv_i = (const float*)d_in[3];
    const float* Wqkv_j = (const float*)d_in[4];
    const float* Wqkv_b = (const float*)d_in[5];
    const float* W_f    = (const float*)d_in[6];
    const float* b_f    = (const float*)d_in[7];
    const float* W_m    = (const float*)d_in[8];
    const float* b_m    = (const float*)d_in[9];
    const float* W_QKV  = (const float*)d_in[10];
    const float* W_proj = (const float*)d_in[11];
    const float* b_proj = (const float*)d_in[12];
    float* out = (float*)d_out;

    const float scale = 0.044194173824159216f;   // 512^-0.5
    const float Scale = 0.125f;                  // 64^-0.5
    const int   BN    = BB * NN_;                // 12288

    #define HI(X) (Bf + (X))
    #define LO(X, SZ) (Bf + (X) + (SZ))

    // ---- input conversions ----
    {
        long long n = 12288LL * 512 / 4;
        conv_hilo<<<(unsigned)((n + 255) / 256), 256>>>(x1, 512, HI(B_X1), LO(B_X1, SZ_X1), 512, 12288, 512);
        conv_hilo<<<(unsigned)((n + 255) / 256), 256>>>(x2, 512, HI(B_X2), LO(B_X2, SZ_X2), 512, 12288, 512);
        long long nz = 256LL * 512 / 4;
        conv_hilo<<<(unsigned)((nz + 255) / 256), 256>>>(zb, 512, HI(B_ZB), LO(B_ZB, SZ_ZB), 512, 256, 512);
    }
    // ---- weight transposes (-> [N,K] K-major) ----
    dim3 tb(32, 8);
    tconv_hilo<<<dim3(1536/32, 512/32, 1), tb>>>(Wqkv_b, 1536, 0, HI(B_WB), LO(B_WB, SZ_WB), 512, 0, 512, 1536);
    tconv_hilo<<<dim3(1024/32, 512/32, 1), tb>>>(Wqkv_i + 512, 1536, 0, HI(B_WI), LO(B_WI, SZ_WI), 512, 0, 512, 1024);
    tconv_hilo<<<dim3(512/32, 512/32, 1), tb>>>(Wqkv_j, 1536, 0, HI(B_WJ), LO(B_WJ, SZ_WJ), 512, 0, 512, 512);
    tconv_hilo<<<dim3(512/32, 512/32, 1), tb>>>(W_f, 512, 0, HI(B_WF1), LO(B_WF1, SZ_WF1), 512, 0, 512, 512);
    tconv_hilo<<<dim3(512/32, 512/32, 1), tb>>>(W_f + 512LL*512, 512, 0, HI(B_WF2), LO(B_WF2, SZ_WF2), 512, 0, 512, 512);
    tconv_hilo<<<dim3(512/32, 512/32, 1), tb>>>(W_m, 512, 0, HI(B_WM), LO(B_WM, SZ_WM), 512, 0, 512, 512);
    tconv_hilo<<<dim3(1536/32, 512/32, 1), tb>>>(W_QKV, 1536, 0, HI(B_WQ), LO(B_WQ, SZ_WQ), 512, 0, 512, 1536);
    tconv_hilo<<<dim3(512/32, 512/32, 1), tb>>>(W_proj, 512, 0, HI(B_WP), LO(B_WP, SZ_WP), 512, 0, 512, 512);

    // ---- G1: qkvb = 0.2 * zb @ Wqkv_b  [256,1536] ----
    tcg(256, 1536, 512, HI(B_ZB), LO(B_ZB, SZ_ZB), 512, 0, HI(B_WB), LO(B_WB, SZ_WB), 512, 0,
        F + F_QKVB, 1536, 0, 1, 0.2f, nullptr, 0, 0, HI(B_QKVB), LO(B_QKVB, SZ_QKVB), 1);
    // ---- G2: kvi = x1 @ Wqkv_i[:,512:]  [12288,1024] ----
    tcg(BN, 1024, 512, HI(B_X1), LO(B_X1, SZ_X1), 512, 0, HI(B_WI), LO(B_WI, SZ_WI), 512, 0,
        F + F_KVI, 1024, 0, 1, 1.0f, nullptr, 0, 0, HI(B_KVI), LO(B_KVI, SZ_KVI), 1);
    // ---- G3: qj = x2 @ Wqkv_j[:,0:512]  [12288,512] (bf16 only) ----
    tcg(BN, 512, 512, HI(B_X2), LO(B_X2, SZ_X2), 512, 0, HI(B_WJ), LO(B_WJ, SZ_WJ), 512, 0,
        F + F_S1, 512, 0, 1, 1.0f, nullptr, 0, 0, HI(B_QJ), LO(B_QJ, SZ_QJ), 0);
    // ---- transposes of v_b, v_i ----
    tconv_hilo<<<dim3(512/32, 256/32, 1), tb>>>(F + F_QKVB + 1024, 1536, 0,
        HI(B_VBT), LO(B_VBT, SZ_VBT), 256, 0, 256, 512);
    tconv_hilo<<<dim3(512/32, 768/32, BB), tb>>>(F + F_KVI + 512, 1024, 768LL*1024,
        HI(B_VIT), LO(B_VIT, SZ_VIT), 768, 512LL*768, 768, 512);

    // ---- G4: S1 = scale * q_b @ k_i^T  [16,256,768] ----
    tcg(256, 768, 512, HI(B_QKVB), LO(B_QKVB, SZ_QKVB), 1536, 0,
        HI(B_KVI), LO(B_KVI, SZ_KVI), 1024, 768LL*1024,
        F + F_S1, 768, 256LL*768, BB, scale, nullptr, 0, 0, nullptr, nullptr, 1);
    softmax_hilo<<<BB*256, 256>>>(F + F_S1, HI(B_S1), LO(B_S1, SZ_S1), 768);

    // ---- G5: aib1 = S1 @ v_i  [16,256,512] ----
    tcg(256, 512, 768, HI(B_S1), LO(B_S1, SZ_S1), 768, 256LL*768,
        HI(B_VIT), LO(B_VIT, SZ_VIT), 768, 512LL*768,
        F + F_AIB1, 512, 256LL*512, BB, 1.0f, nullptr, 0, 0, HI(B_AIB1), LO(B_AIB1, SZ_AIB1), 1);
    tconv_hilo<<<dim3(512/32, 256/32, BB), tb>>>(F + F_AIB1, 512, 256LL*512,
        HI(B_AIB1T), LO(B_AIB1T, SZ_AIB1T), 256, 512LL*256, 256, 512);

    // ---- G6: S2 = scale * q_j @ k_b^T  [16,768,256] ----
    tcg(768, 256, 512, HI(B_QJ), LO(B_QJ, SZ_QJ), 512, 768LL*512,
        HI(B_QKVB) + 512, LO(B_QKVB, SZ_QKVB) + 512, 1536, 0,
        F + F_S2, 256, 768LL*256, BB, scale, nullptr, 0, 0, nullptr, nullptr, 1);
    softmax_hilo<<<BB*768, 256>>>(F + F_S2, HI(B_S2), LO(B_S2, SZ_S2), 256);

    // ---- G7: abj = S2 @ v_b  [16,768,512] ----
    tcg(768, 512, 256, HI(B_S2), LO(B_S2, SZ_S2), 256, 768LL*256,
        HI(B_VBT), LO(B_VBT, SZ_VBT), 256, 0,
        F + F_ABJ, 512, 768LL*512, BB, 1.0f, nullptr, 0, 0, nullptr, nullptr, 1);

    // ---- G8: S3 = scale * z_i @ aib1^T  [16,768,256] ----
    tcg(768, 256, 512, HI(B_X1), LO(B_X1, SZ_X1), 512, 768LL*512,
        HI(B_AIB1), LO(B_AIB1, SZ_AIB1), 512, 256LL*512,
        F + F_S3, 256, 768LL*256, BB, scale, nullptr, 0, 0, nullptr, nullptr, 1);
    softmax_hilo<<<BB*768, 256>>>(F + F_S3, HI(B_S3), LO(B_S3, SZ_S3), 256);

    // ---- G9: aij = S3 @ aib1  [16,768,512] ----
    tcg(768, 512, 256, HI(B_S3), LO(B_S3, SZ_S3), 256, 768LL*256,
        HI(B_AIB1T), LO(B_AIB1T, SZ_AIB1T), 256, 512LL*256,
        F + F_AIJ, 512, 768LL*512, BB, 1.0f, nullptr, 0, 0, nullptr, nullptr, 1);

    // ---- combine: aij = 0.5*(aij + abj) -> hi/lo ----
    {
        long long n = 12288LL * 512;
        combine_hilo<<<(unsigned)((n + 255) / 256), 256>>>(F + F_AIJ, F + F_ABJ,
            HI(B_AIJ), LO(B_AIJ, SZ_AIJ), n);
    }

    // ---- G10/G11: f = sigmoid(aij@Wf1 + x2@Wf2 + b_f) ----
    tcg(BN, 512, 512, HI(B_AIJ), LO(B_AIJ, SZ_AIJ), 512, 0, HI(B_WF1), LO(B_WF1, SZ_WF1), 512, 0,
        F + F_FG, 512, 0, 1, 1.0f, b_f, 0, 0, nullptr, nullptr, 1);
    tcg(BN, 512, 512, HI(B_X2), LO(B_X2, SZ_X2), 512, 0, HI(B_WF2), LO(B_WF2, SZ_WF2), 512, 0,
        F + F_FG, 512, 0, 1, 1.0f, nullptr, 1, 1, nullptr, nullptr, 1);
    // ---- G12: m = aij @ W_m + b_m ----
    tcg(BN, 512, 512, HI(B_AIJ), LO(B_AIJ, SZ_AIJ), 512, 0, HI(B_WM), LO(B_WM, SZ_WM), 512, 0,
        F + F_MG, 512, 0, 1, 1.0f, b_m, 0, 0, nullptr, nullptr, 1);
    // ---- h = relu(z_i + m*f) -> hi/lo ----
    {
        long long n = 12288LL * 512;
        gated_hilo<<<(unsigned)((n + 255) / 256), 256>>>(x1, F + F_MG, F + F_FG,
            HI(B_HB), LO(B_HB, SZ_HB), n);
    }

    // ---- G13: QKV = h @ W_QKV  [12288,1536] ----
    tcg(BN, 1536, 512, HI(B_HB), LO(B_HB, SZ_HB), 512, 0, HI(B_WQ), LO(B_WQ, SZ_WQ), 512, 0,
        F + F_QKV, 1536, 0, 1, 1.0f, nullptr, 0, 0, nullptr, nullptr, 1);

    // ---- split heads ----
    {
        int total = BB * HH * NN_ * (DD / 4);
        split_heads<<<(total + 255) / 256, 256>>>(F + F_QKV,
            HI(B_QH), LO(B_QH, SZ_QH), HI(B_KH), LO(B_KH, SZ_KH), F + F_V);
    }
    // V^T per head
    tconv_hilo<<<dim3(64/32, 768/32, BB*HH), tb>>>(F + F_V, 64, 768LL*64,
        HI(B_VT), LO(B_VT, SZ_VT), 768, 64LL*768, 768, 64);

    // ---- G14: S4 = Scale * Q @ K^T  [128,768,768] ----
    tcg(768, 768, 64, HI(B_QH), LO(B_QH, SZ_QH), 64, 768LL*64,
        HI(B_KH), LO(B_KH, SZ_KH), 64, 768LL*64,
        F + F_S4, 768, 768LL*768, BB*HH, Scale, nullptr, 0, 0, nullptr, nullptr, 1);
    softmax_hilo<<<BB*HH*768, 256>>>(F + F_S4, HI(B_S4), LO(B_S4, SZ_S4), 768);

    // ---- G15: Hh = S4 @ V  [128,768,64] ----
    tcg(768, 64, 768, HI(B_S4), LO(B_S4, SZ_S4), 768, 768LL*768,
        HI(B_VT), LO(B_VT, SZ_VT), 768, 64LL*768,
        F + F_HH, 64, 768LL*64, BB*HH, 1.0f, nullptr, 0, 0, nullptr, nullptr, 1);

    // ---- merge heads -> Hc hi/lo ----
    {
        int total = BB * HH * NN_ * (DD / 4);
        merge_heads<<<(total + 255) / 256, 256>>>(F + F_HH, HI(B_HC), LO(B_HC, SZ_HC));
    }

    // ---- G16: out = Hc @ W_proj + b_proj ----
    tcg(BN, 512, 512, HI(B_HC), LO(B_HC, SZ_HC), 512, 0, HI(B_WP), LO(B_WP, SZ_WP), 512, 0,
        out, 512, 0, 1, 1.0f, b_proj, 0, 0, nullptr, nullptr, 1);
}

// round 8
// speedup vs baseline: 2.2187x; 1.2454x over previous
#include <cuda_runtime.h>
#include <cuda_bf16.h>
#include <math.h>
#include <stdint.h>

// Problem constants
#define BB   16
#define NN_  768
#define FF   512
#define NBB  256
#define HH   8
#define DD   64

typedef __nv_bfloat16 bf16;

__device__ __forceinline__ uint32_t smem_u32(const void* p) {
    uint32_t a;
    asm("{ .reg .u64 t; cvta.to.shared.u64 t, %1; cvt.u32.u64 %0, t; }" : "=r"(a) : "l"(p));
    return a;
}

__device__ __forceinline__ void ldsm4(uint32_t* r, uint32_t addr) {
    asm volatile("ldmatrix.sync.aligned.m8n8.x4.shared.b16 {%0,%1,%2,%3}, [%4];"
        : "=r"(r[0]), "=r"(r[1]), "=r"(r[2]), "=r"(r[3]) : "r"(addr));
}

__device__ __forceinline__ void mma16816(float* c, const uint32_t* a, const uint32_t* b) {
    asm volatile(
        "mma.sync.aligned.m16n8k16.row.col.f32.bf16.bf16.f32 "
        "{%0,%1,%2,%3}, {%4,%5,%6,%7}, {%8,%9}, {%0,%1,%2,%3};"
        : "+f"(c[0]), "+f"(c[1]), "+f"(c[2]), "+f"(c[3])
        : "r"(a[0]), "r"(a[1]), "r"(a[2]), "r"(a[3]), "r"(b[0]), "r"(b[1]));
}

__device__ __forceinline__ void split_hl(float v, bf16& h, bf16& l) {
    h = __float2bfloat16(v);
    l = __float2bfloat16(v - __bfloat162float(h));
}

__device__ __forceinline__ uint32_t packb(bf16 lo16, bf16 hi16) {
    __nv_bfloat162 t; t.x = lo16; t.y = hi16;
    return *(uint32_t*)&t;
}

// ===========================================================================
// Scratch buffers
// ===========================================================================
static const long long F_QKVB = 0;                           // 256x1536
static const long long F_KVI  = F_QKVB + 256LL*1536;         // 12288x1024
static const long long F_S1   = F_KVI  + 12288LL*1024;       // 16x256x768
static const long long F_AIB1 = F_S1   + 16LL*256*768;       // 16x256x512
static const long long F_S2   = F_AIB1 + 16LL*256*512;       // 16x768x256
static const long long F_S3   = F_S2   + 16LL*768*256;       // 16x768x256
static const long long F_AIJ  = F_S3   + 16LL*768*256;       // 12288x512 (0.5*abj then +)
static const long long F_FG   = F_AIJ  + 12288LL*512;        // 12288x512
static const long long F_QKV  = F_FG   + 12288LL*512;        // 12288x1536
static const long long F_V    = F_QKV  + 12288LL*1536;       // 16x8x768x64
static const long long F_TOT  = F_V    + 16LL*8*768*64;

__device__ float g_f32[F_TOT];

static const long long B_X1    = 0;                             static const long long SZ_X1    = 12288LL*512;
static const long long B_X2    = B_X1    + 2*SZ_X1;             static const long long SZ_X2    = 12288LL*512;
static const long long B_ZB    = B_X2    + 2*SZ_X2;             static const long long SZ_ZB    = 256LL*512;
static const long long B_WB    = B_ZB    + 2*SZ_ZB;             static const long long SZ_WB    = 1536LL*512;
static const long long B_WI    = B_WB    + 2*SZ_WB;             static const long long SZ_WI    = 1024LL*512;
static const long long B_WJ    = B_WI    + 2*SZ_WI;             static const long long SZ_WJ    = 512LL*512;
static const long long B_WF1   = B_WJ    + 2*SZ_WJ;             static const long long SZ_WF1   = 512LL*512;
static const long long B_WF2   = B_WF1   + 2*SZ_WF1;            static const long long SZ_WF2   = 512LL*512;
static const long long B_WM    = B_WF2   + 2*SZ_WF2;            static const long long SZ_WM    = 512LL*512;
static const long long B_WQ    = B_WM    + 2*SZ_WM;             static const long long SZ_WQ    = 1536LL*512;
static const long long B_WP    = B_WQ    + 2*SZ_WQ;             static const long long SZ_WP    = 512LL*512;
static const long long B_QKVB  = B_WP    + 2*SZ_WP;             static const long long SZ_QKVB  = 256LL*1536;
static const long long B_KVI   = B_QKVB  + 2*SZ_QKVB;           static const long long SZ_KVI   = 12288LL*1024;
static const long long B_QJ    = B_KVI   + 2*SZ_KVI;            static const long long SZ_QJ    = 12288LL*512;
static const long long B_S1    = B_QJ    + 2*SZ_QJ;             static const long long SZ_S1    = 16LL*256*768;
static const long long B_VIT   = B_S1    + 2*SZ_S1;             static const long long SZ_VIT   = 16LL*512*768;
static const long long B_AIB1  = B_VIT   + 2*SZ_VIT;            static const long long SZ_AIB1  = 16LL*256*512;
static const long long B_AIB1T = B_AIB1  + 2*SZ_AIB1;           static const long long SZ_AIB1T = 16LL*512*256;
static const long long B_VBT   = B_AIB1T + 2*SZ_AIB1T;          static const long long SZ_VBT   = 512LL*256;
static const long long B_S2    = B_VBT   + 2*SZ_VBT;            static const long long SZ_S2    = 16LL*768*256;
static const long long B_S3    = B_S2    + 2*SZ_S2;             static const long long SZ_S3    = 16LL*768*256;
static const long long B_AIJ   = B_S3    + 2*SZ_S3;             static const long long SZ_AIJ   = 12288LL*512;
static const long long B_HB    = B_AIJ   + 2*SZ_AIJ;            static const long long SZ_HB    = 12288LL*512;
static const long long B_QH    = B_HB    + 2*SZ_HB;             static const long long SZ_QH    = 16LL*8*768*64;
static const long long B_KH    = B_QH    + 2*SZ_QH;             static const long long SZ_KH    = 16LL*8*768*64;
static const long long B_VT    = B_KH    + 2*SZ_KH;             static const long long SZ_VT    = 16LL*8*64*768;
static const long long B_HC    = B_VT    + 2*SZ_VT;             static const long long SZ_HC    = 12288LL*512;
static const long long B_TOT   = B_HC    + 2*SZ_HC;

__device__ bf16 g_bf[B_TOT];

// ===========================================================================
// mma.sync GEMM + fused epilogues (act=1 sigmoid, act=2 gated relu)
// ===========================================================================
#define KT 32
#define SMP 40

__global__ void __launch_bounds__(256)
mma_gemm(int M, int N, int K,
         const bf16* __restrict__ Ahi, const bf16* __restrict__ Alo, int lda, long long sA,
         const bf16* __restrict__ Bhi, const bf16* __restrict__ Blo, int ldb, long long sB,
         float* __restrict__ C, int ldc, long long sC,
         float alpha, const float* __restrict__ bias, int beta, int act,
         bf16* __restrict__ Chi, bf16* __restrict__ Clo, int wr_f32,
         const float* __restrict__ Gz, const float* __restrict__ Gf)
{
    __shared__ bf16 As[2][128 * SMP];
    __shared__ bf16 Bs[2][128 * SMP];

    const int tid = threadIdx.x, lane = tid & 31, wid = tid >> 5;
    const int bz = blockIdx.z;
    const int m0 = blockIdx.y * 128, n0 = blockIdx.x * 128;
    const int wm = wid & 3, wn = wid >> 2;
    const int m0w = wm * 32, n0w = wn * 64;

    const bf16* Ah = Ahi + bz * sA + (size_t)m0 * lda;
    const bf16* Al = Alo + bz * sA + (size_t)m0 * lda;
    const bf16* Bh = Bhi + bz * sB + (size_t)n0 * ldb;
    const bf16* Bl = Blo + bz * sB + (size_t)n0 * ldb;

    const uint32_t sa = smem_u32(As);
    const uint32_t sbm = smem_u32(Bs);
    const uint32_t HALF = 128 * SMP * 2;

    float acc[2][8][4];
    #pragma unroll
    for (int i = 0; i < 2; ++i)
        #pragma unroll
        for (int j = 0; j < 8; ++j)
            #pragma unroll
            for (int q = 0; q < 4; ++q) acc[i][j][q] = 0.0f;

    for (int k0 = 0; k0 < K; k0 += KT) {
        #pragma unroll
        for (int it = 0; it < 2; ++it) {
            int cid = tid + it * 256;
            int row = cid >> 2;
            int c   = (cid & 3) * 8;
            *(uint4*)&As[0][row * SMP + c] = *(const uint4*)(Ah + (size_t)row * lda + k0 + c);
            *(uint4*)&As[1][row * SMP + c] = *(const uint4*)(Al + (size_t)row * lda + k0 + c);
            uint4 bh = make_uint4(0u, 0u, 0u, 0u), bl = bh;
            if (n0 + row < N) {
                bh = *(const uint4*)(Bh + (size_t)row * ldb + k0 + c);
                bl = *(const uint4*)(Bl + (size_t)row * ldb + k0 + c);
            }
            *(uint4*)&Bs[0][row * SMP + c] = bh;
            *(uint4*)&Bs[1][row * SMP + c] = bl;
        }
        __syncthreads();

        #pragma unroll
        for (int kk = 0; kk < 2; ++kk) {
            uint32_t ah[2][4], al[2][4];
            #pragma unroll
            for (int mi = 0; mi < 2; ++mi) {
                uint32_t addr = sa + ((m0w + mi * 16 + (lane & 15)) * SMP
                                      + kk * 16 + (lane >> 4) * 8) * 2;
                ldsm4(ah[mi], addr);
                ldsm4(al[mi], addr + HALF);
            }
            #pragma unroll
            for (int g = 0; g < 4; ++g) {
                uint32_t bh[4], bl[4];
                int q = lane >> 3;
                int row = n0w + g * 16 + ((q >> 1) << 3) + (lane & 7);
                int kc  = kk * 16 + (q & 1) * 8;
                uint32_t addr = sbm + (row * SMP + kc) * 2;
                ldsm4(bh, addr);
                ldsm4(bl, addr + HALF);
                #pragma unroll
                for (int mi = 0; mi < 2; ++mi) {
                    mma16816(acc[mi][g * 2 + 0], ah[mi], bh + 0);
                    mma16816(acc[mi][g * 2 + 0], ah[mi], bl + 0);
                    mma16816(acc[mi][g * 2 + 0], al[mi], bh + 0);
                    mma16816(acc[mi][g * 2 + 1], ah[mi], bh + 2);
                    mma16816(acc[mi][g * 2 + 1], ah[mi], bl + 2);
                    mma16816(acc[mi][g * 2 + 1], al[mi], bh + 2);
                }
            }
        }
        __syncthreads();
    }

    float* Cb = C + bz * sC;
    bf16* Chb = Chi ? Chi + bz * sC : nullptr;
    bf16* Clb = Clo ? Clo + bz * sC : nullptr;
    const int rb = m0 + m0w + (lane >> 2);
    const int cb = n0 + n0w + (lane & 3) * 2;

    #pragma unroll
    for (int mi = 0; mi < 2; ++mi) {
        #pragma unroll
        for (int ni = 0; ni < 8; ++ni) {
            const int col = cb + ni * 8;
            if (col >= N) continue;
            float b0 = bias ? bias[col] : 0.0f;
            float b1 = bias ? bias[col + 1] : 0.0f;
            #pragma unroll
            for (int h = 0; h < 2; ++h) {
                const int row = rb + mi * 16 + h * 8;
                size_t ix = (size_t)row * ldc + col;
                float v0 = acc[mi][ni][h * 2 + 0] * alpha + b0;
                float v1 = acc[mi][ni][h * 2 + 1] * alpha + b1;
                if (beta) { v0 += Cb[ix]; v1 += Cb[ix + 1]; }
                if (act == 1) {
                    v0 = 1.0f / (1.0f + __expf(-v0));
                    v1 = 1.0f / (1.0f + __expf(-v1));
                } else if (act == 2) {
                    v0 = fmaxf(0.0f, Gz[ix] + v0 * Gf[ix]);
                    v1 = fmaxf(0.0f, Gz[ix + 1] + v1 * Gf[ix + 1]);
                }
                if (wr_f32) { Cb[ix] = v0; Cb[ix + 1] = v1; }
                if (Chb) {
                    bf16 hh, ll;
                    split_hl(v0, hh, ll); Chb[ix] = hh; Clb[ix] = ll;
                    split_hl(v1, hh, ll); Chb[ix + 1] = hh; Clb[ix + 1] = ll;
                }
            }
        }
    }
}

// ===========================================================================
// Fused flash MHSA
// ===========================================================================
#define QPITCH 72
#define VPITCH 136
#define FL_SMEM ((4 * 128 * QPITCH + 2 * 64 * VPITCH) * 2)

__global__ void __launch_bounds__(256)
flash_mhsa(const bf16* __restrict__ Qhp, const bf16* __restrict__ Qlp,
           const bf16* __restrict__ Khp, const bf16* __restrict__ Klp,
           const bf16* __restrict__ VThp, const bf16* __restrict__ VTlp,
           bf16* __restrict__ Ohi, bf16* __restrict__ Olo)
{
    extern __shared__ char sm[];
    bf16* sQh = (bf16*)sm;
    bf16* sQl = sQh + 128 * QPITCH;
    bf16* sKh = sQl + 128 * QPITCH;
    bf16* sKl = sKh + 128 * QPITCH;
    bf16* sVh = sKl + 128 * QPITCH;
    bf16* sVl = sVh + 64 * VPITCH;

    const int bh = blockIdx.x;
    const int mb = blockIdx.y;
    const int tid = threadIdx.x, lane = tid & 31, wid = tid >> 5;

    const size_t qoff = (size_t)bh * 768 * 64 + (size_t)mb * 128 * 64;
    const size_t koff = (size_t)bh * 768 * 64;
    const size_t voff = (size_t)bh * 64 * 768;

    for (int i = tid; i < 1024; i += 256) {
        int r = i >> 3, c = (i & 7) * 8;
        *(uint4*)&sQh[r * QPITCH + c] = *(const uint4*)(Qhp + qoff + (size_t)r * 64 + c);
        *(uint4*)&sQl[r * QPITCH + c] = *(const uint4*)(Qlp + qoff + (size_t)r * 64 + c);
    }

    const uint32_t uQ = smem_u32(sQh);
    const uint32_t uK = smem_u32(sKh);
    const uint32_t uV = smem_u32(sVh);
    const uint32_t QHALF = 128 * QPITCH * 2;
    const uint32_t VHALF = 64 * VPITCH * 2;

    float m_r[2] = {-1e30f, -1e30f};
    float l_r[2] = {0.0f, 0.0f};
    float oacc[8][4];
    #pragma unroll
    for (int j = 0; j < 8; ++j)
        #pragma unroll
        for (int q = 0; q < 4; ++q) oacc[j][q] = 0.0f;

    for (int it = 0; it < 6; ++it) {
        for (int i = tid; i < 1024; i += 256) {
            int r = i >> 3, c = (i & 7) * 8;
            *(uint4*)&sKh[r * QPITCH + c] =
                *(const uint4*)(Khp + koff + (size_t)(it * 128 + r) * 64 + c);
            *(uint4*)&sKl[r * QPITCH + c] =
                *(const uint4*)(Klp + koff + (size_t)(it * 128 + r) * 64 + c);
        }
        for (int i = tid; i < 1024; i += 256) {
            int r = i >> 4, c = (i & 15) * 8;
            *(uint4*)&sVh[r * VPITCH + c] =
                *(const uint4*)(VThp + voff + (size_t)r * 768 + it * 128 + c);
            *(uint4*)&sVl[r * VPITCH + c] =
                *(const uint4*)(VTlp + voff + (size_t)r * 768 + it * 128 + c);
        }
        __syncthreads();

        float sacc[16][4];
        #pragma unroll
        for (int g = 0; g < 16; ++g)
            #pragma unroll
            for (int q = 0; q < 4; ++q) sacc[g][q] = 0.0f;

        #pragma unroll
        for (int kk = 0; kk < 4; ++kk) {
            uint32_t ah[4], al[4];
            uint32_t addr = uQ + ((wid * 16 + (lane & 15)) * QPITCH
                                  + kk * 16 + (lane >> 4) * 8) * 2;
            ldsm4(ah, addr);
            ldsm4(al, addr + QHALF);
            #pragma unroll
            for (int g = 0; g < 8; ++g) {
                uint32_t bh4[4], bl4[4];
                int q = lane >> 3;
                int row = g * 16 + ((q >> 1) << 3) + (lane & 7);
                int kc  = kk * 16 + (q & 1) * 8;
                uint32_t ba = uK + (row * QPITCH + kc) * 2;
                ldsm4(bh4, ba);
                ldsm4(bl4, ba + QHALF);
                mma16816(sacc[g * 2 + 0], ah, bh4 + 0);
                mma16816(sacc[g * 2 + 0], ah, bl4 + 0);
                mma16816(sacc[g * 2 + 0], al, bh4 + 0);
                mma16816(sacc[g * 2 + 1], ah, bh4 + 2);
                mma16816(sacc[g * 2 + 1], ah, bl4 + 2);
                mma16816(sacc[g * 2 + 1], al, bh4 + 2);
            }
        }

        float mx0 = -1e30f, mx1 = -1e30f;
        #pragma unroll
        for (int g = 0; g < 16; ++g) {
            sacc[g][0] *= 0.125f; sacc[g][1] *= 0.125f;
            sacc[g][2] *= 0.125f; sacc[g][3] *= 0.125f;
            mx0 = fmaxf(mx0, fmaxf(sacc[g][0], sacc[g][1]));
            mx1 = fmaxf(mx1, fmaxf(sacc[g][2], sacc[g][3]));
        }
        #pragma unroll
        for (int d = 1; d <= 2; d <<= 1) {
            mx0 = fmaxf(mx0, __shfl_xor_sync(0xffffffffu, mx0, d));
            mx1 = fmaxf(mx1, __shfl_xor_sync(0xffffffffu, mx1, d));
        }
        float mn0 = fmaxf(m_r[0], mx0), mn1 = fmaxf(m_r[1], mx1);
        float al0 = __expf(m_r[0] - mn0), al1 = __expf(m_r[1] - mn1);
        float sum0 = 0.0f, sum1 = 0.0f;
        #pragma unroll
        for (int g = 0; g < 16; ++g) {
            sacc[g][0] = __expf(sacc[g][0] - mn0);
            sacc[g][1] = __expf(sacc[g][1] - mn0);
            sacc[g][2] = __expf(sacc[g][2] - mn1);
            sacc[g][3] = __expf(sacc[g][3] - mn1);
            sum0 += sacc[g][0] + sacc[g][1];
            sum1 += sacc[g][2] + sacc[g][3];
        }
        #pragma unroll
        for (int d = 1; d <= 2; d <<= 1) {
            sum0 += __shfl_xor_sync(0xffffffffu, sum0, d);
            sum1 += __shfl_xor_sync(0xffffffffu, sum1, d);
        }
        l_r[0] = l_r[0] * al0 + sum0;
        l_r[1] = l_r[1] * al1 + sum1;
        m_r[0] = mn0; m_r[1] = mn1;
        #pragma unroll
        for (int j = 0; j < 8; ++j) {
            oacc[j][0] *= al0; oacc[j][1] *= al0;
            oacc[j][2] *= al1; oacc[j][3] *= al1;
        }

        #pragma unroll
        for (int s = 0; s < 8; ++s) {
            uint32_t pah[4], pal[4];
            {
                bf16 h0, l0, h1, l1;
                split_hl(sacc[2*s][0], h0, l0); split_hl(sacc[2*s][1], h1, l1);
                pah[0] = packb(h0, h1); pal[0] = packb(l0, l1);
                split_hl(sacc[2*s][2], h0, l0); split_hl(sacc[2*s][3], h1, l1);
                pah[1] = packb(h0, h1); pal[1] = packb(l0, l1);
                split_hl(sacc[2*s+1][0], h0, l0); split_hl(sacc[2*s+1][1], h1, l1);
                pah[2] = packb(h0, h1); pal[2] = packb(l0, l1);
                split_hl(sacc[2*s+1][2], h0, l0); split_hl(sacc[2*s+1][3], h1, l1);
                pah[3] = packb(h0, h1); pal[3] = packb(l0, l1);
            }
            #pragma unroll
            for (int g = 0; g < 4; ++g) {
                uint32_t bh4[4], bl4[4];
                int q = lane >> 3;
                int row = g * 16 + ((q >> 1) << 3) + (lane & 7);
                int kc  = s * 16 + (q & 1) * 8;
                uint32_t ba = uV + (row * VPITCH + kc) * 2;
                ldsm4(bh4, ba);
                ldsm4(bl4, ba + VHALF);
                mma16816(oacc[g * 2 + 0], pah, bh4 + 0);
                mma16816(oacc[g * 2 + 0], pah, bl4 + 0);
                mma16816(oacc[g * 2 + 0], pal, bh4 + 0);
                mma16816(oacc[g * 2 + 1], pah, bh4 + 2);
                mma16816(oacc[g * 2 + 1], pah, bl4 + 2);
                mma16816(oacc[g * 2 + 1], pal, bh4 + 2);
            }
        }
        __syncthreads();
    }

    const float inv0 = 1.0f / l_r[0], inv1 = 1.0f / l_r[1];
    const int b = bh >> 3, h = bh & 7;
    const int n0g = mb * 128 + wid * 16 + (lane >> 2);
    #pragma unroll
    for (int j = 0; j < 8; ++j) {
        const int d = j * 8 + (lane & 3) * 2;
        {
            size_t ix = ((size_t)(b * 768 + n0g) * 512) + h * 64 + d;
            bf16 h0, l0, h1, l1;
            split_hl(oacc[j][0] * inv0, h0, l0);
            split_hl(oacc[j][1] * inv0, h1, l1);
            *(uint32_t*)(Ohi + ix) = packb(h0, h1);
            *(uint32_t*)(Olo + ix) = packb(l0, l1);
        }
        {
            size_t ix = ((size_t)(b * 768 + n0g + 8) * 512) + h * 64 + d;
            bf16 h0, l0, h1, l1;
            split_hl(oacc[j][2] * inv1, h0, l0);
            split_hl(oacc[j][3] * inv1, h1, l1);
            *(uint32_t*)(Ohi + ix) = packb(h0, h1);
            *(uint32_t*)(Olo + ix) = packb(l0, l1);
        }
    }
}

// ===========================================================================
// Conversion / transform kernels
// ===========================================================================
__global__ void conv_hilo(const float* __restrict__ src, int lds,
                          bf16* __restrict__ hi, bf16* __restrict__ lo, int ldd,
                          int R, int C)
{
    long long i = (long long)blockIdx.x * blockDim.x + threadIdx.x;
    int c4 = C / 4;
    if (i >= (long long)R * c4) return;
    int r = (int)(i / c4), c = (int)(i % c4) * 4;
    float4 v = *(const float4*)(src + (size_t)r * lds + c);
    bf16 h0, h1, h2, h3, l0, l1, l2, l3;
    split_hl(v.x, h0, l0); split_hl(v.y, h1, l1);
    split_hl(v.z, h2, l2); split_hl(v.w, h3, l3);
    size_t o = (size_t)r * ldd + c;
    hi[o] = h0; hi[o+1] = h1; hi[o+2] = h2; hi[o+3] = h3;
    lo[o] = l0; lo[o+1] = l1; lo[o+2] = l2; lo[o+3] = l3;
}

__global__ void tconv_hilo(const float* __restrict__ src, int lds, long long sS,
                           bf16* __restrict__ hi, bf16* __restrict__ lo, int ldd, long long sD,
                           int R, int C)
{
    __shared__ float t[32][33];
    const float* s = src + blockIdx.z * sS;
    int r0 = blockIdx.y * 32, c0 = blockIdx.x * 32;
    int tx = threadIdx.x, ty = threadIdx.y;
    #pragma unroll
    for (int i = 0; i < 32; i += 8) {
        int r = r0 + ty + i, c = c0 + tx;
        if (r < R && c < C) t[ty + i][tx] = s[(size_t)r * lds + c];
    }
    __syncthreads();
    bf16* hb = hi + blockIdx.z * sD;
    bf16* lb = lo + blockIdx.z * sD;
    #pragma unroll
    for (int i = 0; i < 32; i += 8) {
        int c = c0 + ty + i, r = r0 + tx;
        if (r < R && c < C) {
            bf16 h, l; split_hl(t[tx][ty + i], h, l);
            hb[(size_t)c * ldd + r] = h;
            lb[(size_t)c * ldd + r] = l;
        }
    }
}

__global__ void __launch_bounds__(256)
softmax_hilo(const float* __restrict__ src, bf16* __restrict__ hi, bf16* __restrict__ lo, int L)
{
    __shared__ float red[256];
    const float* p = src + (size_t)blockIdx.x * L;
    bf16* ph = hi + (size_t)blockIdx.x * L;
    bf16* pl = lo + (size_t)blockIdx.x * L;
    const int t = threadIdx.x;

    float mx = -1e30f;
    for (int i = t; i < L; i += 256) mx = fmaxf(mx, p[i]);
    red[t] = mx; __syncthreads();
    for (int s = 128; s > 0; s >>= 1) { if (t < s) red[t] = fmaxf(red[t], red[t + s]); __syncthreads(); }
    mx = red[0]; __syncthreads();

    float sum = 0.0f;
    for (int i = t; i < L; i += 256) sum += __expf(p[i] - mx);
    red[t] = sum; __syncthreads();
    for (int s = 128; s > 0; s >>= 1) { if (t < s) red[t] += red[t + s]; __syncthreads(); }
    const float inv = 1.0f / red[0];
    for (int i = t; i < L; i += 256) {
        float v = __expf(p[i] - mx) * inv;
        bf16 h, l; split_hl(v, h, l);
        ph[i] = h; pl[i] = l;
    }
}

__global__ void split_heads(const float* __restrict__ qkv,
                            bf16* __restrict__ Qh, bf16* __restrict__ Ql,
                            bf16* __restrict__ Kh, bf16* __restrict__ Kl,
                            float* __restrict__ V)
{
    int i = blockIdx.x * blockDim.x + threadIdx.x;
    const int D4 = DD / 4;
    const int total = BB * HH * NN_ * D4;
    if (i >= total) return;
    int d4 = i % D4;
    int n  = (i / D4) % NN_;
    int h  = (i / (D4 * NN_)) % HH;
    int b  = i / (D4 * NN_ * HH);
    size_t src = (size_t)(b * NN_ + n) * 1536 + h * DD + d4 * 4;
    size_t dst = (size_t)((b * HH + h) * NN_ + n) * DD + d4 * 4;
    float4 q = *(const float4*)(qkv + src);
    float4 k = *(const float4*)(qkv + src + 512);
    float4 v = *(const float4*)(qkv + src + 1024);
    bf16 h0, h1, h2, h3, l0, l1, l2, l3;
    split_hl(q.x, h0, l0); split_hl(q.y, h1, l1); split_hl(q.z, h2, l2); split_hl(q.w, h3, l3);
    Qh[dst] = h0; Qh[dst+1] = h1; Qh[dst+2] = h2; Qh[dst+3] = h3;
    Ql[dst] = l0; Ql[dst+1] = l1; Ql[dst+2] = l2; Ql[dst+3] = l3;
    split_hl(k.x, h0, l0); split_hl(k.y, h1, l1); split_hl(k.z, h2, l2); split_hl(k.w, h3, l3);
    Kh[dst] = h0; Kh[dst+1] = h1; Kh[dst+2] = h2; Kh[dst+3] = h3;
    Kl[dst] = l0; Kl[dst+1] = l1; Kl[dst+2] = l2; Kl[dst+3] = l3;
    *(float4*)(V + dst) = v;
}

// ===========================================================================
// Host side
// ===========================================================================
static void tcg(int M, int N, int K,
                const bf16* Ah, const bf16* Al, int lda, long long sA,
                const bf16* Bh, const bf16* Bl, int ldb, long long sB,
                float* C, int ldc, long long sC, int batch,
                float alpha, const float* bias, int beta, int act,
                bf16* Chi, bf16* Clo, int wr_f32,
                const float* Gz = nullptr, const float* Gf = nullptr)
{
    dim3 grid((N + 127) / 128, M / 128, batch);
    mma_gemm<<<grid, 256>>>(M, N, K, Ah, Al, lda, sA, Bh, Bl, ldb, sB,
                            C, ldc, sC, alpha, bias, beta, act, Chi, Clo, wr_f32, Gz, Gf);
}

extern "C" void kernel_launch(void* const* d_in, const int* in_sizes, int n_in,
                              void* d_out, int out_size)
{
    (void)in_sizes; (void)n_in; (void)out_size;

    cudaFuncSetAttribute(flash_mhsa, cudaFuncAttributeMaxDynamicSharedMemorySize, FL_SMEM);

    float* F = nullptr; bf16* Bf = nullptr;
    cudaGetSymbolAddress((void**)&F, g_f32);
    cudaGetSymbolAddress((void**)&Bf, g_bf);

    const float* x1     = (const float*)d_in[0];
    const float* x2     = (const float*)d_in[1];
    const float* zb     = (const float*)d_in[2];
    const float* Wqkv_i = (const float*)d_in[3];
    const float* Wqkv_j = (const float*)d_in[4];
    const float* Wqkv_b = (const float*)d_in[5];
    const float* W_f    = (const float*)d_in[6];
    const float* b_f    = (const float*)d_in[7];
    const float* W_m    = (const float*)d_in[8];
    const float* b_m    = (const float*)d_in[9];
    const float* W_QKV  = (const float*)d_in[10];
    const float* W_proj = (const float*)d_in[11];
    const float* b_proj = (const float*)d_in[12];
    float* out = (float*)d_out;

    const float scale = 0.044194173824159216f;   // 512^-0.5
    const int   BN    = BB * NN_;                // 12288

    #define HI(X) (Bf + (X))
    #define LO(X, SZ) (Bf + (X) + (SZ))

    // ---- input conversions ----
    {
        long long n = 12288LL * 512 / 4;
        conv_hilo<<<(unsigned)((n + 255) / 256), 256>>>(x1, 512, HI(B_X1), LO(B_X1, SZ_X1), 512, 12288, 512);
        conv_hilo<<<(unsigned)((n + 255) / 256), 256>>>(x2, 512, HI(B_X2), LO(B_X2, SZ_X2), 512, 12288, 512);
        long long nz = 256LL * 512 / 4;
        conv_hilo<<<(unsigned)((nz + 255) / 256), 256>>>(zb, 512, HI(B_ZB), LO(B_ZB, SZ_ZB), 512, 256, 512);
    }
    // ---- weight transposes (-> [N,K] K-major) ----
    dim3 tb(32, 8);
    tconv_hilo<<<dim3(1536/32, 512/32, 1), tb>>>(Wqkv_b, 1536, 0, HI(B_WB), LO(B_WB, SZ_WB), 512, 0, 512, 1536);
    tconv_hilo<<<dim3(1024/32, 512/32, 1), tb>>>(Wqkv_i + 512, 1536, 0, HI(B_WI), LO(B_WI, SZ_WI), 512, 0, 512, 1024);
    tconv_hilo<<<dim3(512/32, 512/32, 1), tb>>>(Wqkv_j, 1536, 0, HI(B_WJ), LO(B_WJ, SZ_WJ), 512, 0, 512, 512);
    tconv_hilo<<<dim3(512/32, 512/32, 1), tb>>>(W_f, 512, 0, HI(B_WF1), LO(B_WF1, SZ_WF1), 512, 0, 512, 512);
    tconv_hilo<<<dim3(512/32, 512/32, 1), tb>>>(W_f + 512LL*512, 512, 0, HI(B_WF2), LO(B_WF2, SZ_WF2), 512, 0, 512, 512);
    tconv_hilo<<<dim3(512/32, 512/32, 1), tb>>>(W_m, 512, 0, HI(B_WM), LO(B_WM, SZ_WM), 512, 0, 512, 512);
    tconv_hilo<<<dim3(1536/32, 512/32, 1), tb>>>(W_QKV, 1536, 0, HI(B_WQ), LO(B_WQ, SZ_WQ), 512, 0, 512, 1536);
    tconv_hilo<<<dim3(512/32, 512/32, 1), tb>>>(W_proj, 512, 0, HI(B_WP), LO(B_WP, SZ_WP), 512, 0, 512, 512);

    // ---- G1: qkvb = 0.2 * zb @ Wqkv_b  [256,1536] ----
    tcg(256, 1536, 512, HI(B_ZB), LO(B_ZB, SZ_ZB), 512, 0, HI(B_WB), LO(B_WB, SZ_WB), 512, 0,
        F + F_QKVB, 1536, 0, 1, 0.2f, nullptr, 0, 0, HI(B_QKVB), LO(B_QKVB, SZ_QKVB), 1);
    // ---- G2: kvi = x1 @ Wqkv_i[:,512:]  [12288,1024] ----
    tcg(BN, 1024, 512, HI(B_X1), LO(B_X1, SZ_X1), 512, 0, HI(B_WI), LO(B_WI, SZ_WI), 512, 0,
        F + F_KVI, 1024, 0, 1, 1.0f, nullptr, 0, 0, HI(B_KVI), LO(B_KVI, SZ_KVI), 1);
    // ---- G3: qj = x2 @ Wqkv_j[:,0:512]  [12288,512] (bf16 only) ----
    tcg(BN, 512, 512, HI(B_X2), LO(B_X2, SZ_X2), 512, 0, HI(B_WJ), LO(B_WJ, SZ_WJ), 512, 0,
        F + F_S1, 512, 0, 1, 1.0f, nullptr, 0, 0, HI(B_QJ), LO(B_QJ, SZ_QJ), 0);
    // ---- transposes of v_b, v_i ----
    tconv_hilo<<<dim3(512/32, 256/32, 1), tb>>>(F + F_QKVB + 1024, 1536, 0,
        HI(B_VBT), LO(B_VBT, SZ_VBT), 256, 0, 256, 512);
    tconv_hilo<<<dim3(512/32, 768/32, BB), tb>>>(F + F_KVI + 512, 1024, 768LL*1024,
        HI(B_VIT), LO(B_VIT, SZ_VIT), 768, 512LL*768, 768, 512);

    // ---- G4: S1 = scale * q_b @ k_i^T  [16,256,768] ----
    tcg(256, 768, 512, HI(B_QKVB), LO(B_QKVB, SZ_QKVB), 1536, 0,
        HI(B_KVI), LO(B_KVI, SZ_KVI), 1024, 768LL*1024,
        F + F_S1, 768, 256LL*768, BB, scale, nullptr, 0, 0, nullptr, nullptr, 1);
    softmax_hilo<<<BB*256, 256>>>(F + F_S1, HI(B_S1), LO(B_S1, SZ_S1), 768);

    // ---- G5: aib1 = S1 @ v_i  [16,256,512] ----
    tcg(256, 512, 768, HI(B_S1), LO(B_S1, SZ_S1), 768, 256LL*768,
        HI(B_VIT), LO(B_VIT, SZ_VIT), 768, 512LL*768,
        F + F_AIB1, 512, 256LL*512, BB, 1.0f, nullptr, 0, 0, HI(B_AIB1), LO(B_AIB1, SZ_AIB1), 1);
    tconv_hilo<<<dim3(512/32, 256/32, BB), tb>>>(F + F_AIB1, 512, 256LL*512,
        HI(B_AIB1T), LO(B_AIB1T, SZ_AIB1T), 256, 512LL*256, 256, 512);

    // ---- G6: S2 = scale * q_j @ k_b^T  [16,768,256] ----
    tcg(768, 256, 512, HI(B_QJ), LO(B_QJ, SZ_QJ), 512, 768LL*512,
        HI(B_QKVB) + 512, LO(B_QKVB, SZ_QKVB) + 512, 1536, 0,
        F + F_S2, 256, 768LL*256, BB, scale, nullptr, 0, 0, nullptr, nullptr, 1);
    softmax_hilo<<<BB*768, 256>>>(F + F_S2, HI(B_S2), LO(B_S2, SZ_S2), 256);

    // ---- G7: 0.5*abj = 0.5 * S2 @ v_b -> F_AIJ  [16,768,512] ----
    tcg(768, 512, 256, HI(B_S2), LO(B_S2, SZ_S2), 256, 768LL*256,
        HI(B_VBT), LO(B_VBT, SZ_VBT), 256, 0,
        F + F_AIJ, 512, 768LL*512, BB, 0.5f, nullptr, 0, 0, nullptr, nullptr, 1);

    // ---- G8: S3 = scale * z_i @ aib1^T  [16,768,256] ----
    tcg(768, 256, 512, HI(B_X1), LO(B_X1, SZ_X1), 512, 768LL*512,
        HI(B_AIB1), LO(B_AIB1, SZ_AIB1), 512, 256LL*512,
        F + F_S3, 256, 768LL*256, BB, scale, nullptr, 0, 0, nullptr, nullptr, 1);
    softmax_hilo<<<BB*768, 256>>>(F + F_S3, HI(B_S3), LO(B_S3, SZ_S3), 256);

    // ---- G9: aij = 0.5 * S3 @ aib1 + F_AIJ -> hi/lo  [16,768,512] ----
    tcg(768, 512, 256, HI(B_S3), LO(B_S3, SZ_S3), 256, 768LL*256,
        HI(B_AIB1T), LO(B_AIB1T, SZ_AIB1T), 256, 512LL*256,
        F + F_AIJ, 512, 768LL*512, BB, 0.5f, nullptr, 1, 0, HI(B_AIJ), LO(B_AIJ, SZ_AIJ), 0);

    // ---- G10/G11: f = sigmoid(aij@Wf1 + x2@Wf2 + b_f) ----
    tcg(BN, 512, 512, HI(B_AIJ), LO(B_AIJ, SZ_AIJ), 512, 0, HI(B_WF1), LO(B_WF1, SZ_WF1), 512, 0,
        F + F_FG, 512, 0, 1, 1.0f, b_f, 0, 0, nullptr, nullptr, 1);
    tcg(BN, 512, 512, HI(B_X2), LO(B_X2, SZ_X2), 512, 0, HI(B_WF2), LO(B_WF2, SZ_WF2), 512, 0,
        F + F_FG, 512, 0, 1, 1.0f, nullptr, 1, 1, nullptr, nullptr, 1);

    // ---- G12: h = relu(x1 + (aij@W_m + b_m) * f) -> hi/lo (act=2 fused) ----
    tcg(BN, 512, 512, HI(B_AIJ), LO(B_AIJ, SZ_AIJ), 512, 0, HI(B_WM), LO(B_WM, SZ_WM), 512, 0,
        F + F_FG, 512, 0, 1, 1.0f, b_m, 0, 2, HI(B_HB), LO(B_HB, SZ_HB), 0, x1, F + F_FG);

    // ---- G13: QKV = h @ W_QKV  [12288,1536] ----
    tcg(BN, 1536, 512, HI(B_HB), LO(B_HB, SZ_HB), 512, 0, HI(B_WQ), LO(B_WQ, SZ_WQ), 512, 0,
        F + F_QKV, 1536, 0, 1, 1.0f, nullptr, 0, 0, nullptr, nullptr, 1);

    // ---- split heads ----
    {
        int total = BB * HH * NN_ * (DD / 4);
        split_heads<<<(total + 255) / 256, 256>>>(F + F_QKV,
            HI(B_QH), LO(B_QH, SZ_QH), HI(B_KH), LO(B_KH, SZ_KH), F + F_V);
    }
    // V^T per head
    tconv_hilo<<<dim3(64/32, 768/32, BB*HH), tb>>>(F + F_V, 64, 768LL*64,
        HI(B_VT), LO(B_VT, SZ_VT), 768, 64LL*768, 768, 64);

    // ---- fused flash MHSA -> HC hi/lo (merged layout) ----
    flash_mhsa<<<dim3(BB*HH, NN_/128), 256, FL_SMEM>>>(
        HI(B_QH), LO(B_QH, SZ_QH), HI(B_KH), LO(B_KH, SZ_KH),
        HI(B_VT), LO(B_VT, SZ_VT), HI(B_HC), LO(B_HC, SZ_HC));

    // ---- G16: out = Hc @ W_proj + b_proj ----
    tcg(BN, 512, 512, HI(B_HC), LO(B_HC, SZ_HC), 512, 0, HI(B_WP), LO(B_WP, SZ_WP), 512, 0,
        out, 512, 0, 1, 1.0f, b_proj, 0, 0, nullptr, nullptr, 1);
}

// round 9
// speedup vs baseline: 2.2861x; 1.0304x over previous
#include <cuda_runtime.h>
#include <cuda_bf16.h>
#include <math.h>
#include <stdint.h>

// Problem constants
#define BB   16
#define NN_  768
#define FF   512
#define NBB  256
#define HH   8
#define DD   64

typedef __nv_bfloat16 bf16;

__device__ __forceinline__ uint32_t smem_u32(const void* p) {
    uint32_t a;
    asm("{ .reg .u64 t; cvta.to.shared.u64 t, %1; cvt.u32.u64 %0, t; }" : "=r"(a) : "l"(p));
    return a;
}

__device__ __forceinline__ void ldsm4(uint32_t* r, uint32_t addr) {
    asm volatile("ldmatrix.sync.aligned.m8n8.x4.shared.b16 {%0,%1,%2,%3}, [%4];"
        : "=r"(r[0]), "=r"(r[1]), "=r"(r[2]), "=r"(r[3]) : "r"(addr));
}

__device__ __forceinline__ void mma16816(float* c, const uint32_t* a, const uint32_t* b) {
    asm volatile(
        "mma.sync.aligned.m16n8k16.row.col.f32.bf16.bf16.f32 "
        "{%0,%1,%2,%3}, {%4,%5,%6,%7}, {%8,%9}, {%0,%1,%2,%3};"
        : "+f"(c[0]), "+f"(c[1]), "+f"(c[2]), "+f"(c[3])
        : "r"(a[0]), "r"(a[1]), "r"(a[2]), "r"(a[3]), "r"(b[0]), "r"(b[1]));
}

__device__ __forceinline__ void split_hl(float v, bf16& h, bf16& l) {
    h = __float2bfloat16(v);
    l = __float2bfloat16(v - __bfloat162float(h));
}

__device__ __forceinline__ uint32_t packb(bf16 lo16, bf16 hi16) {
    __nv_bfloat162 t; t.x = lo16; t.y = hi16;
    return *(uint32_t*)&t;
}

// ===========================================================================
// Scratch buffers
// ===========================================================================
// fp32: only true intermediates that need fp32 (softmax inputs, gate chain)
static const long long F_S1   = 0;                          // 16x256x768
static const long long F_S2   = F_S1  + 16LL*256*768;       // 16x768x256
static const long long F_S3   = F_S2  + 16LL*768*256;       // 16x768x256
static const long long F_AIJ  = F_S3  + 16LL*768*256;       // 12288x512
static const long long F_FG   = F_AIJ + 12288LL*512;        // 12288x512
static const long long F_TOT  = F_FG  + 12288LL*512;

__device__ float g_f32[F_TOT];

#define PS 6291456LL   // plane size: 16*8*768*64 elements (one Q/K/V hi or lo plane)

static const long long B_X1    = 0;                             static const long long SZ_X1    = 12288LL*512;
static const long long B_X2    = B_X1    + 2*SZ_X1;             static const long long SZ_X2    = 12288LL*512;
static const long long B_ZB    = B_X2    + 2*SZ_X2;             static const long long SZ_ZB    = 256LL*512;
static const long long B_WB    = B_ZB    + 2*SZ_ZB;             static const long long SZ_WB    = 1536LL*512;
static const long long B_WI    = B_WB    + 2*SZ_WB;             static const long long SZ_WI    = 1024LL*512;
static const long long B_WJ    = B_WI    + 2*SZ_WI;             static const long long SZ_WJ    = 512LL*512;
static const long long B_WF1   = B_WJ    + 2*SZ_WJ;             static const long long SZ_WF1   = 512LL*512;
static const long long B_WF2   = B_WF1   + 2*SZ_WF1;            static const long long SZ_WF2   = 512LL*512;
static const long long B_WM    = B_WF2   + 2*SZ_WF2;            static const long long SZ_WM    = 512LL*512;
static const long long B_WQ    = B_WM    + 2*SZ_WM;             static const long long SZ_WQ    = 1536LL*512;
static const long long B_WP    = B_WQ    + 2*SZ_WQ;             static const long long SZ_WP    = 512LL*512;
static const long long B_QKVB  = B_WP    + 2*SZ_WP;             static const long long SZ_QKVB  = 256LL*1536;
static const long long B_KVI   = B_QKVB  + 2*SZ_QKVB;           static const long long SZ_KVI   = 12288LL*1024;
static const long long B_QJ    = B_KVI   + 2*SZ_KVI;            static const long long SZ_QJ    = 12288LL*512;
static const long long B_S1    = B_QJ    + 2*SZ_QJ;             static const long long SZ_S1    = 16LL*256*768;
static const long long B_VIT   = B_S1    + 2*SZ_S1;             static const long long SZ_VIT   = 16LL*512*768;
static const long long B_AIB1  = B_VIT   + 2*SZ_VIT;            static const long long SZ_AIB1  = 16LL*256*512;
static const long long B_AIB1T = B_AIB1  + 2*SZ_AIB1;           static const long long SZ_AIB1T = 16LL*512*256;
static const long long B_VBT   = B_AIB1T + 2*SZ_AIB1T;          static const long long SZ_VBT   = 512LL*256;
static const long long B_S2    = B_VBT   + 2*SZ_VBT;            static const long long SZ_S2    = 16LL*768*256;
static const long long B_S3    = B_S2    + 2*SZ_S2;             static const long long SZ_S3    = 16LL*768*256;
static const long long B_AIJ   = B_S3    + 2*SZ_S3;             static const long long SZ_AIJ   = 12288LL*512;
static const long long B_HB    = B_AIJ   + 2*SZ_AIJ;            static const long long SZ_HB    = 12288LL*512;
static const long long B_QKVH  = B_HB    + 2*SZ_HB;             // 6 planes: Qh,Ql,Kh,Kl,Vh,Vl
static const long long B_VT    = B_QKVH  + 6*PS;                // 2 planes: VT hi, lo
static const long long B_HC    = B_VT    + 2*PS;                static const long long SZ_HC    = 12288LL*512;
static const long long B_TOT   = B_HC    + 2*SZ_HC;

__device__ bf16 g_bf[B_TOT];

// ===========================================================================
// mma.sync GEMM + fused epilogues (act=1 sigmoid, act=2 gated relu,
// qkv=1: scatter to head-split Q/K/V hi/lo planes)
// ===========================================================================
#define KT 32
#define SMP 40

__global__ void __launch_bounds__(256)
mma_gemm(int M, int N, int K,
         const bf16* __restrict__ Ahi, const bf16* __restrict__ Alo, int lda, long long sA,
         const bf16* __restrict__ Bhi, const bf16* __restrict__ Blo, int ldb, long long sB,
         float* __restrict__ C, int ldc, long long sC,
         float alpha, const float* __restrict__ bias, int beta, int act,
         bf16* __restrict__ Chi, bf16* __restrict__ Clo, int wr_f32,
         const float* __restrict__ Gz, const float* __restrict__ Gf, int qkv)
{
    __shared__ bf16 As[2][128 * SMP];
    __shared__ bf16 Bs[2][128 * SMP];

    const int tid = threadIdx.x, lane = tid & 31, wid = tid >> 5;
    const int bz = blockIdx.z;
    const int m0 = blockIdx.y * 128, n0 = blockIdx.x * 128;
    const int wm = wid & 3, wn = wid >> 2;
    const int m0w = wm * 32, n0w = wn * 64;

    const bf16* Ah = Ahi + bz * sA + (size_t)m0 * lda;
    const bf16* Al = Alo + bz * sA + (size_t)m0 * lda;
    const bf16* Bh = Bhi + bz * sB + (size_t)n0 * ldb;
    const bf16* Bl = Blo + bz * sB + (size_t)n0 * ldb;

    const uint32_t sa = smem_u32(As);
    const uint32_t sbm = smem_u32(Bs);
    const uint32_t HALF = 128 * SMP * 2;

    float acc[2][8][4];
    #pragma unroll
    for (int i = 0; i < 2; ++i)
        #pragma unroll
        for (int j = 0; j < 8; ++j)
            #pragma unroll
            for (int q = 0; q < 4; ++q) acc[i][j][q] = 0.0f;

    for (int k0 = 0; k0 < K; k0 += KT) {
        #pragma unroll
        for (int it = 0; it < 2; ++it) {
            int cid = tid + it * 256;
            int row = cid >> 2;
            int c   = (cid & 3) * 8;
            *(uint4*)&As[0][row * SMP + c] = *(const uint4*)(Ah + (size_t)row * lda + k0 + c);
            *(uint4*)&As[1][row * SMP + c] = *(const uint4*)(Al + (size_t)row * lda + k0 + c);
            uint4 bh = make_uint4(0u, 0u, 0u, 0u), bl = bh;
            if (n0 + row < N) {
                bh = *(const uint4*)(Bh + (size_t)row * ldb + k0 + c);
                bl = *(const uint4*)(Bl + (size_t)row * ldb + k0 + c);
            }
            *(uint4*)&Bs[0][row * SMP + c] = bh;
            *(uint4*)&Bs[1][row * SMP + c] = bl;
        }
        __syncthreads();

        #pragma unroll
        for (int kk = 0; kk < 2; ++kk) {
            uint32_t ah[2][4], al[2][4];
            #pragma unroll
            for (int mi = 0; mi < 2; ++mi) {
                uint32_t addr = sa + ((m0w + mi * 16 + (lane & 15)) * SMP
                                      + kk * 16 + (lane >> 4) * 8) * 2;
                ldsm4(ah[mi], addr);
                ldsm4(al[mi], addr + HALF);
            }
            #pragma unroll
            for (int g = 0; g < 4; ++g) {
                uint32_t bh[4], bl[4];
                int q = lane >> 3;
                int row = n0w + g * 16 + ((q >> 1) << 3) + (lane & 7);
                int kc  = kk * 16 + (q & 1) * 8;
                uint32_t addr = sbm + (row * SMP + kc) * 2;
                ldsm4(bh, addr);
                ldsm4(bl, addr + HALF);
                #pragma unroll
                for (int mi = 0; mi < 2; ++mi) {
                    mma16816(acc[mi][g * 2 + 0], ah[mi], bh + 0);
                    mma16816(acc[mi][g * 2 + 0], ah[mi], bl + 0);
                    mma16816(acc[mi][g * 2 + 0], al[mi], bh + 0);
                    mma16816(acc[mi][g * 2 + 1], ah[mi], bh + 2);
                    mma16816(acc[mi][g * 2 + 1], ah[mi], bl + 2);
                    mma16816(acc[mi][g * 2 + 1], al[mi], bh + 2);
                }
            }
        }
        __syncthreads();
    }

    const int rb = m0 + m0w + (lane >> 2);
    const int cb = n0 + n0w + (lane & 3) * 2;

    if (qkv) {
        // scatter epilogue: col -> (t, h, d); row -> (b, n); write hi/lo planes
        #pragma unroll
        for (int mi = 0; mi < 2; ++mi) {
            #pragma unroll
            for (int ni = 0; ni < 8; ++ni) {
                const int col = cb + ni * 8;
                const int t = col >> 9, cw = col & 511;
                const int hh2 = cw >> 6, dd2 = cw & 63;
                bf16* ph = Chi + (long long)t * 2 * PS;
                #pragma unroll
                for (int h2 = 0; h2 < 2; ++h2) {
                    const int row = rb + mi * 16 + h2 * 8;
                    const int b2 = row / 768, n2 = row - b2 * 768;
                    size_t ix = ((size_t)((b2 * 8 + hh2) * 768 + n2)) * 64 + dd2;
                    float v0 = acc[mi][ni][h2 * 2 + 0] * alpha;
                    float v1 = acc[mi][ni][h2 * 2 + 1] * alpha;
                    bf16 h0, l0, h1, l1;
                    split_hl(v0, h0, l0); split_hl(v1, h1, l1);
                    *(uint32_t*)(ph + ix) = packb(h0, h1);
                    *(uint32_t*)(ph + PS + ix) = packb(l0, l1);
                }
            }
        }
        return;
    }

    float* Cb = C + bz * sC;
    bf16* Chb = Chi ? Chi + bz * sC : nullptr;
    bf16* Clb = Clo ? Clo + bz * sC : nullptr;

    #pragma unroll
    for (int mi = 0; mi < 2; ++mi) {
        #pragma unroll
        for (int ni = 0; ni < 8; ++ni) {
            const int col = cb + ni * 8;
            if (col >= N) continue;
            float b0 = bias ? bias[col] : 0.0f;
            float b1 = bias ? bias[col + 1] : 0.0f;
            #pragma unroll
            for (int h = 0; h < 2; ++h) {
                const int row = rb + mi * 16 + h * 8;
                size_t ix = (size_t)row * ldc + col;
                float v0 = acc[mi][ni][h * 2 + 0] * alpha + b0;
                float v1 = acc[mi][ni][h * 2 + 1] * alpha + b1;
                if (beta) { v0 += Cb[ix]; v1 += Cb[ix + 1]; }
                if (act == 1) {
                    v0 = 1.0f / (1.0f + __expf(-v0));
                    v1 = 1.0f / (1.0f + __expf(-v1));
                } else if (act == 2) {
                    v0 = fmaxf(0.0f, Gz[ix] + v0 * Gf[ix]);
                    v1 = fmaxf(0.0f, Gz[ix + 1] + v1 * Gf[ix + 1]);
                }
                if (wr_f32) { Cb[ix] = v0; Cb[ix + 1] = v1; }
                if (Chb) {
                    bf16 hh, ll;
                    split_hl(v0, hh, ll); Chb[ix] = hh; Clb[ix] = ll;
                    split_hl(v1, hh, ll); Chb[ix + 1] = hh; Clb[ix + 1] = ll;
                }
            }
        }
    }
}

// ===========================================================================
// Fused flash MHSA (unchanged from R5 — verified working)
// ===========================================================================
#define QPITCH 72
#define VPITCH 136
#define FL_SMEM ((4 * 128 * QPITCH + 2 * 64 * VPITCH) * 2)

__global__ void __launch_bounds__(256)
flash_mhsa(const bf16* __restrict__ Qhp, const bf16* __restrict__ Qlp,
           const bf16* __restrict__ Khp, const bf16* __restrict__ Klp,
           const bf16* __restrict__ VThp, const bf16* __restrict__ VTlp,
           bf16* __restrict__ Ohi, bf16* __restrict__ Olo)
{
    extern __shared__ char sm[];
    bf16* sQh = (bf16*)sm;
    bf16* sQl = sQh + 128 * QPITCH;
    bf16* sKh = sQl + 128 * QPITCH;
    bf16* sKl = sKh + 128 * QPITCH;
    bf16* sVh = sKl + 128 * QPITCH;
    bf16* sVl = sVh + 64 * VPITCH;

    const int bh = blockIdx.x;
    const int mb = blockIdx.y;
    const int tid = threadIdx.x, lane = tid & 31, wid = tid >> 5;

    const size_t qoff = (size_t)bh * 768 * 64 + (size_t)mb * 128 * 64;
    const size_t koff = (size_t)bh * 768 * 64;
    const size_t voff = (size_t)bh * 64 * 768;

    for (int i = tid; i < 1024; i += 256) {
        int r = i >> 3, c = (i & 7) * 8;
        *(uint4*)&sQh[r * QPITCH + c] = *(const uint4*)(Qhp + qoff + (size_t)r * 64 + c);
        *(uint4*)&sQl[r * QPITCH + c] = *(const uint4*)(Qlp + qoff + (size_t)r * 64 + c);
    }

    const uint32_t uQ = smem_u32(sQh);
    const uint32_t uK = smem_u32(sKh);
    const uint32_t uV = smem_u32(sVh);
    const uint32_t QHALF = 128 * QPITCH * 2;
    const uint32_t VHALF = 64 * VPITCH * 2;

    float m_r[2] = {-1e30f, -1e30f};
    float l_r[2] = {0.0f, 0.0f};
    float oacc[8][4];
    #pragma unroll
    for (int j = 0; j < 8; ++j)
        #pragma unroll
        for (int q = 0; q < 4; ++q) oacc[j][q] = 0.0f;

    for (int it = 0; it < 6; ++it) {
        for (int i = tid; i < 1024; i += 256) {
            int r = i >> 3, c = (i & 7) * 8;
            *(uint4*)&sKh[r * QPITCH + c] =
                *(const uint4*)(Khp + koff + (size_t)(it * 128 + r) * 64 + c);
            *(uint4*)&sKl[r * QPITCH + c] =
                *(const uint4*)(Klp + koff + (size_t)(it * 128 + r) * 64 + c);
        }
        for (int i = tid; i < 1024; i += 256) {
            int r = i >> 4, c = (i & 15) * 8;
            *(uint4*)&sVh[r * VPITCH + c] =
                *(const uint4*)(VThp + voff + (size_t)r * 768 + it * 128 + c);
            *(uint4*)&sVl[r * VPITCH + c] =
                *(const uint4*)(VTlp + voff + (size_t)r * 768 + it * 128 + c);
        }
        __syncthreads();

        float sacc[16][4];
        #pragma unroll
        for (int g = 0; g < 16; ++g)
            #pragma unroll
            for (int q = 0; q < 4; ++q) sacc[g][q] = 0.0f;

        #pragma unroll
        for (int kk = 0; kk < 4; ++kk) {
            uint32_t ah[4], al[4];
            uint32_t addr = uQ + ((wid * 16 + (lane & 15)) * QPITCH
                                  + kk * 16 + (lane >> 4) * 8) * 2;
            ldsm4(ah, addr);
            ldsm4(al, addr + QHALF);
            #pragma unroll
            for (int g = 0; g < 8; ++g) {
                uint32_t bh4[4], bl4[4];
                int q = lane >> 3;
                int row = g * 16 + ((q >> 1) << 3) + (lane & 7);
                int kc  = kk * 16 + (q & 1) * 8;
                uint32_t ba = uK + (row * QPITCH + kc) * 2;
                ldsm4(bh4, ba);
                ldsm4(bl4, ba + QHALF);
                mma16816(sacc[g * 2 + 0], ah, bh4 + 0);
                mma16816(sacc[g * 2 + 0], ah, bl4 + 0);
                mma16816(sacc[g * 2 + 0], al, bh4 + 0);
                mma16816(sacc[g * 2 + 1], ah, bh4 + 2);
                mma16816(sacc[g * 2 + 1], ah, bl4 + 2);
                mma16816(sacc[g * 2 + 1], al, bh4 + 2);
            }
        }

        float mx0 = -1e30f, mx1 = -1e30f;
        #pragma unroll
        for (int g = 0; g < 16; ++g) {
            sacc[g][0] *= 0.125f; sacc[g][1] *= 0.125f;
            sacc[g][2] *= 0.125f; sacc[g][3] *= 0.125f;
            mx0 = fmaxf(mx0, fmaxf(sacc[g][0], sacc[g][1]));
            mx1 = fmaxf(mx1, fmaxf(sacc[g][2], sacc[g][3]));
        }
        #pragma unroll
        for (int d = 1; d <= 2; d <<= 1) {
            mx0 = fmaxf(mx0, __shfl_xor_sync(0xffffffffu, mx0, d));
            mx1 = fmaxf(mx1, __shfl_xor_sync(0xffffffffu, mx1, d));
        }
        float mn0 = fmaxf(m_r[0], mx0), mn1 = fmaxf(m_r[1], mx1);
        float al0 = __expf(m_r[0] - mn0), al1 = __expf(m_r[1] - mn1);
        float sum0 = 0.0f, sum1 = 0.0f;
        #pragma unroll
        for (int g = 0; g < 16; ++g) {
            sacc[g][0] = __expf(sacc[g][0] - mn0);
            sacc[g][1] = __expf(sacc[g][1] - mn0);
            sacc[g][2] = __expf(sacc[g][2] - mn1);
            sacc[g][3] = __expf(sacc[g][3] - mn1);
            sum0 += sacc[g][0] + sacc[g][1];
            sum1 += sacc[g][2] + sacc[g][3];
        }
        #pragma unroll
        for (int d = 1; d <= 2; d <<= 1) {
            sum0 += __shfl_xor_sync(0xffffffffu, sum0, d);
            sum1 += __shfl_xor_sync(0xffffffffu, sum1, d);
        }
        l_r[0] = l_r[0] * al0 + sum0;
        l_r[1] = l_r[1] * al1 + sum1;
        m_r[0] = mn0; m_r[1] = mn1;
        #pragma unroll
        for (int j = 0; j < 8; ++j) {
            oacc[j][0] *= al0; oacc[j][1] *= al0;
            oacc[j][2] *= al1; oacc[j][3] *= al1;
        }

        #pragma unroll
        for (int s = 0; s < 8; ++s) {
            uint32_t pah[4], pal[4];
            {
                bf16 h0, l0, h1, l1;
                split_hl(sacc[2*s][0], h0, l0); split_hl(sacc[2*s][1], h1, l1);
                pah[0] = packb(h0, h1); pal[0] = packb(l0, l1);
                split_hl(sacc[2*s][2], h0, l0); split_hl(sacc[2*s][3], h1, l1);
                pah[1] = packb(h0, h1); pal[1] = packb(l0, l1);
                split_hl(sacc[2*s+1][0], h0, l0); split_hl(sacc[2*s+1][1], h1, l1);
                pah[2] = packb(h0, h1); pal[2] = packb(l0, l1);
                split_hl(sacc[2*s+1][2], h0, l0); split_hl(sacc[2*s+1][3], h1, l1);
                pah[3] = packb(h0, h1); pal[3] = packb(l0, l1);
            }
            #pragma unroll
            for (int g = 0; g < 4; ++g) {
                uint32_t bh4[4], bl4[4];
                int q = lane >> 3;
                int row = g * 16 + ((q >> 1) << 3) + (lane & 7);
                int kc  = s * 16 + (q & 1) * 8;
                uint32_t ba = uV + (row * VPITCH + kc) * 2;
                ldsm4(bh4, ba);
                ldsm4(bl4, ba + VHALF);
                mma16816(oacc[g * 2 + 0], pah, bh4 + 0);
                mma16816(oacc[g * 2 + 0], pah, bl4 + 0);
                mma16816(oacc[g * 2 + 0], pal, bh4 + 0);
                mma16816(oacc[g * 2 + 1], pah, bh4 + 2);
                mma16816(oacc[g * 2 + 1], pah, bl4 + 2);
                mma16816(oacc[g * 2 + 1], pal, bh4 + 2);
            }
        }
        __syncthreads();
    }

    const float inv0 = 1.0f / l_r[0], inv1 = 1.0f / l_r[1];
    const int b = bh >> 3, h = bh & 7;
    const int n0g = mb * 128 + wid * 16 + (lane >> 2);
    #pragma unroll
    for (int j = 0; j < 8; ++j) {
        const int d = j * 8 + (lane & 3) * 2;
        {
            size_t ix = ((size_t)(b * 768 + n0g) * 512) + h * 64 + d;
            bf16 h0, l0, h1, l1;
            split_hl(oacc[j][0] * inv0, h0, l0);
            split_hl(oacc[j][1] * inv0, h1, l1);
            *(uint32_t*)(Ohi + ix) = packb(h0, h1);
            *(uint32_t*)(Olo + ix) = packb(l0, l1);
        }
        {
            size_t ix = ((size_t)(b * 768 + n0g + 8) * 512) + h * 64 + d;
            bf16 h0, l0, h1, l1;
            split_hl(oacc[j][2] * inv1, h0, l0);
            split_hl(oacc[j][3] * inv1, h1, l1);
            *(uint32_t*)(Ohi + ix) = packb(h0, h1);
            *(uint32_t*)(Olo + ix) = packb(l0, l1);
        }
    }
}

// ===========================================================================
// Conversion / transform kernels
// ===========================================================================
__global__ void conv_hilo(const float* __restrict__ src, int lds,
                          bf16* __restrict__ hi, bf16* __restrict__ lo, int ldd,
                          int R, int C)
{
    long long i = (long long)blockIdx.x * blockDim.x + threadIdx.x;
    int c4 = C / 4;
    if (i >= (long long)R * c4) return;
    int r = (int)(i / c4), c = (int)(i % c4) * 4;
    float4 v = *(const float4*)(src + (size_t)r * lds + c);
    bf16 h0, h1, h2, h3, l0, l1, l2, l3;
    split_hl(v.x, h0, l0); split_hl(v.y, h1, l1);
    split_hl(v.z, h2, l2); split_hl(v.w, h3, l3);
    size_t o = (size_t)r * ldd + c;
    hi[o] = h0; hi[o+1] = h1; hi[o+2] = h2; hi[o+3] = h3;
    lo[o] = l0; lo[o+1] = l1; lo[o+2] = l2; lo[o+3] = l3;
}

// fp32 transpose+split (for weights)
__global__ void tconv_hilo(const float* __restrict__ src, int lds, long long sS,
                           bf16* __restrict__ hi, bf16* __restrict__ lo, int ldd, long long sD,
                           int R, int C)
{
    __shared__ float t[32][33];
    const float* s = src + blockIdx.z * sS;
    int r0 = blockIdx.y * 32, c0 = blockIdx.x * 32;
    int tx = threadIdx.x, ty = threadIdx.y;
    #pragma unroll
    for (int i = 0; i < 32; i += 8) {
        int r = r0 + ty + i, c = c0 + tx;
        if (r < R && c < C) t[ty + i][tx] = s[(size_t)r * lds + c];
    }
    __syncthreads();
    bf16* hb = hi + blockIdx.z * sD;
    bf16* lb = lo + blockIdx.z * sD;
    #pragma unroll
    for (int i = 0; i < 32; i += 8) {
        int c = c0 + ty + i, r = r0 + tx;
        if (r < R && c < C) {
            bf16 h, l; split_hl(t[tx][ty + i], h, l);
            hb[(size_t)c * ldd + r] = h;
            lb[(size_t)c * ldd + r] = l;
        }
    }
}

// bf16 hi/lo plane transpose (transpose commutes with the hi/lo split)
__global__ void tconv_bf(const bf16* __restrict__ sh, const bf16* __restrict__ sl,
                         int lds, long long sS,
                         bf16* __restrict__ dh, bf16* __restrict__ dl,
                         int ldd, long long sD, int R, int C)
{
    __shared__ uint32_t t[32][33];   // packed (hi, lo)
    const bf16* ph = sh + blockIdx.z * sS;
    const bf16* pl = sl + blockIdx.z * sS;
    int r0 = blockIdx.y * 32, c0 = blockIdx.x * 32;
    int tx = threadIdx.x, ty = threadIdx.y;
    #pragma unroll
    for (int i = 0; i < 32; i += 8) {
        int r = r0 + ty + i, c = c0 + tx;
        t[ty + i][tx] = packb(ph[(size_t)r * lds + c], pl[(size_t)r * lds + c]);
    }
    __syncthreads();
    bf16* hb = dh + blockIdx.z * sD;
    bf16* lb = dl + blockIdx.z * sD;
    #pragma unroll
    for (int i = 0; i < 32; i += 8) {
        int c = c0 + ty + i, r = r0 + tx;
        uint32_t u = t[tx][ty + i];
        __nv_bfloat162 p = *(__nv_bfloat162*)&u;
        hb[(size_t)c * ldd + r] = p.x;
        lb[(size_t)c * ldd + r] = p.y;
    }
}

__global__ void __launch_bounds__(256)
softmax_hilo(const float* __restrict__ src, bf16* __restrict__ hi, bf16* __restrict__ lo, int L)
{
    __shared__ float red[256];
    const float* p = src + (size_t)blockIdx.x * L;
    bf16* ph = hi + (size_t)blockIdx.x * L;
    bf16* pl = lo + (size_t)blockIdx.x * L;
    const int t = threadIdx.x;

    float mx = -1e30f;
    for (int i = t; i < L; i += 256) mx = fmaxf(mx, p[i]);
    red[t] = mx; __syncthreads();
    for (int s = 128; s > 0; s >>= 1) { if (t < s) red[t] = fmaxf(red[t], red[t + s]); __syncthreads(); }
    mx = red[0]; __syncthreads();

    float sum = 0.0f;
    for (int i = t; i < L; i += 256) sum += __expf(p[i] - mx);
    red[t] = sum; __syncthreads();
    for (int s = 128; s > 0; s >>= 1) { if (t < s) red[t] += red[t + s]; __syncthreads(); }
    const float inv = 1.0f / red[0];
    for (int i = t; i < L; i += 256) {
        float v = __expf(p[i] - mx) * inv;
        bf16 h, l; split_hl(v, h, l);
        ph[i] = h; pl[i] = l;
    }
}

// ===========================================================================
// Host side
// ===========================================================================
static void tcg(int M, int N, int K,
                const bf16* Ah, const bf16* Al, int lda, long long sA,
                const bf16* Bh, const bf16* Bl, int ldb, long long sB,
                float* C, int ldc, long long sC, int batch,
                float alpha, const float* bias, int beta, int act,
                bf16* Chi, bf16* Clo, int wr_f32,
                const float* Gz = nullptr, const float* Gf = nullptr, int qkv = 0)
{
    dim3 grid((N + 127) / 128, M / 128, batch);
    mma_gemm<<<grid, 256>>>(M, N, K, Ah, Al, lda, sA, Bh, Bl, ldb, sB,
                            C, ldc, sC, alpha, bias, beta, act, Chi, Clo, wr_f32, Gz, Gf, qkv);
}

extern "C" void kernel_launch(void* const* d_in, const int* in_sizes, int n_in,
                              void* d_out, int out_size)
{
    (void)in_sizes; (void)n_in; (void)out_size;

    cudaFuncSetAttribute(flash_mhsa, cudaFuncAttributeMaxDynamicSharedMemorySize, FL_SMEM);

    float* F = nullptr; bf16* Bf = nullptr;
    cudaGetSymbolAddress((void**)&F, g_f32);
    cudaGetSymbolAddress((void**)&Bf, g_bf);

    const float* x1     = (const float*)d_in[0];
    const float* x2     = (const float*)d_in[1];
    const float* zb     = (const float*)d_in[2];
    const float* Wqkv_i = (const float*)d_in[3];
    const float* Wqkv_j = (const float*)d_in[4];
    const float* Wqkv_b = (const float*)d_in[5];
    const float* W_f    = (const float*)d_in[6];
    const float* b_f    = (const float*)d_in[7];
    const float* W_m    = (const float*)d_in[8];
    const float* b_m    = (const float*)d_in[9];
    const float* W_QKV  = (const float*)d_in[10];
    const float* W_proj = (const float*)d_in[11];
    const float* b_proj = (const float*)d_in[12];
    float* out = (float*)d_out;

    const float scale = 0.044194173824159216f;   // 512^-0.5
    const int   BN    = BB * NN_;                // 12288

    #define HI(X) (Bf + (X))
    #define LO(X, SZ) (Bf + (X) + (SZ))

    bf16* QKVH = Bf + B_QKVH;   // Qh | Ql | Kh | Kl | Vh | Vl, each PS elements
    bf16* VT   = Bf + B_VT;     // VT hi | VT lo

    // ---- input conversions ----
    {
        long long n = 12288LL * 512 / 4;
        conv_hilo<<<(unsigned)((n + 255) / 256), 256>>>(x1, 512, HI(B_X1), LO(B_X1, SZ_X1), 512, 12288, 512);
        conv_hilo<<<(unsigned)((n + 255) / 256), 256>>>(x2, 512, HI(B_X2), LO(B_X2, SZ_X2), 512, 12288, 512);
        long long nz = 256LL * 512 / 4;
        conv_hilo<<<(unsigned)((nz + 255) / 256), 256>>>(zb, 512, HI(B_ZB), LO(B_ZB, SZ_ZB), 512, 256, 512);
    }
    // ---- weight transposes (-> [N,K] K-major) ----
    dim3 tb(32, 8);
    tconv_hilo<<<dim3(1536/32, 512/32, 1), tb>>>(Wqkv_b, 1536, 0, HI(B_WB), LO(B_WB, SZ_WB), 512, 0, 512, 1536);
    tconv_hilo<<<dim3(1024/32, 512/32, 1), tb>>>(Wqkv_i + 512, 1536, 0, HI(B_WI), LO(B_WI, SZ_WI), 512, 0, 512, 1024);
    tconv_hilo<<<dim3(512/32, 512/32, 1), tb>>>(Wqkv_j, 1536, 0, HI(B_WJ), LO(B_WJ, SZ_WJ), 512, 0, 512, 512);
    tconv_hilo<<<dim3(512/32, 512/32, 1), tb>>>(W_f, 512, 0, HI(B_WF1), LO(B_WF1, SZ_WF1), 512, 0, 512, 512);
    tconv_hilo<<<dim3(512/32, 512/32, 1), tb>>>(W_f + 512LL*512, 512, 0, HI(B_WF2), LO(B_WF2, SZ_WF2), 512, 0, 512, 512);
    tconv_hilo<<<dim3(512/32, 512/32, 1), tb>>>(W_m, 512, 0, HI(B_WM), LO(B_WM, SZ_WM), 512, 0, 512, 512);
    tconv_hilo<<<dim3(1536/32, 512/32, 1), tb>>>(W_QKV, 1536, 0, HI(B_WQ), LO(B_WQ, SZ_WQ), 512, 0, 512, 1536);
    tconv_hilo<<<dim3(512/32, 512/32, 1), tb>>>(W_proj, 512, 0, HI(B_WP), LO(B_WP, SZ_WP), 512, 0, 512, 512);

    // ---- G1: qkvb = 0.2 * zb @ Wqkv_b  [256,1536] (hi/lo only) ----
    tcg(256, 1536, 512, HI(B_ZB), LO(B_ZB, SZ_ZB), 512, 0, HI(B_WB), LO(B_WB, SZ_WB), 512, 0,
        F, 1536, 0, 1, 0.2f, nullptr, 0, 0, HI(B_QKVB), LO(B_QKVB, SZ_QKVB), 0);
    // ---- G2: kvi = x1 @ Wqkv_i[:,512:]  [12288,1024] (hi/lo only) ----
    tcg(BN, 1024, 512, HI(B_X1), LO(B_X1, SZ_X1), 512, 0, HI(B_WI), LO(B_WI, SZ_WI), 512, 0,
        F, 1024, 0, 1, 1.0f, nullptr, 0, 0, HI(B_KVI), LO(B_KVI, SZ_KVI), 0);
    // ---- G3: qj = x2 @ Wqkv_j[:,0:512]  [12288,512] (hi/lo only) ----
    tcg(BN, 512, 512, HI(B_X2), LO(B_X2, SZ_X2), 512, 0, HI(B_WJ), LO(B_WJ, SZ_WJ), 512, 0,
        F, 512, 0, 1, 1.0f, nullptr, 0, 0, HI(B_QJ), LO(B_QJ, SZ_QJ), 0);
    // ---- transposes of v_b, v_i (bf16-plane transpose; value-preserving) ----
    tconv_bf<<<dim3(512/32, 256/32, 1), tb>>>(HI(B_QKVB) + 1024, LO(B_QKVB, SZ_QKVB) + 1024, 1536, 0,
        HI(B_VBT), LO(B_VBT, SZ_VBT), 256, 0, 256, 512);
    tconv_bf<<<dim3(512/32, 768/32, BB), tb>>>(HI(B_KVI) + 512, LO(B_KVI, SZ_KVI) + 512, 1024, 768LL*1024,
        HI(B_VIT), LO(B_VIT, SZ_VIT), 768, 512LL*768, 768, 512);

    // ---- G4: S1 = scale * q_b @ k_i^T  [16,256,768] ----
    tcg(256, 768, 512, HI(B_QKVB), LO(B_QKVB, SZ_QKVB), 1536, 0,
        HI(B_KVI), LO(B_KVI, SZ_KVI), 1024, 768LL*1024,
        F + F_S1, 768, 256LL*768, BB, scale, nullptr, 0, 0, nullptr, nullptr, 1);
    softmax_hilo<<<BB*256, 256>>>(F + F_S1, HI(B_S1), LO(B_S1, SZ_S1), 768);

    // ---- G5: aib1 = S1 @ v_i  [16,256,512] (hi/lo only) ----
    tcg(256, 512, 768, HI(B_S1), LO(B_S1, SZ_S1), 768, 256LL*768,
        HI(B_VIT), LO(B_VIT, SZ_VIT), 768, 512LL*768,
        F, 512, 256LL*512, BB, 1.0f, nullptr, 0, 0, HI(B_AIB1), LO(B_AIB1, SZ_AIB1), 0);
    tconv_bf<<<dim3(512/32, 256/32, BB), tb>>>(HI(B_AIB1), LO(B_AIB1, SZ_AIB1), 512, 256LL*512,
        HI(B_AIB1T), LO(B_AIB1T, SZ_AIB1T), 256, 512LL*256, 256, 512);

    // ---- G6: S2 = scale * q_j @ k_b^T  [16,768,256] ----
    tcg(768, 256, 512, HI(B_QJ), LO(B_QJ, SZ_QJ), 512, 768LL*512,
        HI(B_QKVB) + 512, LO(B_QKVB, SZ_QKVB) + 512, 1536, 0,
        F + F_S2, 256, 768LL*256, BB, scale, nullptr, 0, 0, nullptr, nullptr, 1);
    softmax_hilo<<<BB*768, 256>>>(F + F_S2, HI(B_S2), LO(B_S2, SZ_S2), 256);

    // ---- G7: 0.5*abj -> F_AIJ  [16,768,512] ----
    tcg(768, 512, 256, HI(B_S2), LO(B_S2, SZ_S2), 256, 768LL*256,
        HI(B_VBT), LO(B_VBT, SZ_VBT), 256, 0,
        F + F_AIJ, 512, 768LL*512, BB, 0.5f, nullptr, 0, 0, nullptr, nullptr, 1);

    // ---- G8: S3 = scale * z_i @ aib1^T  [16,768,256] ----
    tcg(768, 256, 512, HI(B_X1), LO(B_X1, SZ_X1), 512, 768LL*512,
        HI(B_AIB1), LO(B_AIB1, SZ_AIB1), 512, 256LL*512,
        F + F_S3, 256, 768LL*256, BB, scale, nullptr, 0, 0, nullptr, nullptr, 1);
    softmax_hilo<<<BB*768, 256>>>(F + F_S3, HI(B_S3), LO(B_S3, SZ_S3), 256);

    // ---- G9: aij = 0.5 * S3 @ aib1 + F_AIJ -> hi/lo ----
    tcg(768, 512, 256, HI(B_S3), LO(B_S3, SZ_S3), 256, 768LL*256,
        HI(B_AIB1T), LO(B_AIB1T, SZ_AIB1T), 256, 512LL*256,
        F + F_AIJ, 512, 768LL*512, BB, 0.5f, nullptr, 1, 0, HI(B_AIJ), LO(B_AIJ, SZ_AIJ), 0);

    // ---- G10/G11: f = sigmoid(aij@Wf1 + x2@Wf2 + b_f) ----
    tcg(BN, 512, 512, HI(B_AIJ), LO(B_AIJ, SZ_AIJ), 512, 0, HI(B_WF1), LO(B_WF1, SZ_WF1), 512, 0,
        F + F_FG, 512, 0, 1, 1.0f, b_f, 0, 0, nullptr, nullptr, 1);
    tcg(BN, 512, 512, HI(B_X2), LO(B_X2, SZ_X2), 512, 0, HI(B_WF2), LO(B_WF2, SZ_WF2), 512, 0,
        F + F_FG, 512, 0, 1, 1.0f, nullptr, 1, 1, nullptr, nullptr, 1);

    // ---- G12: h = relu(x1 + (aij@W_m + b_m) * f) -> hi/lo (act=2 fused) ----
    tcg(BN, 512, 512, HI(B_AIJ), LO(B_AIJ, SZ_AIJ), 512, 0, HI(B_WM), LO(B_WM, SZ_WM), 512, 0,
        F + F_FG, 512, 0, 1, 1.0f, b_m, 0, 2, HI(B_HB), LO(B_HB, SZ_HB), 0, x1, F + F_FG);

    // ---- G13: QKV = h @ W_QKV -> Q/K/V hi/lo head-split planes (qkv epilogue) ----
    tcg(BN, 1536, 512, HI(B_HB), LO(B_HB, SZ_HB), 512, 0, HI(B_WQ), LO(B_WQ, SZ_WQ), 512, 0,
        F, 1536, 0, 1, 1.0f, nullptr, 0, 0, QKVH, nullptr, 0, nullptr, nullptr, 1);

    // ---- V^T per head (bf16-plane transpose from head-layout V) ----
    tconv_bf<<<dim3(64/32, 768/32, BB*HH), tb>>>(QKVH + 4*PS, QKVH + 5*PS, 64, 768LL*64,
        VT, VT + PS, 768, 64LL*768, 768, 64);

    // ---- fused flash MHSA -> HC hi/lo (merged layout) ----
    flash_mhsa<<<dim3(BB*HH, NN_/128), 256, FL_SMEM>>>(
        QKVH, QKVH + PS, QKVH + 2*PS, QKVH + 3*PS,
        VT, VT + PS, HI(B_HC), LO(B_HC, SZ_HC));

    // ---- G16: out = Hc @ W_proj + b_proj ----
    tcg(BN, 512, 512, HI(B_HC), LO(B_HC, SZ_HC), 512, 0, HI(B_WP), LO(B_WP, SZ_WP), 512, 0,
        out, 512, 0, 1, 1.0f, b_proj, 0, 0, nullptr, nullptr, 1);
}

// round 10
// speedup vs baseline: 2.4214x; 1.0592x over previous
#include <cuda_runtime.h>
#include <cuda_bf16.h>
#include <math.h>
#include <stdint.h>

// Problem constants
#define BB   16
#define NN_  768
#define FF   512
#define NBB  256
#define HH   8
#define DD   64

typedef __nv_bfloat16 bf16;

__device__ __forceinline__ uint32_t smem_u32(const void* p) {
    uint32_t a;
    asm("{ .reg .u64 t; cvta.to.shared.u64 t, %1; cvt.u32.u64 %0, t; }" : "=r"(a) : "l"(p));
    return a;
}

__device__ __forceinline__ void ldsm4(uint32_t* r, uint32_t addr) {
    asm volatile("ldmatrix.sync.aligned.m8n8.x4.shared.b16 {%0,%1,%2,%3}, [%4];"
        : "=r"(r[0]), "=r"(r[1]), "=r"(r[2]), "=r"(r[3]) : "r"(addr));
}

__device__ __forceinline__ void mma16816(float* c, const uint32_t* a, const uint32_t* b) {
    asm volatile(
        "mma.sync.aligned.m16n8k16.row.col.f32.bf16.bf16.f32 "
        "{%0,%1,%2,%3}, {%4,%5,%6,%7}, {%8,%9}, {%0,%1,%2,%3};"
        : "+f"(c[0]), "+f"(c[1]), "+f"(c[2]), "+f"(c[3])
        : "r"(a[0]), "r"(a[1]), "r"(a[2]), "r"(a[3]), "r"(b[0]), "r"(b[1]));
}

__device__ __forceinline__ void split_hl(float v, bf16& h, bf16& l) {
    h = __float2bfloat16(v);
    l = __float2bfloat16(v - __bfloat162float(h));
}

__device__ __forceinline__ uint32_t packb(bf16 lo16, bf16 hi16) {
    __nv_bfloat162 t; t.x = lo16; t.y = hi16;
    return *(uint32_t*)&t;
}

// cp.async helpers (16B)
__device__ __forceinline__ void cp16(uint32_t d, const void* s) {
    asm volatile("cp.async.cg.shared.global [%0], [%1], 16;" :: "r"(d), "l"(s));
}
__device__ __forceinline__ void cp16z(uint32_t d, const void* s, int srcsz) {
    asm volatile("cp.async.cg.shared.global [%0], [%1], 16, %2;" :: "r"(d), "l"(s), "r"(srcsz));
}
#define CP_COMMIT() asm volatile("cp.async.commit_group;" ::: "memory")
#define CP_WAIT0()  asm volatile("cp.async.wait_group 0;" ::: "memory")
#define CP_WAIT1()  asm volatile("cp.async.wait_group 1;" ::: "memory")

// ===========================================================================
// Scratch buffers
// ===========================================================================
static const long long F_S1   = 0;                          // 16x256x768
static const long long F_S2   = F_S1  + 16LL*256*768;       // 16x768x256
static const long long F_S3   = F_S2  + 16LL*768*256;       // 16x768x256
static const long long F_AIJ  = F_S3  + 16LL*768*256;       // 12288x512
static const long long F_FG   = F_AIJ + 12288LL*512;        // 12288x512
static const long long F_TOT  = F_FG  + 12288LL*512;

__device__ float g_f32[F_TOT];

#define PS 6291456LL   // plane size: 16*8*768*64

static const long long B_X1    = 0;                             static const long long SZ_X1    = 12288LL*512;
static const long long B_X2    = B_X1    + 2*SZ_X1;             static const long long SZ_X2    = 12288LL*512;
static const long long B_ZB    = B_X2    + 2*SZ_X2;             static const long long SZ_ZB    = 256LL*512;
static const long long B_WB    = B_ZB    + 2*SZ_ZB;             static const long long SZ_WB    = 1536LL*512;
static const long long B_WI    = B_WB    + 2*SZ_WB;             static const long long SZ_WI    = 1024LL*512;
static const long long B_WJ    = B_WI    + 2*SZ_WI;             static const long long SZ_WJ    = 512LL*512;
static const long long B_WF1   = B_WJ    + 2*SZ_WJ;             static const long long SZ_WF1   = 512LL*512;
static const long long B_WF2   = B_WF1   + 2*SZ_WF1;            static const long long SZ_WF2   = 512LL*512;
static const long long B_WM    = B_WF2   + 2*SZ_WF2;            static const long long SZ_WM    = 512LL*512;
static const long long B_WQ    = B_WM    + 2*SZ_WM;             static const long long SZ_WQ    = 1536LL*512;
static const long long B_WP    = B_WQ    + 2*SZ_WQ;             static const long long SZ_WP    = 512LL*512;
static const long long B_QKVB  = B_WP    + 2*SZ_WP;             static const long long SZ_QKVB  = 256LL*1536;
static const long long B_KVI   = B_QKVB  + 2*SZ_QKVB;           static const long long SZ_KVI   = 12288LL*1024;
static const long long B_QJ    = B_KVI   + 2*SZ_KVI;            static const long long SZ_QJ    = 12288LL*512;
static const long long B_S1    = B_QJ    + 2*SZ_QJ;             static const long long SZ_S1    = 16LL*256*768;
static const long long B_VIT   = B_S1    + 2*SZ_S1;             static const long long SZ_VIT   = 16LL*512*768;
static const long long B_AIB1  = B_VIT   + 2*SZ_VIT;            static const long long SZ_AIB1  = 16LL*256*512;
static const long long B_AIB1T = B_AIB1  + 2*SZ_AIB1;           static const long long SZ_AIB1T = 16LL*512*256;
static const long long B_VBT   = B_AIB1T + 2*SZ_AIB1T;          static const long long SZ_VBT   = 512LL*256;
static const long long B_S2    = B_VBT   + 2*SZ_VBT;            static const long long SZ_S2    = 16LL*768*256;
static const long long B_S3    = B_S2    + 2*SZ_S2;             static const long long SZ_S3    = 16LL*768*256;
static const long long B_AIJ   = B_S3    + 2*SZ_S3;             static const long long SZ_AIJ   = 12288LL*512;
static const long long B_HB    = B_AIJ   + 2*SZ_AIJ;            static const long long SZ_HB    = 12288LL*512;
static const long long B_QKVH  = B_HB    + 2*SZ_HB;             // 6 planes
static const long long B_VT    = B_QKVH  + 6*PS;                // 2 planes
static const long long B_HC    = B_VT    + 2*PS;                static const long long SZ_HC    = 12288LL*512;
static const long long B_TOT   = B_HC    + 2*SZ_HC;

__device__ bf16 g_bf[B_TOT];

// ===========================================================================
// mma.sync GEMM, cp.async 2-stage pipelined mainloop + fused epilogues
// ===========================================================================
#define KT 32
#define SMP 40
#define HALFB  (128 * SMP * 2)      // bytes per plane
#define STGB   (4 * HALFB)          // bytes per stage (Ah|Al|Bh|Bl)
#define GEMM_SMEM (2 * STGB)        // 81920 bytes

__global__ void __launch_bounds__(256)
mma_gemm(int M, int N, int K,
         const bf16* __restrict__ Ahi, const bf16* __restrict__ Alo, int lda, long long sA,
         const bf16* __restrict__ Bhi, const bf16* __restrict__ Blo, int ldb, long long sB,
         float* __restrict__ C, int ldc, long long sC,
         float alpha, const float* __restrict__ bias, int beta, int act,
         bf16* __restrict__ Chi, bf16* __restrict__ Clo, int wr_f32,
         const float* __restrict__ Gz, const float* __restrict__ Gf, int qkv)
{
    extern __shared__ bf16 smbuf[];
    const uint32_t sbase = smem_u32(smbuf);

    const int tid = threadIdx.x, lane = tid & 31, wid = tid >> 5;
    const int bz = blockIdx.z;
    const int m0 = blockIdx.y * 128, n0 = blockIdx.x * 128;
    const int wm = wid & 3, wn = wid >> 2;
    const int m0w = wm * 32, n0w = wn * 64;

    const bf16* Ah = Ahi + bz * sA + (size_t)m0 * lda;
    const bf16* Al = Alo + bz * sA + (size_t)m0 * lda;
    const bf16* Bh = Bhi + bz * sB + (size_t)n0 * ldb;
    const bf16* Bl = Blo + bz * sB + (size_t)n0 * ldb;

    // per-thread load coords (2 chunks of 16B each per plane)
    const int r0c = (tid * 2) >> 3;            // iter0: cid=tid*? keep original mapping
    (void)r0c;

    float acc[2][8][4];
    #pragma unroll
    for (int i = 0; i < 2; ++i)
        #pragma unroll
        for (int j = 0; j < 8; ++j)
            #pragma unroll
            for (int q = 0; q < 4; ++q) acc[i][j][q] = 0.0f;

    const int nk = K / KT;

    // ---- stage loader ----
    auto load_stage = [&](int st, int k0) {
        const uint32_t sb0 = sbase + st * STGB;
        #pragma unroll
        for (int it = 0; it < 2; ++it) {
            int cid = tid + it * 256;
            int row = cid >> 2;
            int c   = (cid & 3) * 8;
            uint32_t off = (uint32_t)(row * SMP + c) * 2;
            cp16(sb0 + off,             Ah + (size_t)row * lda + k0 + c);
            cp16(sb0 + HALFB + off,     Al + (size_t)row * lda + k0 + c);
            int ok = (n0 + row < N) ? 16 : 0;
            cp16z(sb0 + 2 * HALFB + off, Bh + (size_t)row * ldb + k0 + c, ok);
            cp16z(sb0 + 3 * HALFB + off, Bl + (size_t)row * ldb + k0 + c, ok);
        }
    };

    load_stage(0, 0);
    CP_COMMIT();

    for (int i = 0; i < nk; ++i) {
        if (i + 1 < nk) { load_stage((i + 1) & 1, (i + 1) * KT); CP_COMMIT(); }
        if (i + 1 < nk) CP_WAIT1(); else CP_WAIT0();
        __syncthreads();

        const uint32_t sa  = sbase + (i & 1) * STGB;
        const uint32_t sbm = sa + 2 * HALFB;

        #pragma unroll
        for (int kk = 0; kk < 2; ++kk) {
            uint32_t ah[2][4], al[2][4];
            #pragma unroll
            for (int mi = 0; mi < 2; ++mi) {
                uint32_t addr = sa + ((m0w + mi * 16 + (lane & 15)) * SMP
                                      + kk * 16 + (lane >> 4) * 8) * 2;
                ldsm4(ah[mi], addr);
                ldsm4(al[mi], addr + HALFB);
            }
            #pragma unroll
            for (int g = 0; g < 4; ++g) {
                uint32_t bh[4], bl[4];
                int q = lane >> 3;
                int row = n0w + g * 16 + ((q >> 1) << 3) + (lane & 7);
                int kc  = kk * 16 + (q & 1) * 8;
                uint32_t addr = sbm + (row * SMP + kc) * 2;
                ldsm4(bh, addr);
                ldsm4(bl, addr + HALFB);
                #pragma unroll
                for (int mi = 0; mi < 2; ++mi) {
                    mma16816(acc[mi][g * 2 + 0], ah[mi], bh + 0);
                    mma16816(acc[mi][g * 2 + 0], ah[mi], bl + 0);
                    mma16816(acc[mi][g * 2 + 0], al[mi], bh + 0);
                    mma16816(acc[mi][g * 2 + 1], ah[mi], bh + 2);
                    mma16816(acc[mi][g * 2 + 1], ah[mi], bl + 2);
                    mma16816(acc[mi][g * 2 + 1], al[mi], bh + 2);
                }
            }
        }
        __syncthreads();
    }

    const int rb = m0 + m0w + (lane >> 2);
    const int cb = n0 + n0w + (lane & 3) * 2;

    if (qkv) {
        #pragma unroll
        for (int mi = 0; mi < 2; ++mi) {
            #pragma unroll
            for (int ni = 0; ni < 8; ++ni) {
                const int col = cb + ni * 8;
                const int t = col >> 9, cw = col & 511;
                const int hh2 = cw >> 6, dd2 = cw & 63;
                bf16* ph = Chi + (long long)t * 2 * PS;
                #pragma unroll
                for (int h2 = 0; h2 < 2; ++h2) {
                    const int row = rb + mi * 16 + h2 * 8;
                    const int b2 = row / 768, n2 = row - b2 * 768;
                    size_t ix = ((size_t)((b2 * 8 + hh2) * 768 + n2)) * 64 + dd2;
                    float v0 = acc[mi][ni][h2 * 2 + 0] * alpha;
                    float v1 = acc[mi][ni][h2 * 2 + 1] * alpha;
                    bf16 h0, l0, h1, l1;
                    split_hl(v0, h0, l0); split_hl(v1, h1, l1);
                    *(uint32_t*)(ph + ix) = packb(h0, h1);
                    *(uint32_t*)(ph + PS + ix) = packb(l0, l1);
                }
            }
        }
        return;
    }

    float* Cb = C + bz * sC;
    bf16* Chb = Chi ? Chi + bz * sC : nullptr;
    bf16* Clb = Clo ? Clo + bz * sC : nullptr;

    #pragma unroll
    for (int mi = 0; mi < 2; ++mi) {
        #pragma unroll
        for (int ni = 0; ni < 8; ++ni) {
            const int col = cb + ni * 8;
            if (col >= N) continue;
            float b0 = bias ? bias[col] : 0.0f;
            float b1 = bias ? bias[col + 1] : 0.0f;
            #pragma unroll
            for (int h = 0; h < 2; ++h) {
                const int row = rb + mi * 16 + h * 8;
                size_t ix = (size_t)row * ldc + col;
                float v0 = acc[mi][ni][h * 2 + 0] * alpha + b0;
                float v1 = acc[mi][ni][h * 2 + 1] * alpha + b1;
                if (beta) { v0 += Cb[ix]; v1 += Cb[ix + 1]; }
                if (act == 1) {
                    v0 = 1.0f / (1.0f + __expf(-v0));
                    v1 = 1.0f / (1.0f + __expf(-v1));
                } else if (act == 2) {
                    v0 = fmaxf(0.0f, Gz[ix] + v0 * Gf[ix]);
                    v1 = fmaxf(0.0f, Gz[ix + 1] + v1 * Gf[ix + 1]);
                }
                if (wr_f32) { Cb[ix] = v0; Cb[ix + 1] = v1; }
                if (Chb) {
                    bf16 hh, ll;
                    split_hl(v0, hh, ll); Chb[ix] = hh; Clb[ix] = ll;
                    split_hl(v1, hh, ll); Chb[ix + 1] = hh; Clb[ix + 1] = ll;
                }
            }
        }
    }
}

// ===========================================================================
// Fused flash MHSA (unchanged — verified)
// ===========================================================================
#define QPITCH 72
#define VPITCH 136
#define FL_SMEM ((4 * 128 * QPITCH + 2 * 64 * VPITCH) * 2)

__global__ void __launch_bounds__(256)
flash_mhsa(const bf16* __restrict__ Qhp, const bf16* __restrict__ Qlp,
           const bf16* __restrict__ Khp, const bf16* __restrict__ Klp,
           const bf16* __restrict__ VThp, const bf16* __restrict__ VTlp,
           bf16* __restrict__ Ohi, bf16* __restrict__ Olo)
{
    extern __shared__ char sm[];
    bf16* sQh = (bf16*)sm;
    bf16* sQl = sQh + 128 * QPITCH;
    bf16* sKh = sQl + 128 * QPITCH;
    bf16* sKl = sKh + 128 * QPITCH;
    bf16* sVh = sKl + 128 * QPITCH;
    bf16* sVl = sVh + 64 * VPITCH;

    const int bh = blockIdx.x;
    const int mb = blockIdx.y;
    const int tid = threadIdx.x, lane = tid & 31, wid = tid >> 5;

    const size_t qoff = (size_t)bh * 768 * 64 + (size_t)mb * 128 * 64;
    const size_t koff = (size_t)bh * 768 * 64;
    const size_t voff = (size_t)bh * 64 * 768;

    for (int i = tid; i < 1024; i += 256) {
        int r = i >> 3, c = (i & 7) * 8;
        *(uint4*)&sQh[r * QPITCH + c] = *(const uint4*)(Qhp + qoff + (size_t)r * 64 + c);
        *(uint4*)&sQl[r * QPITCH + c] = *(const uint4*)(Qlp + qoff + (size_t)r * 64 + c);
    }

    const uint32_t uQ = smem_u32(sQh);
    const uint32_t uK = smem_u32(sKh);
    const uint32_t uV = smem_u32(sVh);
    const uint32_t QHALF = 128 * QPITCH * 2;
    const uint32_t VHALF = 64 * VPITCH * 2;

    float m_r[2] = {-1e30f, -1e30f};
    float l_r[2] = {0.0f, 0.0f};
    float oacc[8][4];
    #pragma unroll
    for (int j = 0; j < 8; ++j)
        #pragma unroll
        for (int q = 0; q < 4; ++q) oacc[j][q] = 0.0f;

    for (int it = 0; it < 6; ++it) {
        for (int i = tid; i < 1024; i += 256) {
            int r = i >> 3, c = (i & 7) * 8;
            *(uint4*)&sKh[r * QPITCH + c] =
                *(const uint4*)(Khp + koff + (size_t)(it * 128 + r) * 64 + c);
            *(uint4*)&sKl[r * QPITCH + c] =
                *(const uint4*)(Klp + koff + (size_t)(it * 128 + r) * 64 + c);
        }
        for (int i = tid; i < 1024; i += 256) {
            int r = i >> 4, c = (i & 15) * 8;
            *(uint4*)&sVh[r * VPITCH + c] =
                *(const uint4*)(VThp + voff + (size_t)r * 768 + it * 128 + c);
            *(uint4*)&sVl[r * VPITCH + c] =
                *(const uint4*)(VTlp + voff + (size_t)r * 768 + it * 128 + c);
        }
        __syncthreads();

        float sacc[16][4];
        #pragma unroll
        for (int g = 0; g < 16; ++g)
            #pragma unroll
            for (int q = 0; q < 4; ++q) sacc[g][q] = 0.0f;

        #pragma unroll
        for (int kk = 0; kk < 4; ++kk) {
            uint32_t ah[4], al[4];
            uint32_t addr = uQ + ((wid * 16 + (lane & 15)) * QPITCH
                                  + kk * 16 + (lane >> 4) * 8) * 2;
            ldsm4(ah, addr);
            ldsm4(al, addr + QHALF);
            #pragma unroll
            for (int g = 0; g < 8; ++g) {
                uint32_t bh4[4], bl4[4];
                int q = lane >> 3;
                int row = g * 16 + ((q >> 1) << 3) + (lane & 7);
                int kc  = kk * 16 + (q & 1) * 8;
                uint32_t ba = uK + (row * QPITCH + kc) * 2;
                ldsm4(bh4, ba);
                ldsm4(bl4, ba + QHALF);
                mma16816(sacc[g * 2 + 0], ah, bh4 + 0);
                mma16816(sacc[g * 2 + 0], ah, bl4 + 0);
                mma16816(sacc[g * 2 + 0], al, bh4 + 0);
                mma16816(sacc[g * 2 + 1], ah, bh4 + 2);
                mma16816(sacc[g * 2 + 1], ah, bl4 + 2);
                mma16816(sacc[g * 2 + 1], al, bh4 + 2);
            }
        }

        float mx0 = -1e30f, mx1 = -1e30f;
        #pragma unroll
        for (int g = 0; g < 16; ++g) {
            sacc[g][0] *= 0.125f; sacc[g][1] *= 0.125f;
            sacc[g][2] *= 0.125f; sacc[g][3] *= 0.125f;
            mx0 = fmaxf(mx0, fmaxf(sacc[g][0], sacc[g][1]));
            mx1 = fmaxf(mx1, fmaxf(sacc[g][2], sacc[g][3]));
        }
        #pragma unroll
        for (int d = 1; d <= 2; d <<= 1) {
            mx0 = fmaxf(mx0, __shfl_xor_sync(0xffffffffu, mx0, d));
            mx1 = fmaxf(mx1, __shfl_xor_sync(0xffffffffu, mx1, d));
        }
        float mn0 = fmaxf(m_r[0], mx0), mn1 = fmaxf(m_r[1], mx1);
        float al0 = __expf(m_r[0] - mn0), al1 = __expf(m_r[1] - mn1);
        float sum0 = 0.0f, sum1 = 0.0f;
        #pragma unroll
        for (int g = 0; g < 16; ++g) {
            sacc[g][0] = __expf(sacc[g][0] - mn0);
            sacc[g][1] = __expf(sacc[g][1] - mn0);
            sacc[g][2] = __expf(sacc[g][2] - mn1);
            sacc[g][3] = __expf(sacc[g][3] - mn1);
            sum0 += sacc[g][0] + sacc[g][1];
            sum1 += sacc[g][2] + sacc[g][3];
        }
        #pragma unroll
        for (int d = 1; d <= 2; d <<= 1) {
            sum0 += __shfl_xor_sync(0xffffffffu, sum0, d);
            sum1 += __shfl_xor_sync(0xffffffffu, sum1, d);
        }
        l_r[0] = l_r[0] * al0 + sum0;
        l_r[1] = l_r[1] * al1 + sum1;
        m_r[0] = mn0; m_r[1] = mn1;
        #pragma unroll
        for (int j = 0; j < 8; ++j) {
            oacc[j][0] *= al0; oacc[j][1] *= al0;
            oacc[j][2] *= al1; oacc[j][3] *= al1;
        }

        #pragma unroll
        for (int s = 0; s < 8; ++s) {
            uint32_t pah[4], pal[4];
            {
                bf16 h0, l0, h1, l1;
                split_hl(sacc[2*s][0], h0, l0); split_hl(sacc[2*s][1], h1, l1);
                pah[0] = packb(h0, h1); pal[0] = packb(l0, l1);
                split_hl(sacc[2*s][2], h0, l0); split_hl(sacc[2*s][3], h1, l1);
                pah[1] = packb(h0, h1); pal[1] = packb(l0, l1);
                split_hl(sacc[2*s+1][0], h0, l0); split_hl(sacc[2*s+1][1], h1, l1);
                pah[2] = packb(h0, h1); pal[2] = packb(l0, l1);
                split_hl(sacc[2*s+1][2], h0, l0); split_hl(sacc[2*s+1][3], h1, l1);
                pah[3] = packb(h0, h1); pal[3] = packb(l0, l1);
            }
            #pragma unroll
            for (int g = 0; g < 4; ++g) {
                uint32_t bh4[4], bl4[4];
                int q = lane >> 3;
                int row = g * 16 + ((q >> 1) << 3) + (lane & 7);
                int kc  = s * 16 + (q & 1) * 8;
                uint32_t ba = uV + (row * VPITCH + kc) * 2;
                ldsm4(bh4, ba);
                ldsm4(bl4, ba + VHALF);
                mma16816(oacc[g * 2 + 0], pah, bh4 + 0);
                mma16816(oacc[g * 2 + 0], pah, bl4 + 0);
                mma16816(oacc[g * 2 + 0], pal, bh4 + 0);
                mma16816(oacc[g * 2 + 1], pah, bh4 + 2);
                mma16816(oacc[g * 2 + 1], pah, bl4 + 2);
                mma16816(oacc[g * 2 + 1], pal, bh4 + 2);
            }
        }
        __syncthreads();
    }

    const float inv0 = 1.0f / l_r[0], inv1 = 1.0f / l_r[1];
    const int b = bh >> 3, h = bh & 7;
    const int n0g = mb * 128 + wid * 16 + (lane >> 2);
    #pragma unroll
    for (int j = 0; j < 8; ++j) {
        const int d = j * 8 + (lane & 3) * 2;
        {
            size_t ix = ((size_t)(b * 768 + n0g) * 512) + h * 64 + d;
            bf16 h0, l0, h1, l1;
            split_hl(oacc[j][0] * inv0, h0, l0);
            split_hl(oacc[j][1] * inv0, h1, l1);
            *(uint32_t*)(Ohi + ix) = packb(h0, h1);
            *(uint32_t*)(Olo + ix) = packb(l0, l1);
        }
        {
            size_t ix = ((size_t)(b * 768 + n0g + 8) * 512) + h * 64 + d;
            bf16 h0, l0, h1, l1;
            split_hl(oacc[j][2] * inv1, h0, l0);
            split_hl(oacc[j][3] * inv1, h1, l1);
            *(uint32_t*)(Ohi + ix) = packb(h0, h1);
            *(uint32_t*)(Olo + ix) = packb(l0, l1);
        }
    }
}

// ===========================================================================
// Conversion / transform kernels
// ===========================================================================
__global__ void conv_hilo(const float* __restrict__ src, int lds,
                          bf16* __restrict__ hi, bf16* __restrict__ lo, int ldd,
                          int R, int C)
{
    long long i = (long long)blockIdx.x * blockDim.x + threadIdx.x;
    int c4 = C / 4;
    if (i >= (long long)R * c4) return;
    int r = (int)(i / c4), c = (int)(i % c4) * 4;
    float4 v = *(const float4*)(src + (size_t)r * lds + c);
    bf16 h0, h1, h2, h3, l0, l1, l2, l3;
    split_hl(v.x, h0, l0); split_hl(v.y, h1, l1);
    split_hl(v.z, h2, l2); split_hl(v.w, h3, l3);
    size_t o = (size_t)r * ldd + c;
    hi[o] = h0; hi[o+1] = h1; hi[o+2] = h2; hi[o+3] = h3;
    lo[o] = l0; lo[o+1] = l1; lo[o+2] = l2; lo[o+3] = l3;
}

__global__ void tconv_hilo(const float* __restrict__ src, int lds, long long sS,
                           bf16* __restrict__ hi, bf16* __restrict__ lo, int ldd, long long sD,
                           int R, int C)
{
    __shared__ float t[32][33];
    const float* s = src + blockIdx.z * sS;
    int r0 = blockIdx.y * 32, c0 = blockIdx.x * 32;
    int tx = threadIdx.x, ty = threadIdx.y;
    #pragma unroll
    for (int i = 0; i < 32; i += 8) {
        int r = r0 + ty + i, c = c0 + tx;
        if (r < R && c < C) t[ty + i][tx] = s[(size_t)r * lds + c];
    }
    __syncthreads();
    bf16* hb = hi + blockIdx.z * sD;
    bf16* lb = lo + blockIdx.z * sD;
    #pragma unroll
    for (int i = 0; i < 32; i += 8) {
        int c = c0 + ty + i, r = r0 + tx;
        if (r < R && c < C) {
            bf16 h, l; split_hl(t[tx][ty + i], h, l);
            hb[(size_t)c * ldd + r] = h;
            lb[(size_t)c * ldd + r] = l;
        }
    }
}

__global__ void tconv_bf(const bf16* __restrict__ sh, const bf16* __restrict__ sl,
                         int lds, long long sS,
                         bf16* __restrict__ dh, bf16* __restrict__ dl,
                         int ldd, long long sD, int R, int C)
{
    __shared__ uint32_t t[32][33];
    const bf16* ph = sh + blockIdx.z * sS;
    const bf16* pl = sl + blockIdx.z * sS;
    int r0 = blockIdx.y * 32, c0 = blockIdx.x * 32;
    int tx = threadIdx.x, ty = threadIdx.y;
    #pragma unroll
    for (int i = 0; i < 32; i += 8) {
        int r = r0 + ty + i, c = c0 + tx;
        t[ty + i][tx] = packb(ph[(size_t)r * lds + c], pl[(size_t)r * lds + c]);
    }
    __syncthreads();
    bf16* hb = dh + blockIdx.z * sD;
    bf16* lb = dl + blockIdx.z * sD;
    #pragma unroll
    for (int i = 0; i < 32; i += 8) {
        int c = c0 + ty + i, r = r0 + tx;
        uint32_t u = t[tx][ty + i];
        __nv_bfloat162 p = *(__nv_bfloat162*)&u;
        hb[(size_t)c * ldd + r] = p.x;
        lb[(size_t)c * ldd + r] = p.y;
    }
}

__global__ void __launch_bounds__(256)
softmax_hilo(const float* __restrict__ src, bf16* __restrict__ hi, bf16* __restrict__ lo, int L)
{
    __shared__ float red[256];
    const float* p = src + (size_t)blockIdx.x * L;
    bf16* ph = hi + (size_t)blockIdx.x * L;
    bf16* pl = lo + (size_t)blockIdx.x * L;
    const int t = threadIdx.x;

    float mx = -1e30f;
    for (int i = t; i < L; i += 256) mx = fmaxf(mx, p[i]);
    red[t] = mx; __syncthreads();
    for (int s = 128; s > 0; s >>= 1) { if (t < s) red[t] = fmaxf(red[t], red[t + s]); __syncthreads(); }
    mx = red[0]; __syncthreads();

    float sum = 0.0f;
    for (int i = t; i < L; i += 256) sum += __expf(p[i] - mx);
    red[t] = sum; __syncthreads();
    for (int s = 128; s > 0; s >>= 1) { if (t < s) red[t] += red[t + s]; __syncthreads(); }
    const float inv = 1.0f / red[0];
    for (int i = t; i < L; i += 256) {
        float v = __expf(p[i] - mx) * inv;
        bf16 h, l; split_hl(v, h, l);
        ph[i] = h; pl[i] = l;
    }
}

// ===========================================================================
// Host side
// ===========================================================================
static void tcg(int M, int N, int K,
                const bf16* Ah, const bf16* Al, int lda, long long sA,
                const bf16* Bh, const bf16* Bl, int ldb, long long sB,
                float* C, int ldc, long long sC, int batch,
                float alpha, const float* bias, int beta, int act,
                bf16* Chi, bf16* Clo, int wr_f32,
                const float* Gz = nullptr, const float* Gf = nullptr, int qkv = 0)
{
    dim3 grid((N + 127) / 128, M / 128, batch);
    mma_gemm<<<grid, 256, GEMM_SMEM>>>(M, N, K, Ah, Al, lda, sA, Bh, Bl, ldb, sB,
                                       C, ldc, sC, alpha, bias, beta, act, Chi, Clo,
                                       wr_f32, Gz, Gf, qkv);
}

extern "C" void kernel_launch(void* const* d_in, const int* in_sizes, int n_in,
                              void* d_out, int out_size)
{
    (void)in_sizes; (void)n_in; (void)out_size;

    cudaFuncSetAttribute(flash_mhsa, cudaFuncAttributeMaxDynamicSharedMemorySize, FL_SMEM);
    cudaFuncSetAttribute(mma_gemm, cudaFuncAttributeMaxDynamicSharedMemorySize, GEMM_SMEM);

    float* F = nullptr; bf16* Bf = nullptr;
    cudaGetSymbolAddress((void**)&F, g_f32);
    cudaGetSymbolAddress((void**)&Bf, g_bf);

    const float* x1     = (const float*)d_in[0];
    const float* x2     = (const float*)d_in[1];
    const float* zb     = (const float*)d_in[2];
    const float* Wqkv_i = (const float*)d_in[3];
    const float* Wqkv_j = (const float*)d_in[4];
    const float* Wqkv_b = (const float*)d_in[5];
    const float* W_f    = (const float*)d_in[6];
    const float* b_f    = (const float*)d_in[7];
    const float* W_m    = (const float*)d_in[8];
    const float* b_m    = (const float*)d_in[9];
    const float* W_QKV  = (const float*)d_in[10];
    const float* W_proj = (const float*)d_in[11];
    const float* b_proj = (const float*)d_in[12];
    float* out = (float*)d_out;

    const float scale = 0.044194173824159216f;   // 512^-0.5
    const int   BN    = BB * NN_;                // 12288

    #define HI(X) (Bf + (X))
    #define LO(X, SZ) (Bf + (X) + (SZ))

    bf16* QKVH = Bf + B_QKVH;
    bf16* VT   = Bf + B_VT;

    // ---- input conversions ----
    {
        long long n = 12288LL * 512 / 4;
        conv_hilo<<<(unsigned)((n + 255) / 256), 256>>>(x1, 512, HI(B_X1), LO(B_X1, SZ_X1), 512, 12288, 512);
        conv_hilo<<<(unsigned)((n + 255) / 256), 256>>>(x2, 512, HI(B_X2), LO(B_X2, SZ_X2), 512, 12288, 512);
        long long nz = 256LL * 512 / 4;
        conv_hilo<<<(unsigned)((nz + 255) / 256), 256>>>(zb, 512, HI(B_ZB), LO(B_ZB, SZ_ZB), 512, 256, 512);
    }
    // ---- weight transposes ----
    dim3 tb(32, 8);
    tconv_hilo<<<dim3(1536/32, 512/32, 1), tb>>>(Wqkv_b, 1536, 0, HI(B_WB), LO(B_WB, SZ_WB), 512, 0, 512, 1536);
    tconv_hilo<<<dim3(1024/32, 512/32, 1), tb>>>(Wqkv_i + 512, 1536, 0, HI(B_WI), LO(B_WI, SZ_WI), 512, 0, 512, 1024);
    tconv_hilo<<<dim3(512/32, 512/32, 1), tb>>>(Wqkv_j, 1536, 0, HI(B_WJ), LO(B_WJ, SZ_WJ), 512, 0, 512, 512);
    tconv_hilo<<<dim3(512/32, 512/32, 1), tb>>>(W_f, 512, 0, HI(B_WF1), LO(B_WF1, SZ_WF1), 512, 0, 512, 512);
    tconv_hilo<<<dim3(512/32, 512/32, 1), tb>>>(W_f + 512LL*512, 512, 0, HI(B_WF2), LO(B_WF2, SZ_WF2), 512, 0, 512, 512);
    tconv_hilo<<<dim3(512/32, 512/32, 1), tb>>>(W_m, 512, 0, HI(B_WM), LO(B_WM, SZ_WM), 512, 0, 512, 512);
    tconv_hilo<<<dim3(1536/32, 512/32, 1), tb>>>(W_QKV, 1536, 0, HI(B_WQ), LO(B_WQ, SZ_WQ), 512, 0, 512, 1536);
    tconv_hilo<<<dim3(512/32, 512/32, 1), tb>>>(W_proj, 512, 0, HI(B_WP), LO(B_WP, SZ_WP), 512, 0, 512, 512);

    // ---- G1 ----
    tcg(256, 1536, 512, HI(B_ZB), LO(B_ZB, SZ_ZB), 512, 0, HI(B_WB), LO(B_WB, SZ_WB), 512, 0,
        F, 1536, 0, 1, 0.2f, nullptr, 0, 0, HI(B_QKVB), LO(B_QKVB, SZ_QKVB), 0);
    // ---- G2 ----
    tcg(BN, 1024, 512, HI(B_X1), LO(B_X1, SZ_X1), 512, 0, HI(B_WI), LO(B_WI, SZ_WI), 512, 0,
        F, 1024, 0, 1, 1.0f, nullptr, 0, 0, HI(B_KVI), LO(B_KVI, SZ_KVI), 0);
    // ---- G3 ----
    tcg(BN, 512, 512, HI(B_X2), LO(B_X2, SZ_X2), 512, 0, HI(B_WJ), LO(B_WJ, SZ_WJ), 512, 0,
        F, 512, 0, 1, 1.0f, nullptr, 0, 0, HI(B_QJ), LO(B_QJ, SZ_QJ), 0);
    // ---- transposes of v_b, v_i ----
    tconv_bf<<<dim3(512/32, 256/32, 1), tb>>>(HI(B_QKVB) + 1024, LO(B_QKVB, SZ_QKVB) + 1024, 1536, 0,
        HI(B_VBT), LO(B_VBT, SZ_VBT), 256, 0, 256, 512);
    tconv_bf<<<dim3(512/32, 768/32, BB), tb>>>(HI(B_KVI) + 512, LO(B_KVI, SZ_KVI) + 512, 1024, 768LL*1024,
        HI(B_VIT), LO(B_VIT, SZ_VIT), 768, 512LL*768, 768, 512);

    // ---- G4 + softmax ----
    tcg(256, 768, 512, HI(B_QKVB), LO(B_QKVB, SZ_QKVB), 1536, 0,
        HI(B_KVI), LO(B_KVI, SZ_KVI), 1024, 768LL*1024,
        F + F_S1, 768, 256LL*768, BB, scale, nullptr, 0, 0, nullptr, nullptr, 1);
    softmax_hilo<<<BB*256, 256>>>(F + F_S1, HI(B_S1), LO(B_S1, SZ_S1), 768);

    // ---- G5 ----
    tcg(256, 512, 768, HI(B_S1), LO(B_S1, SZ_S1), 768, 256LL*768,
        HI(B_VIT), LO(B_VIT, SZ_VIT), 768, 512LL*768,
        F, 512, 256LL*512, BB, 1.0f, nullptr, 0, 0, HI(B_AIB1), LO(B_AIB1, SZ_AIB1), 0);
    tconv_bf<<<dim3(512/32, 256/32, BB), tb>>>(HI(B_AIB1), LO(B_AIB1, SZ_AIB1), 512, 256LL*512,
        HI(B_AIB1T), LO(B_AIB1T, SZ_AIB1T), 256, 512LL*256, 256, 512);

    // ---- G6 + softmax ----
    tcg(768, 256, 512, HI(B_QJ), LO(B_QJ, SZ_QJ), 512, 768LL*512,
        HI(B_QKVB) + 512, LO(B_QKVB, SZ_QKVB) + 512, 1536, 0,
        F + F_S2, 256, 768LL*256, BB, scale, nullptr, 0, 0, nullptr, nullptr, 1);
    softmax_hilo<<<BB*768, 256>>>(F + F_S2, HI(B_S2), LO(B_S2, SZ_S2), 256);

    // ---- G7: 0.5*abj -> F_AIJ ----
    tcg(768, 512, 256, HI(B_S2), LO(B_S2, SZ_S2), 256, 768LL*256,
        HI(B_VBT), LO(B_VBT, SZ_VBT), 256, 0,
        F + F_AIJ, 512, 768LL*512, BB, 0.5f, nullptr, 0, 0, nullptr, nullptr, 1);

    // ---- G8 + softmax ----
    tcg(768, 256, 512, HI(B_X1), LO(B_X1, SZ_X1), 512, 768LL*512,
        HI(B_AIB1), LO(B_AIB1, SZ_AIB1), 512, 256LL*512,
        F + F_S3, 256, 768LL*256, BB, scale, nullptr, 0, 0, nullptr, nullptr, 1);
    softmax_hilo<<<BB*768, 256>>>(F + F_S3, HI(B_S3), LO(B_S3, SZ_S3), 256);

    // ---- G9: aij = 0.5*S3@aib1 + F_AIJ -> hi/lo ----
    tcg(768, 512, 256, HI(B_S3), LO(B_S3, SZ_S3), 256, 768LL*256,
        HI(B_AIB1T), LO(B_AIB1T, SZ_AIB1T), 256, 512LL*256,
        F + F_AIJ, 512, 768LL*512, BB, 0.5f, nullptr, 1, 0, HI(B_AIJ), LO(B_AIJ, SZ_AIJ), 0);

    // ---- G10/G11: f ----
    tcg(BN, 512, 512, HI(B_AIJ), LO(B_AIJ, SZ_AIJ), 512, 0, HI(B_WF1), LO(B_WF1, SZ_WF1), 512, 0,
        F + F_FG, 512, 0, 1, 1.0f, b_f, 0, 0, nullptr, nullptr, 1);
    tcg(BN, 512, 512, HI(B_X2), LO(B_X2, SZ_X2), 512, 0, HI(B_WF2), LO(B_WF2, SZ_WF2), 512, 0,
        F + F_FG, 512, 0, 1, 1.0f, nullptr, 1, 1, nullptr, nullptr, 1);

    // ---- G12: h (act=2) ----
    tcg(BN, 512, 512, HI(B_AIJ), LO(B_AIJ, SZ_AIJ), 512, 0, HI(B_WM), LO(B_WM, SZ_WM), 512, 0,
        F + F_FG, 512, 0, 1, 1.0f, b_m, 0, 2, HI(B_HB), LO(B_HB, SZ_HB), 0, x1, F + F_FG);

    // ---- G13: QKV -> head-split planes ----
    tcg(BN, 1536, 512, HI(B_HB), LO(B_HB, SZ_HB), 512, 0, HI(B_WQ), LO(B_WQ, SZ_WQ), 512, 0,
        F, 1536, 0, 1, 1.0f, nullptr, 0, 0, QKVH, nullptr, 0, nullptr, nullptr, 1);

    // ---- V^T per head ----
    tconv_bf<<<dim3(64/32, 768/32, BB*HH), tb>>>(QKVH + 4*PS, QKVH + 5*PS, 64, 768LL*64,
        VT, VT + PS, 768, 64LL*768, 768, 64);

    // ---- fused flash MHSA ----
    flash_mhsa<<<dim3(BB*HH, NN_/128), 256, FL_SMEM>>>(
        QKVH, QKVH + PS, QKVH + 2*PS, QKVH + 3*PS,
        VT, VT + PS, HI(B_HC), LO(B_HC, SZ_HC));

    // ---- G16 ----
    tcg(BN, 512, 512, HI(B_HC), LO(B_HC, SZ_HC), 512, 0, HI(B_WP), LO(B_WP, SZ_WP), 512, 0,
        out, 512, 0, 1, 1.0f, b_proj, 0, 0, nullptr, nullptr, 1);
}

// round 11
// speedup vs baseline: 2.4664x; 1.0186x over previous
#include <cuda_runtime.h>
#include <cuda_bf16.h>
#include <math.h>
#include <stdint.h>

// Problem constants
#define BB   16
#define NN_  768
#define FF   512
#define NBB  256
#define HH   8
#define DD   64

typedef __nv_bfloat16 bf16;

__device__ __forceinline__ uint32_t smem_u32(const void* p) {
    uint32_t a;
    asm("{ .reg .u64 t; cvta.to.shared.u64 t, %1; cvt.u32.u64 %0, t; }" : "=r"(a) : "l"(p));
    return a;
}

__device__ __forceinline__ void ldsm4(uint32_t* r, uint32_t addr) {
    asm volatile("ldmatrix.sync.aligned.m8n8.x4.shared.b16 {%0,%1,%2,%3}, [%4];"
        : "=r"(r[0]), "=r"(r[1]), "=r"(r[2]), "=r"(r[3]) : "r"(addr));
}

__device__ __forceinline__ void mma16816(float* c, const uint32_t* a, const uint32_t* b) {
    asm volatile(
        "mma.sync.aligned.m16n8k16.row.col.f32.bf16.bf16.f32 "
        "{%0,%1,%2,%3}, {%4,%5,%6,%7}, {%8,%9}, {%0,%1,%2,%3};"
        : "+f"(c[0]), "+f"(c[1]), "+f"(c[2]), "+f"(c[3])
        : "r"(a[0]), "r"(a[1]), "r"(a[2]), "r"(a[3]), "r"(b[0]), "r"(b[1]));
}

__device__ __forceinline__ void split_hl(float v, bf16& h, bf16& l) {
    h = __float2bfloat16(v);
    l = __float2bfloat16(v - __bfloat162float(h));
}

__device__ __forceinline__ uint32_t packb(bf16 lo16, bf16 hi16) {
    __nv_bfloat162 t; t.x = lo16; t.y = hi16;
    return *(uint32_t*)&t;
}

// cp.async helpers (16B)
__device__ __forceinline__ void cp16(uint32_t d, const void* s) {
    asm volatile("cp.async.cg.shared.global [%0], [%1], 16;" :: "r"(d), "l"(s));
}
#define CP_COMMIT() asm volatile("cp.async.commit_group;" ::: "memory")
#define CP_WAIT0()  asm volatile("cp.async.wait_group 0;" ::: "memory")
#define CP_WAIT1()  asm volatile("cp.async.wait_group 1;" ::: "memory")

// ===========================================================================
// Scratch buffers
// ===========================================================================
static const long long F_S1   = 0;                          // 16x256x768
static const long long F_S2   = F_S1  + 16LL*256*768;       // 16x768x256
static const long long F_S3   = F_S2  + 16LL*768*256;       // 16x768x256
static const long long F_AIJ  = F_S3  + 16LL*768*256;       // 12288x512
static const long long F_FG   = F_AIJ + 12288LL*512;        // 12288x512
static const long long F_TOT  = F_FG  + 12288LL*512;

__device__ float g_f32[F_TOT];

#define PS 6291456LL   // plane size: 16*8*768*64

static const long long B_X1    = 0;                             static const long long SZ_X1    = 12288LL*512;
static const long long B_X2    = B_X1    + 2*SZ_X1;             static const long long SZ_X2    = 12288LL*512;
static const long long B_ZB    = B_X2    + 2*SZ_X2;             static const long long SZ_ZB    = 256LL*512;
static const long long B_WB    = B_ZB    + 2*SZ_ZB;             static const long long SZ_WB    = 1536LL*512;
static const long long B_WI    = B_WB    + 2*SZ_WB;             static const long long SZ_WI    = 1024LL*512;
static const long long B_WJ    = B_WI    + 2*SZ_WI;             static const long long SZ_WJ    = 512LL*512;
static const long long B_WFC   = B_WJ    + 2*SZ_WJ;             static const long long SZ_WFC   = 512LL*1024;
static const long long B_WM    = B_WFC   + 2*SZ_WFC;            static const long long SZ_WM    = 512LL*512;
static const long long B_WQ    = B_WM    + 2*SZ_WM;             static const long long SZ_WQ    = 1536LL*512;
static const long long B_WP    = B_WQ    + 2*SZ_WQ;             static const long long SZ_WP    = 512LL*512;
static const long long B_QKVB  = B_WP    + 2*SZ_WP;             static const long long SZ_QKVB  = 256LL*1536;
static const long long B_KVI   = B_QKVB  + 2*SZ_QKVB;           static const long long SZ_KVI   = 12288LL*1024;
static const long long B_QJ    = B_KVI   + 2*SZ_KVI;            static const long long SZ_QJ    = 12288LL*512;
static const long long B_S1    = B_QJ    + 2*SZ_QJ;             static const long long SZ_S1    = 16LL*256*768;
static const long long B_VIT   = B_S1    + 2*SZ_S1;             static const long long SZ_VIT   = 16LL*512*768;
static const long long B_AIB1  = B_VIT   + 2*SZ_VIT;            static const long long SZ_AIB1  = 16LL*256*512;
static const long long B_AIB1T = B_AIB1  + 2*SZ_AIB1;           static const long long SZ_AIB1T = 16LL*512*256;
static const long long B_VBT   = B_AIB1T + 2*SZ_AIB1T;          static const long long SZ_VBT   = 512LL*256;
static const long long B_S2    = B_VBT   + 2*SZ_VBT;            static const long long SZ_S2    = 16LL*768*256;
static const long long B_S3    = B_S2    + 2*SZ_S2;             static const long long SZ_S3    = 16LL*768*256;
static const long long B_CAT   = B_S3    + 2*SZ_S3;             static const long long SZ_CAT   = 12288LL*1024; // [aij | x2]
static const long long B_HB    = B_CAT   + 2*SZ_CAT;            static const long long SZ_HB    = 12288LL*512;
static const long long B_QKVH  = B_HB    + 2*SZ_HB;             // 6 planes
static const long long B_VT    = B_QKVH  + 6*PS;                // 2 planes
static const long long B_HC    = B_VT    + 2*PS;                static const long long SZ_HC    = 12288LL*512;
static const long long B_TOT   = B_HC    + 2*SZ_HC;

__device__ bf16 g_bf[B_TOT];

// ===========================================================================
// mma.sync GEMM, cp.async 2-stage pipelined mainloop + fused epilogues
// ===========================================================================
#define KT 32
#define SMP 40
#define HALFB  (128 * SMP * 2)
#define STGB   (4 * HALFB)
#define GEMM_SMEM (2 * STGB)        // 81920 bytes

__global__ void __launch_bounds__(256, 2)
mma_gemm(int M, int N, int K,
         const bf16* __restrict__ Ahi, const bf16* __restrict__ Alo, int lda, long long sA,
         const bf16* __restrict__ Bhi, const bf16* __restrict__ Blo, int ldb, long long sB,
         float* __restrict__ C, int ldc, long long sC,
         float alpha, const float* __restrict__ bias, int beta, int act,
         bf16* __restrict__ Chi, bf16* __restrict__ Clo, int wr_f32,
         const float* __restrict__ Gz, const float* __restrict__ Gf, int qkv,
         int ldco, long long sCo)
{
    extern __shared__ bf16 smbuf[];
    const uint32_t sbase = smem_u32(smbuf);

    const int tid = threadIdx.x, lane = tid & 31, wid = tid >> 5;
    const int bz = blockIdx.z;
    const int m0 = blockIdx.y * 128, n0 = blockIdx.x * 128;
    const int wm = wid & 3, wn = wid >> 2;
    const int m0w = wm * 32, n0w = wn * 64;

    const bf16* Ah = Ahi + bz * sA + (size_t)m0 * lda;
    const bf16* Al = Alo + bz * sA + (size_t)m0 * lda;
    const bf16* Bh = Bhi + bz * sB + (size_t)n0 * ldb;
    const bf16* Bl = Blo + bz * sB + (size_t)n0 * ldb;

    float acc[2][8][4];
    #pragma unroll
    for (int i = 0; i < 2; ++i)
        #pragma unroll
        for (int j = 0; j < 8; ++j)
            #pragma unroll
            for (int q = 0; q < 4; ++q) acc[i][j][q] = 0.0f;

    const int nk = K / KT;

    auto load_stage = [&](int st, int k0) {
        const uint32_t sb0 = sbase + st * STGB;
        #pragma unroll
        for (int it = 0; it < 2; ++it) {
            int cid = tid + it * 256;
            int row = cid >> 2;
            int c   = (cid & 3) * 8;
            uint32_t off = (uint32_t)(row * SMP + c) * 2;
            cp16(sb0 + off,              Ah + (size_t)row * lda + k0 + c);
            cp16(sb0 + HALFB + off,      Al + (size_t)row * lda + k0 + c);
            cp16(sb0 + 2 * HALFB + off,  Bh + (size_t)row * ldb + k0 + c);
            cp16(sb0 + 3 * HALFB + off,  Bl + (size_t)row * ldb + k0 + c);
        }
    };

    load_stage(0, 0);
    CP_COMMIT();

    for (int i = 0; i < nk; ++i) {
        if (i + 1 < nk) { load_stage((i + 1) & 1, (i + 1) * KT); CP_COMMIT(); }
        if (i + 1 < nk) CP_WAIT1(); else CP_WAIT0();
        __syncthreads();

        const uint32_t sa  = sbase + (i & 1) * STGB;
        const uint32_t sbm = sa + 2 * HALFB;

        #pragma unroll
        for (int kk = 0; kk < 2; ++kk) {
            uint32_t ah[2][4], al[2][4];
            #pragma unroll
            for (int mi = 0; mi < 2; ++mi) {
                uint32_t addr = sa + ((m0w + mi * 16 + (lane & 15)) * SMP
                                      + kk * 16 + (lane >> 4) * 8) * 2;
                ldsm4(ah[mi], addr);
                ldsm4(al[mi], addr + HALFB);
            }
            #pragma unroll
            for (int g = 0; g < 4; ++g) {
                uint32_t bh[4], bl[4];
                int q = lane >> 3;
                int row = n0w + g * 16 + ((q >> 1) << 3) + (lane & 7);
                int kc  = kk * 16 + (q & 1) * 8;
                uint32_t addr = sbm + (row * SMP + kc) * 2;
                ldsm4(bh, addr);
                ldsm4(bl, addr + HALFB);
                #pragma unroll
                for (int mi = 0; mi < 2; ++mi) {
                    mma16816(acc[mi][g * 2 + 0], ah[mi], bh + 0);
                    mma16816(acc[mi][g * 2 + 0], ah[mi], bl + 0);
                    mma16816(acc[mi][g * 2 + 0], al[mi], bh + 0);
                    mma16816(acc[mi][g * 2 + 1], ah[mi], bh + 2);
                    mma16816(acc[mi][g * 2 + 1], ah[mi], bl + 2);
                    mma16816(acc[mi][g * 2 + 1], al[mi], bh + 2);
                }
            }
        }
        __syncthreads();
    }

    const int rb = m0 + m0w + (lane >> 2);
    const int cb = n0 + n0w + (lane & 3) * 2;

    if (qkv) {
        #pragma unroll
        for (int mi = 0; mi < 2; ++mi) {
            #pragma unroll
            for (int ni = 0; ni < 8; ++ni) {
                const int col = cb + ni * 8;
                const int t = col >> 9, cw = col & 511;
                const int hh2 = cw >> 6, dd2 = cw & 63;
                bf16* ph = Chi + (long long)t * 2 * PS;
                #pragma unroll
                for (int h2 = 0; h2 < 2; ++h2) {
                    const int row = rb + mi * 16 + h2 * 8;
                    const int b2 = row / 768, n2 = row - b2 * 768;
                    size_t ix = ((size_t)((b2 * 8 + hh2) * 768 + n2)) * 64 + dd2;
                    float v0 = acc[mi][ni][h2 * 2 + 0] * alpha;
                    float v1 = acc[mi][ni][h2 * 2 + 1] * alpha;
                    bf16 h0, l0, h1, l1;
                    split_hl(v0, h0, l0); split_hl(v1, h1, l1);
                    *(uint32_t*)(ph + ix) = packb(h0, h1);
                    *(uint32_t*)(ph + PS + ix) = packb(l0, l1);
                }
            }
        }
        return;
    }

    float* Cb = C + bz * sC;
    bf16* Chb = Chi ? Chi + bz * sCo : nullptr;
    bf16* Clb = Clo ? Clo + bz * sCo : nullptr;

    #pragma unroll
    for (int mi = 0; mi < 2; ++mi) {
        #pragma unroll
        for (int ni = 0; ni < 8; ++ni) {
            const int col = cb + ni * 8;
            if (col >= N) continue;
            float b0 = bias ? bias[col] : 0.0f;
            float b1 = bias ? bias[col + 1] : 0.0f;
            #pragma unroll
            for (int h = 0; h < 2; ++h) {
                const int row = rb + mi * 16 + h * 8;
                size_t ix = (size_t)row * ldc + col;
                float v0 = acc[mi][ni][h * 2 + 0] * alpha + b0;
                float v1 = acc[mi][ni][h * 2 + 1] * alpha + b1;
                if (beta) { v0 += Cb[ix]; v1 += Cb[ix + 1]; }
                if (act == 1) {
                    v0 = 1.0f / (1.0f + __expf(-v0));
                    v1 = 1.0f / (1.0f + __expf(-v1));
                } else if (act == 2) {
                    v0 = fmaxf(0.0f, Gz[ix] + v0 * Gf[ix]);
                    v1 = fmaxf(0.0f, Gz[ix + 1] + v1 * Gf[ix + 1]);
                }
                if (wr_f32) { Cb[ix] = v0; Cb[ix + 1] = v1; }
                if (Chb) {
                    size_t ixo = (size_t)row * ldco + col;
                    bf16 hh, ll;
                    split_hl(v0, hh, ll); Chb[ixo] = hh; Clb[ixo] = ll;
                    split_hl(v1, hh, ll); Chb[ixo + 1] = hh; Clb[ixo + 1] = ll;
                }
            }
        }
    }
}

// ===========================================================================
// Fused flash MHSA (unchanged — verified)
// ===========================================================================
#define QPITCH 72
#define VPITCH 136
#define FL_SMEM ((4 * 128 * QPITCH + 2 * 64 * VPITCH) * 2)

__global__ void __launch_bounds__(256)
flash_mhsa(const bf16* __restrict__ Qhp, const bf16* __restrict__ Qlp,
           const bf16* __restrict__ Khp, const bf16* __restrict__ Klp,
           const bf16* __restrict__ VThp, const bf16* __restrict__ VTlp,
           bf16* __restrict__ Ohi, bf16* __restrict__ Olo)
{
    extern __shared__ char sm[];
    bf16* sQh = (bf16*)sm;
    bf16* sQl = sQh + 128 * QPITCH;
    bf16* sKh = sQl + 128 * QPITCH;
    bf16* sKl = sKh + 128 * QPITCH;
    bf16* sVh = sKl + 128 * QPITCH;
    bf16* sVl = sVh + 64 * VPITCH;

    const int bh = blockIdx.x;
    const int mb = blockIdx.y;
    const int tid = threadIdx.x, lane = tid & 31, wid = tid >> 5;

    const size_t qoff = (size_t)bh * 768 * 64 + (size_t)mb * 128 * 64;
    const size_t koff = (size_t)bh * 768 * 64;
    const size_t voff = (size_t)bh * 64 * 768;

    for (int i = tid; i < 1024; i += 256) {
        int r = i >> 3, c = (i & 7) * 8;
        *(uint4*)&sQh[r * QPITCH + c] = *(const uint4*)(Qhp + qoff + (size_t)r * 64 + c);
        *(uint4*)&sQl[r * QPITCH + c] = *(const uint4*)(Qlp + qoff + (size_t)r * 64 + c);
    }

    const uint32_t uQ = smem_u32(sQh);
    const uint32_t uK = smem_u32(sKh);
    const uint32_t uV = smem_u32(sVh);
    const uint32_t QHALF = 128 * QPITCH * 2;
    const uint32_t VHALF = 64 * VPITCH * 2;

    float m_r[2] = {-1e30f, -1e30f};
    float l_r[2] = {0.0f, 0.0f};
    float oacc[8][4];
    #pragma unroll
    for (int j = 0; j < 8; ++j)
        #pragma unroll
        for (int q = 0; q < 4; ++q) oacc[j][q] = 0.0f;

    for (int it = 0; it < 6; ++it) {
        for (int i = tid; i < 1024; i += 256) {
            int r = i >> 3, c = (i & 7) * 8;
            *(uint4*)&sKh[r * QPITCH + c] =
                *(const uint4*)(Khp + koff + (size_t)(it * 128 + r) * 64 + c);
            *(uint4*)&sKl[r * QPITCH + c] =
                *(const uint4*)(Klp + koff + (size_t)(it * 128 + r) * 64 + c);
        }
        for (int i = tid; i < 1024; i += 256) {
            int r = i >> 4, c = (i & 15) * 8;
            *(uint4*)&sVh[r * VPITCH + c] =
                *(const uint4*)(VThp + voff + (size_t)r * 768 + it * 128 + c);
            *(uint4*)&sVl[r * VPITCH + c] =
                *(const uint4*)(VTlp + voff + (size_t)r * 768 + it * 128 + c);
        }
        __syncthreads();

        float sacc[16][4];
        #pragma unroll
        for (int g = 0; g < 16; ++g)
            #pragma unroll
            for (int q = 0; q < 4; ++q) sacc[g][q] = 0.0f;

        #pragma unroll
        for (int kk = 0; kk < 4; ++kk) {
            uint32_t ah[4], al[4];
            uint32_t addr = uQ + ((wid * 16 + (lane & 15)) * QPITCH
                                  + kk * 16 + (lane >> 4) * 8) * 2;
            ldsm4(ah, addr);
            ldsm4(al, addr + QHALF);
            #pragma unroll
            for (int g = 0; g < 8; ++g) {
                uint32_t bh4[4], bl4[4];
                int q = lane >> 3;
                int row = g * 16 + ((q >> 1) << 3) + (lane & 7);
                int kc  = kk * 16 + (q & 1) * 8;
                uint32_t ba = uK + (row * QPITCH + kc) * 2;
                ldsm4(bh4, ba);
                ldsm4(bl4, ba + QHALF);
                mma16816(sacc[g * 2 + 0], ah, bh4 + 0);
                mma16816(sacc[g * 2 + 0], ah, bl4 + 0);
                mma16816(sacc[g * 2 + 0], al, bh4 + 0);
                mma16816(sacc[g * 2 + 1], ah, bh4 + 2);
                mma16816(sacc[g * 2 + 1], ah, bl4 + 2);
                mma16816(sacc[g * 2 + 1], al, bh4 + 2);
            }
        }

        float mx0 = -1e30f, mx1 = -1e30f;
        #pragma unroll
        for (int g = 0; g < 16; ++g) {
            sacc[g][0] *= 0.125f; sacc[g][1] *= 0.125f;
            sacc[g][2] *= 0.125f; sacc[g][3] *= 0.125f;
            mx0 = fmaxf(mx0, fmaxf(sacc[g][0], sacc[g][1]));
            mx1 = fmaxf(mx1, fmaxf(sacc[g][2], sacc[g][3]));
        }
        #pragma unroll
        for (int d = 1; d <= 2; d <<= 1) {
            mx0 = fmaxf(mx0, __shfl_xor_sync(0xffffffffu, mx0, d));
            mx1 = fmaxf(mx1, __shfl_xor_sync(0xffffffffu, mx1, d));
        }
        float mn0 = fmaxf(m_r[0], mx0), mn1 = fmaxf(m_r[1], mx1);
        float al0 = __expf(m_r[0] - mn0), al1 = __expf(m_r[1] - mn1);
        float sum0 = 0.0f, sum1 = 0.0f;
        #pragma unroll
        for (int g = 0; g < 16; ++g) {
            sacc[g][0] = __expf(sacc[g][0] - mn0);
            sacc[g][1] = __expf(sacc[g][1] - mn0);
            sacc[g][2] = __expf(sacc[g][2] - mn1);
            sacc[g][3] = __expf(sacc[g][3] - mn1);
            sum0 += sacc[g][0] + sacc[g][1];
            sum1 += sacc[g][2] + sacc[g][3];
        }
        #pragma unroll
        for (int d = 1; d <= 2; d <<= 1) {
            sum0 += __shfl_xor_sync(0xffffffffu, sum0, d);
            sum1 += __shfl_xor_sync(0xffffffffu, sum1, d);
        }
        l_r[0] = l_r[0] * al0 + sum0;
        l_r[1] = l_r[1] * al1 + sum1;
        m_r[0] = mn0; m_r[1] = mn1;
        #pragma unroll
        for (int j = 0; j < 8; ++j) {
            oacc[j][0] *= al0; oacc[j][1] *= al0;
            oacc[j][2] *= al1; oacc[j][3] *= al1;
        }

        #pragma unroll
        for (int s = 0; s < 8; ++s) {
            uint32_t pah[4], pal[4];
            {
                bf16 h0, l0, h1, l1;
                split_hl(sacc[2*s][0], h0, l0); split_hl(sacc[2*s][1], h1, l1);
                pah[0] = packb(h0, h1); pal[0] = packb(l0, l1);
                split_hl(sacc[2*s][2], h0, l0); split_hl(sacc[2*s][3], h1, l1);
                pah[1] = packb(h0, h1); pal[1] = packb(l0, l1);
                split_hl(sacc[2*s+1][0], h0, l0); split_hl(sacc[2*s+1][1], h1, l1);
                pah[2] = packb(h0, h1); pal[2] = packb(l0, l1);
                split_hl(sacc[2*s+1][2], h0, l0); split_hl(sacc[2*s+1][3], h1, l1);
                pah[3] = packb(h0, h1); pal[3] = packb(l0, l1);
            }
            #pragma unroll
            for (int g = 0; g < 4; ++g) {
                uint32_t bh4[4], bl4[4];
                int q = lane >> 3;
                int row = g * 16 + ((q >> 1) << 3) + (lane & 7);
                int kc  = s * 16 + (q & 1) * 8;
                uint32_t ba = uV + (row * VPITCH + kc) * 2;
                ldsm4(bh4, ba);
                ldsm4(bl4, ba + VHALF);
                mma16816(oacc[g * 2 + 0], pah, bh4 + 0);
                mma16816(oacc[g * 2 + 0], pah, bl4 + 0);
                mma16816(oacc[g * 2 + 0], pal, bh4 + 0);
                mma16816(oacc[g * 2 + 1], pah, bh4 + 2);
                mma16816(oacc[g * 2 + 1], pah, bl4 + 2);
                mma16816(oacc[g * 2 + 1], pal, bh4 + 2);
            }
        }
        __syncthreads();
    }

    const float inv0 = 1.0f / l_r[0], inv1 = 1.0f / l_r[1];
    const int b = bh >> 3, h = bh & 7;
    const int n0g = mb * 128 + wid * 16 + (lane >> 2);
    #pragma unroll
    for (int j = 0; j < 8; ++j) {
        const int d = j * 8 + (lane & 3) * 2;
        {
            size_t ix = ((size_t)(b * 768 + n0g) * 512) + h * 64 + d;
            bf16 h0, l0, h1, l1;
            split_hl(oacc[j][0] * inv0, h0, l0);
            split_hl(oacc[j][1] * inv0, h1, l1);
            *(uint32_t*)(Ohi + ix) = packb(h0, h1);
            *(uint32_t*)(Olo + ix) = packb(l0, l1);
        }
        {
            size_t ix = ((size_t)(b * 768 + n0g + 8) * 512) + h * 64 + d;
            bf16 h0, l0, h1, l1;
            split_hl(oacc[j][2] * inv1, h0, l0);
            split_hl(oacc[j][3] * inv1, h1, l1);
            *(uint32_t*)(Ohi + ix) = packb(h0, h1);
            *(uint32_t*)(Olo + ix) = packb(l0, l1);
        }
    }
}

// ===========================================================================
// Conversion / transform kernels
// ===========================================================================
__global__ void conv_hilo(const float* __restrict__ src, int lds,
                          bf16* __restrict__ hi, bf16* __restrict__ lo, int ldd,
                          int R, int C)
{
    long long i = (long long)blockIdx.x * blockDim.x + threadIdx.x;
    int c4 = C / 4;
    if (i >= (long long)R * c4) return;
    int r = (int)(i / c4), c = (int)(i % c4) * 4;
    float4 v = *(const float4*)(src + (size_t)r * lds + c);
    bf16 h0, h1, h2, h3, l0, l1, l2, l3;
    split_hl(v.x, h0, l0); split_hl(v.y, h1, l1);
    split_hl(v.z, h2, l2); split_hl(v.w, h3, l3);
    size_t o = (size_t)r * ldd + c;
    hi[o] = h0; hi[o+1] = h1; hi[o+2] = h2; hi[o+3] = h3;
    lo[o] = l0; lo[o+1] = l1; lo[o+2] = l2; lo[o+3] = l3;
}

__global__ void tconv_hilo(const float* __restrict__ src, int lds, long long sS,
                           bf16* __restrict__ hi, bf16* __restrict__ lo, int ldd, long long sD,
                           int R, int C)
{
    __shared__ float t[32][33];
    const float* s = src + blockIdx.z * sS;
    int r0 = blockIdx.y * 32, c0 = blockIdx.x * 32;
    int tx = threadIdx.x, ty = threadIdx.y;
    #pragma unroll
    for (int i = 0; i < 32; i += 8) {
        int r = r0 + ty + i, c = c0 + tx;
        if (r < R && c < C) t[ty + i][tx] = s[(size_t)r * lds + c];
    }
    __syncthreads();
    bf16* hb = hi + blockIdx.z * sD;
    bf16* lb = lo + blockIdx.z * sD;
    #pragma unroll
    for (int i = 0; i < 32; i += 8) {
        int c = c0 + ty + i, r = r0 + tx;
        if (r < R && c < C) {
            bf16 h, l; split_hl(t[tx][ty + i], h, l);
            hb[(size_t)c * ldd + r] = h;
            lb[(size_t)c * ldd + r] = l;
        }
    }
}

__global__ void tconv_bf(const bf16* __restrict__ sh, const bf16* __restrict__ sl,
                         int lds, long long sS,
                         bf16* __restrict__ dh, bf16* __restrict__ dl,
                         int ldd, long long sD, int R, int C)
{
    __shared__ uint32_t t[32][33];
    const bf16* ph = sh + blockIdx.z * sS;
    const bf16* pl = sl + blockIdx.z * sS;
    int r0 = blockIdx.y * 32, c0 = blockIdx.x * 32;
    int tx = threadIdx.x, ty = threadIdx.y;
    #pragma unroll
    for (int i = 0; i < 32; i += 8) {
        int r = r0 + ty + i, c = c0 + tx;
        t[ty + i][tx] = packb(ph[(size_t)r * lds + c], pl[(size_t)r * lds + c]);
    }
    __syncthreads();
    bf16* hb = dh + blockIdx.z * sD;
    bf16* lb = dl + blockIdx.z * sD;
    #pragma unroll
    for (int i = 0; i < 32; i += 8) {
        int c = c0 + ty + i, r = r0 + tx;
        uint32_t u = t[tx][ty + i];
        __nv_bfloat162 p = *(__nv_bfloat162*)&u;
        hb[(size_t)c * ldd + r] = p.x;
        lb[(size_t)c * ldd + r] = p.y;
    }
}

__global__ void __launch_bounds__(256)
softmax_hilo(const float* __restrict__ src, bf16* __restrict__ hi, bf16* __restrict__ lo, int L)
{
    __shared__ float red[256];
    const float* p = src + (size_t)blockIdx.x * L;
    bf16* ph = hi + (size_t)blockIdx.x * L;
    bf16* pl = lo + (size_t)blockIdx.x * L;
    const int t = threadIdx.x;

    float mx = -1e30f;
    for (int i = t; i < L; i += 256) mx = fmaxf(mx, p[i]);
    red[t] = mx; __syncthreads();
    for (int s = 128; s > 0; s >>= 1) { if (t < s) red[t] = fmaxf(red[t], red[t + s]); __syncthreads(); }
    mx = red[0]; __syncthreads();

    float sum = 0.0f;
    for (int i = t; i < L; i += 256) sum += __expf(p[i] - mx);
    red[t] = sum; __syncthreads();
    for (int s = 128; s > 0; s >>= 1) { if (t < s) red[t] += red[t + s]; __syncthreads(); }
    const float inv = 1.0f / red[0];
    for (int i = t; i < L; i += 256) {
        float v = __expf(p[i] - mx) * inv;
        bf16 h, l; split_hl(v, h, l);
        ph[i] = h; pl[i] = l;
    }
}

// ===========================================================================
// Host side
// ===========================================================================
static void tcg(int M, int N, int K,
                const bf16* Ah, const bf16* Al, int lda, long long sA,
                const bf16* Bh, const bf16* Bl, int ldb, long long sB,
                float* C, int ldc, long long sC, int batch,
                float alpha, const float* bias, int beta, int act,
                bf16* Chi, bf16* Clo, int wr_f32,
                const float* Gz = nullptr, const float* Gf = nullptr, int qkv = 0,
                int ldco = -1, long long sCo = -1)
{
    if (ldco < 0) ldco = ldc;
    if (sCo < 0) sCo = sC;
    dim3 grid((N + 127) / 128, M / 128, batch);
    mma_gemm<<<grid, 256, GEMM_SMEM>>>(M, N, K, Ah, Al, lda, sA, Bh, Bl, ldb, sB,
                                       C, ldc, sC, alpha, bias, beta, act, Chi, Clo,
                                       wr_f32, Gz, Gf, qkv, ldco, sCo);
}

extern "C" void kernel_launch(void* const* d_in, const int* in_sizes, int n_in,
                              void* d_out, int out_size)
{
    (void)in_sizes; (void)n_in; (void)out_size;

    cudaFuncSetAttribute(flash_mhsa, cudaFuncAttributeMaxDynamicSharedMemorySize, FL_SMEM);
    cudaFuncSetAttribute(mma_gemm, cudaFuncAttributeMaxDynamicSharedMemorySize, GEMM_SMEM);

    float* F = nullptr; bf16* Bf = nullptr;
    cudaGetSymbolAddress((void**)&F, g_f32);
    cudaGetSymbolAddress((void**)&Bf, g_bf);

    const float* x1     = (const float*)d_in[0];
    const float* x2     = (const float*)d_in[1];
    const float* zb     = (const float*)d_in[2];
    const float* Wqkv_i = (const float*)d_in[3];
    const float* Wqkv_j = (const float*)d_in[4];
    const float* Wqkv_b = (const float*)d_in[5];
    const float* W_f    = (const float*)d_in[6];
    const float* b_f    = (const float*)d_in[7];
    const float* W_m    = (const float*)d_in[8];
    const float* b_m    = (const float*)d_in[9];
    const float* W_QKV  = (const float*)d_in[10];
    const float* W_proj = (const float*)d_in[11];
    const float* b_proj = (const float*)d_in[12];
    float* out = (float*)d_out;

    const float scale = 0.044194173824159216f;   // 512^-0.5
    const int   BN    = BB * NN_;                // 12288

    #define HI(X) (Bf + (X))
    #define LO(X, SZ) (Bf + (X) + (SZ))

    bf16* QKVH = Bf + B_QKVH;
    bf16* VT   = Bf + B_VT;

    // ---- input conversions ----
    {
        long long n = 12288LL * 512 / 4;
        conv_hilo<<<(unsigned)((n + 255) / 256), 256>>>(x1, 512, HI(B_X1), LO(B_X1, SZ_X1), 512, 12288, 512);
        conv_hilo<<<(unsigned)((n + 255) / 256), 256>>>(x2, 512, HI(B_X2), LO(B_X2, SZ_X2), 512, 12288, 512);
        // x2 copy into concat buffer columns 512..1023
        conv_hilo<<<(unsigned)((n + 255) / 256), 256>>>(x2, 512, HI(B_CAT) + 512, LO(B_CAT, SZ_CAT) + 512, 1024, 12288, 512);
        long long nz = 256LL * 512 / 4;
        conv_hilo<<<(unsigned)((nz + 255) / 256), 256>>>(zb, 512, HI(B_ZB), LO(B_ZB, SZ_ZB), 512, 256, 512);
    }
    // ---- weight transposes ----
    dim3 tb(32, 8);
    tconv_hilo<<<dim3(1536/32, 512/32, 1), tb>>>(Wqkv_b, 1536, 0, HI(B_WB), LO(B_WB, SZ_WB), 512, 0, 512, 1536);
    tconv_hilo<<<dim3(1024/32, 512/32, 1), tb>>>(Wqkv_i + 512, 1536, 0, HI(B_WI), LO(B_WI, SZ_WI), 512, 0, 512, 1024);
    tconv_hilo<<<dim3(512/32, 512/32, 1), tb>>>(Wqkv_j, 1536, 0, HI(B_WJ), LO(B_WJ, SZ_WJ), 512, 0, 512, 512);
    // W_f halves -> concatenated K-major [512, 1024]
    tconv_hilo<<<dim3(512/32, 512/32, 1), tb>>>(W_f, 512, 0, HI(B_WFC), LO(B_WFC, SZ_WFC), 1024, 0, 512, 512);
    tconv_hilo<<<dim3(512/32, 512/32, 1), tb>>>(W_f + 512LL*512, 512, 0, HI(B_WFC) + 512, LO(B_WFC, SZ_WFC) + 512, 1024, 0, 512, 512);
    tconv_hilo<<<dim3(512/32, 512/32, 1), tb>>>(W_m, 512, 0, HI(B_WM), LO(B_WM, SZ_WM), 512, 0, 512, 512);
    tconv_hilo<<<dim3(1536/32, 512/32, 1), tb>>>(W_QKV, 1536, 0, HI(B_WQ), LO(B_WQ, SZ_WQ), 512, 0, 512, 1536);
    tconv_hilo<<<dim3(512/32, 512/32, 1), tb>>>(W_proj, 512, 0, HI(B_WP), LO(B_WP, SZ_WP), 512, 0, 512, 512);

    // ---- G1 ----
    tcg(256, 1536, 512, HI(B_ZB), LO(B_ZB, SZ_ZB), 512, 0, HI(B_WB), LO(B_WB, SZ_WB), 512, 0,
        F, 1536, 0, 1, 0.2f, nullptr, 0, 0, HI(B_QKVB), LO(B_QKVB, SZ_QKVB), 0);
    // ---- G2 ----
    tcg(BN, 1024, 512, HI(B_X1), LO(B_X1, SZ_X1), 512, 0, HI(B_WI), LO(B_WI, SZ_WI), 512, 0,
        F, 1024, 0, 1, 1.0f, nullptr, 0, 0, HI(B_KVI), LO(B_KVI, SZ_KVI), 0);
    // ---- G3 ----
    tcg(BN, 512, 512, HI(B_X2), LO(B_X2, SZ_X2), 512, 0, HI(B_WJ), LO(B_WJ, SZ_WJ), 512, 0,
        F, 512, 0, 1, 1.0f, nullptr, 0, 0, HI(B_QJ), LO(B_QJ, SZ_QJ), 0);
    // ---- transposes of v_b, v_i ----
    tconv_bf<<<dim3(512/32, 256/32, 1), tb>>>(HI(B_QKVB) + 1024, LO(B_QKVB, SZ_QKVB) + 1024, 1536, 0,
        HI(B_VBT), LO(B_VBT, SZ_VBT), 256, 0, 256, 512);
    tconv_bf<<<dim3(512/32, 768/32, BB), tb>>>(HI(B_KVI) + 512, LO(B_KVI, SZ_KVI) + 512, 1024, 768LL*1024,
        HI(B_VIT), LO(B_VIT, SZ_VIT), 768, 512LL*768, 768, 512);

    // ---- G4 + softmax ----
    tcg(256, 768, 512, HI(B_QKVB), LO(B_QKVB, SZ_QKVB), 1536, 0,
        HI(B_KVI), LO(B_KVI, SZ_KVI), 1024, 768LL*1024,
        F + F_S1, 768, 256LL*768, BB, scale, nullptr, 0, 0, nullptr, nullptr, 1);
    softmax_hilo<<<BB*256, 256>>>(F + F_S1, HI(B_S1), LO(B_S1, SZ_S1), 768);

    // ---- G5 ----
    tcg(256, 512, 768, HI(B_S1), LO(B_S1, SZ_S1), 768, 256LL*768,
        HI(B_VIT), LO(B_VIT, SZ_VIT), 768, 512LL*768,
        F, 512, 256LL*512, BB, 1.0f, nullptr, 0, 0, HI(B_AIB1), LO(B_AIB1, SZ_AIB1), 0);
    tconv_bf<<<dim3(512/32, 256/32, BB), tb>>>(HI(B_AIB1), LO(B_AIB1, SZ_AIB1), 512, 256LL*512,
        HI(B_AIB1T), LO(B_AIB1T, SZ_AIB1T), 256, 512LL*256, 256, 512);

    // ---- G6 + softmax ----
    tcg(768, 256, 512, HI(B_QJ), LO(B_QJ, SZ_QJ), 512, 768LL*512,
        HI(B_QKVB) + 512, LO(B_QKVB, SZ_QKVB) + 512, 1536, 0,
        F + F_S2, 256, 768LL*256, BB, scale, nullptr, 0, 0, nullptr, nullptr, 1);
    softmax_hilo<<<BB*768, 256>>>(F + F_S2, HI(B_S2), LO(B_S2, SZ_S2), 256);

    // ---- G7: 0.5*abj -> F_AIJ ----
    tcg(768, 512, 256, HI(B_S2), LO(B_S2, SZ_S2), 256, 768LL*256,
        HI(B_VBT), LO(B_VBT, SZ_VBT), 256, 0,
        F + F_AIJ, 512, 768LL*512, BB, 0.5f, nullptr, 0, 0, nullptr, nullptr, 1);

    // ---- G8 + softmax ----
    tcg(768, 256, 512, HI(B_X1), LO(B_X1, SZ_X1), 512, 768LL*512,
        HI(B_AIB1), LO(B_AIB1, SZ_AIB1), 512, 256LL*512,
        F + F_S3, 256, 768LL*256, BB, scale, nullptr, 0, 0, nullptr, nullptr, 1);
    softmax_hilo<<<BB*768, 256>>>(F + F_S3, HI(B_S3), LO(B_S3, SZ_S3), 256);

    // ---- G9: aij = 0.5*S3@aib1 + F_AIJ -> hi/lo into CAT columns 0..511 ----
    tcg(768, 512, 256, HI(B_S3), LO(B_S3, SZ_S3), 256, 768LL*256,
        HI(B_AIB1T), LO(B_AIB1T, SZ_AIB1T), 256, 512LL*256,
        F + F_AIJ, 512, 768LL*512, BB, 0.5f, nullptr, 1, 0,
        HI(B_CAT), LO(B_CAT, SZ_CAT), 0, nullptr, nullptr, 0, 1024, 768LL*1024);

    // ---- G10 (fused): f = sigmoid([aij|x2] @ [Wf1;Wf2] + b_f), K=1024 ----
    tcg(BN, 512, 1024, HI(B_CAT), LO(B_CAT, SZ_CAT), 1024, 0, HI(B_WFC), LO(B_WFC, SZ_WFC), 1024, 0,
        F + F_FG, 512, 0, 1, 1.0f, b_f, 0, 1, nullptr, nullptr, 1);

    // ---- G12: h = relu(x1 + (aij@W_m + b_m)*f) (act=2) ----
    tcg(BN, 512, 512, HI(B_CAT), LO(B_CAT, SZ_CAT), 1024, 0, HI(B_WM), LO(B_WM, SZ_WM), 512, 0,
        F + F_FG, 512, 0, 1, 1.0f, b_m, 0, 2, HI(B_HB), LO(B_HB, SZ_HB), 0, x1, F + F_FG);

    // ---- G13: QKV -> head-split planes ----
    tcg(BN, 1536, 512, HI(B_HB), LO(B_HB, SZ_HB), 512, 0, HI(B_WQ), LO(B_WQ, SZ_WQ), 512, 0,
        F, 1536, 0, 1, 1.0f, nullptr, 0, 0, QKVH, nullptr, 0, nullptr, nullptr, 1);

    // ---- V^T per head ----
    tconv_bf<<<dim3(64/32, 768/32, BB*HH), tb>>>(QKVH + 4*PS, QKVH + 5*PS, 64, 768LL*64,
        VT, VT + PS, 768, 64LL*768, 768, 64);

    // ---- fused flash MHSA ----
    flash_mhsa<<<dim3(BB*HH, NN_/128), 256, FL_SMEM>>>(
        QKVH, QKVH + PS, QKVH + 2*PS, QKVH + 3*PS,
        VT, VT + PS, HI(B_HC), LO(B_HC, SZ_HC));

    // ---- G16 ----
    tcg(BN, 512, 512, HI(B_HC), LO(B_HC, SZ_HC), 512, 0, HI(B_WP), LO(B_WP, SZ_WP), 512, 0,
        out, 512, 0, 1, 1.0f, b_proj, 0, 0, nullptr, nullptr, 1);
}

// round 12
// speedup vs baseline: 2.5267x; 1.0244x over previous
#include <cuda_runtime.h>
#include <cuda_bf16.h>
#include <math.h>
#include <stdint.h>

// Problem constants
#define BB   16
#define NN_  768
#define FF   512
#define NBB  256
#define HH   8
#define DD   64

typedef __nv_bfloat16 bf16;

__device__ __forceinline__ uint32_t smem_u32(const void* p) {
    uint32_t a;
    asm("{ .reg .u64 t; cvta.to.shared.u64 t, %1; cvt.u32.u64 %0, t; }" : "=r"(a) : "l"(p));
    return a;
}

__device__ __forceinline__ void ldsm4(uint32_t* r, uint32_t addr) {
    asm volatile("ldmatrix.sync.aligned.m8n8.x4.shared.b16 {%0,%1,%2,%3}, [%4];"
        : "=r"(r[0]), "=r"(r[1]), "=r"(r[2]), "=r"(r[3]) : "r"(addr));
}

__device__ __forceinline__ void mma16816(float* c, const uint32_t* a, const uint32_t* b) {
    asm volatile(
        "mma.sync.aligned.m16n8k16.row.col.f32.bf16.bf16.f32 "
        "{%0,%1,%2,%3}, {%4,%5,%6,%7}, {%8,%9}, {%0,%1,%2,%3};"
        : "+f"(c[0]), "+f"(c[1]), "+f"(c[2]), "+f"(c[3])
        : "r"(a[0]), "r"(a[1]), "r"(a[2]), "r"(a[3]), "r"(b[0]), "r"(b[1]));
}

__device__ __forceinline__ void split_hl(float v, bf16& h, bf16& l) {
    h = __float2bfloat16(v);
    l = __float2bfloat16(v - __bfloat162float(h));
}

__device__ __forceinline__ uint32_t packb(bf16 lo16, bf16 hi16) {
    __nv_bfloat162 t; t.x = lo16; t.y = hi16;
    return *(uint32_t*)&t;
}

// cp.async helpers (16B)
__device__ __forceinline__ void cp16(uint32_t d, const void* s) {
    asm volatile("cp.async.cg.shared.global [%0], [%1], 16;" :: "r"(d), "l"(s));
}
#define CP_COMMIT() asm volatile("cp.async.commit_group;" ::: "memory")
#define CP_WAIT0()  asm volatile("cp.async.wait_group 0;" ::: "memory")
#define CP_WAIT1()  asm volatile("cp.async.wait_group 1;" ::: "memory")

// ===========================================================================
// Scratch buffers
// ===========================================================================
static const long long F_S1   = 0;                          // 16x256x768
static const long long F_S2   = F_S1  + 16LL*256*768;       // 16x768x256
static const long long F_S3   = F_S2  + 16LL*768*256;       // 16x768x256
static const long long F_AIJ  = F_S3  + 16LL*768*256;       // 12288x512
static const long long F_FG   = F_AIJ + 12288LL*512;        // 12288x512
static const long long F_TOT  = F_FG  + 12288LL*512;

__device__ float g_f32[F_TOT];

#define PS 6291456LL   // plane size: 16*8*768*64

static const long long B_X1    = 0;                             static const long long SZ_X1    = 12288LL*512;
static const long long B_ZB    = B_X1    + 2*SZ_X1;             static const long long SZ_ZB    = 256LL*512;
static const long long B_WB    = B_ZB    + 2*SZ_ZB;             static const long long SZ_WB    = 1536LL*512;
static const long long B_WI    = B_WB    + 2*SZ_WB;             static const long long SZ_WI    = 1024LL*512;
static const long long B_WJ    = B_WI    + 2*SZ_WI;             static const long long SZ_WJ    = 512LL*512;
static const long long B_WFC   = B_WJ    + 2*SZ_WJ;             static const long long SZ_WFC   = 512LL*1024;
static const long long B_WM    = B_WFC   + 2*SZ_WFC;            static const long long SZ_WM    = 512LL*512;
static const long long B_WQ    = B_WM    + 2*SZ_WM;             static const long long SZ_WQ    = 1536LL*512;
static const long long B_WP    = B_WQ    + 2*SZ_WQ;             static const long long SZ_WP    = 512LL*512;
static const long long B_QKVB  = B_WP    + 2*SZ_WP;             static const long long SZ_QKVB  = 256LL*1536;
static const long long B_KVI   = B_QKVB  + 2*SZ_QKVB;           static const long long SZ_KVI   = 12288LL*1024;
static const long long B_QJ    = B_KVI   + 2*SZ_KVI;            static const long long SZ_QJ    = 12288LL*512;
static const long long B_S1    = B_QJ    + 2*SZ_QJ;             static const long long SZ_S1    = 16LL*256*768;
static const long long B_VIT   = B_S1    + 2*SZ_S1;             static const long long SZ_VIT   = 16LL*512*768;
static const long long B_AIB1  = B_VIT   + 2*SZ_VIT;            static const long long SZ_AIB1  = 16LL*256*512;
static const long long B_AIB1T = B_AIB1  + 2*SZ_AIB1;           static const long long SZ_AIB1T = 16LL*512*256;
static const long long B_VBT   = B_AIB1T + 2*SZ_AIB1T;          static const long long SZ_VBT   = 512LL*256;
static const long long B_S2    = B_VBT   + 2*SZ_VBT;            static const long long SZ_S2    = 16LL*768*256;
static const long long B_S3    = B_S2    + 2*SZ_S2;             static const long long SZ_S3    = 16LL*768*256;
static const long long B_CAT   = B_S3    + 2*SZ_S3;             static const long long SZ_CAT   = 12288LL*1024; // [aij | x2]
static const long long B_HB    = B_CAT   + 2*SZ_CAT;            static const long long SZ_HB    = 12288LL*512;
static const long long B_QKVH  = B_HB    + 2*SZ_HB;             // 6 planes
static const long long B_VT    = B_QKVH  + 6*PS;                // 2 planes
static const long long B_HC    = B_VT    + 2*PS;                static const long long SZ_HC    = 12288LL*512;
static const long long B_TOT   = B_HC    + 2*SZ_HC;

__device__ bf16 g_bf[B_TOT];

// ===========================================================================
// mma.sync GEMM, cp.async 2-stage pipelined mainloop + fused epilogues
// ===========================================================================
#define KT 32
#define SMP 40
#define HALFB  (128 * SMP * 2)
#define STGB   (4 * HALFB)
#define GEMM_SMEM (2 * STGB)        // 81920 bytes

__global__ void __launch_bounds__(256, 2)
mma_gemm(int M, int N, int K,
         const bf16* __restrict__ Ahi, const bf16* __restrict__ Alo, int lda, long long sA,
         const bf16* __restrict__ Bhi, const bf16* __restrict__ Blo, int ldb, long long sB,
         float* __restrict__ C, int ldc, long long sC,
         float alpha, const float* __restrict__ bias, int beta, int act,
         bf16* __restrict__ Chi, bf16* __restrict__ Clo, int wr_f32,
         const float* __restrict__ Gz, const float* __restrict__ Gf, int qkv,
         int ldco, long long sCo)
{
    extern __shared__ bf16 smbuf[];
    const uint32_t sbase = smem_u32(smbuf);

    const int tid = threadIdx.x, lane = tid & 31, wid = tid >> 5;
    const int bz = blockIdx.z;
    const int m0 = blockIdx.y * 128, n0 = blockIdx.x * 128;
    const int wm = wid & 3, wn = wid >> 2;
    const int m0w = wm * 32, n0w = wn * 64;

    const bf16* Ah = Ahi + bz * sA + (size_t)m0 * lda;
    const bf16* Al = Alo + bz * sA + (size_t)m0 * lda;
    const bf16* Bh = Bhi + bz * sB + (size_t)n0 * ldb;
    const bf16* Bl = Blo + bz * sB + (size_t)n0 * ldb;

    float acc[2][8][4];
    #pragma unroll
    for (int i = 0; i < 2; ++i)
        #pragma unroll
        for (int j = 0; j < 8; ++j)
            #pragma unroll
            for (int q = 0; q < 4; ++q) acc[i][j][q] = 0.0f;

    const int nk = K / KT;

    auto load_stage = [&](int st, int k0) {
        const uint32_t sb0 = sbase + st * STGB;
        #pragma unroll
        for (int it = 0; it < 2; ++it) {
            int cid = tid + it * 256;
            int row = cid >> 2;
            int c   = (cid & 3) * 8;
            uint32_t off = (uint32_t)(row * SMP + c) * 2;
            cp16(sb0 + off,              Ah + (size_t)row * lda + k0 + c);
            cp16(sb0 + HALFB + off,      Al + (size_t)row * lda + k0 + c);
            cp16(sb0 + 2 * HALFB + off,  Bh + (size_t)row * ldb + k0 + c);
            cp16(sb0 + 3 * HALFB + off,  Bl + (size_t)row * ldb + k0 + c);
        }
    };

    load_stage(0, 0);
    CP_COMMIT();

    for (int i = 0; i < nk; ++i) {
        if (i + 1 < nk) { load_stage((i + 1) & 1, (i + 1) * KT); CP_COMMIT(); }
        if (i + 1 < nk) CP_WAIT1(); else CP_WAIT0();
        __syncthreads();

        const uint32_t sa  = sbase + (i & 1) * STGB;
        const uint32_t sbm = sa + 2 * HALFB;

        #pragma unroll
        for (int kk = 0; kk < 2; ++kk) {
            uint32_t ah[2][4], al[2][4];
            #pragma unroll
            for (int mi = 0; mi < 2; ++mi) {
                uint32_t addr = sa + ((m0w + mi * 16 + (lane & 15)) * SMP
                                      + kk * 16 + (lane >> 4) * 8) * 2;
                ldsm4(ah[mi], addr);
                ldsm4(al[mi], addr + HALFB);
            }
            #pragma unroll
            for (int g = 0; g < 4; ++g) {
                uint32_t bh[4], bl[4];
                int q = lane >> 3;
                int row = n0w + g * 16 + ((q >> 1) << 3) + (lane & 7);
                int kc  = kk * 16 + (q & 1) * 8;
                uint32_t addr = sbm + (row * SMP + kc) * 2;
                ldsm4(bh, addr);
                ldsm4(bl, addr + HALFB);
                #pragma unroll
                for (int mi = 0; mi < 2; ++mi) {
                    mma16816(acc[mi][g * 2 + 0], ah[mi], bh + 0);
                    mma16816(acc[mi][g * 2 + 0], ah[mi], bl + 0);
                    mma16816(acc[mi][g * 2 + 0], al[mi], bh + 0);
                    mma16816(acc[mi][g * 2 + 1], ah[mi], bh + 2);
                    mma16816(acc[mi][g * 2 + 1], ah[mi], bl + 2);
                    mma16816(acc[mi][g * 2 + 1], al[mi], bh + 2);
                }
            }
        }
        __syncthreads();
    }

    const int rb = m0 + m0w + (lane >> 2);
    const int cb = n0 + n0w + (lane & 3) * 2;

    if (qkv) {
        #pragma unroll
        for (int mi = 0; mi < 2; ++mi) {
            #pragma unroll
            for (int ni = 0; ni < 8; ++ni) {
                const int col = cb + ni * 8;
                const int t = col >> 9, cw = col & 511;
                const int hh2 = cw >> 6, dd2 = cw & 63;
                bf16* ph = Chi + (long long)t * 2 * PS;
                #pragma unroll
                for (int h2 = 0; h2 < 2; ++h2) {
                    const int row = rb + mi * 16 + h2 * 8;
                    const int b2 = row / 768, n2 = row - b2 * 768;
                    size_t ix = ((size_t)((b2 * 8 + hh2) * 768 + n2)) * 64 + dd2;
                    float v0 = acc[mi][ni][h2 * 2 + 0] * alpha;
                    float v1 = acc[mi][ni][h2 * 2 + 1] * alpha;
                    bf16 h0, l0, h1, l1;
                    split_hl(v0, h0, l0); split_hl(v1, h1, l1);
                    *(uint32_t*)(ph + ix) = packb(h0, h1);
                    *(uint32_t*)(ph + PS + ix) = packb(l0, l1);
                }
            }
        }
        return;
    }

    float* Cb = C + bz * sC;
    bf16* Chb = Chi ? Chi + bz * sCo : nullptr;
    bf16* Clb = Clo ? Clo + bz * sCo : nullptr;

    #pragma unroll
    for (int mi = 0; mi < 2; ++mi) {
        #pragma unroll
        for (int ni = 0; ni < 8; ++ni) {
            const int col = cb + ni * 8;
            if (col >= N) continue;
            float b0 = bias ? bias[col] : 0.0f;
            float b1 = bias ? bias[col + 1] : 0.0f;
            #pragma unroll
            for (int h = 0; h < 2; ++h) {
                const int row = rb + mi * 16 + h * 8;
                size_t ix = (size_t)row * ldc + col;
                float v0 = acc[mi][ni][h * 2 + 0] * alpha + b0;
                float v1 = acc[mi][ni][h * 2 + 1] * alpha + b1;
                if (beta) { v0 += Cb[ix]; v1 += Cb[ix + 1]; }
                if (act == 1) {
                    v0 = 1.0f / (1.0f + __expf(-v0));
                    v1 = 1.0f / (1.0f + __expf(-v1));
                } else if (act == 2) {
                    v0 = fmaxf(0.0f, Gz[ix] + v0 * Gf[ix]);
                    v1 = fmaxf(0.0f, Gz[ix + 1] + v1 * Gf[ix + 1]);
                }
                if (wr_f32) { Cb[ix] = v0; Cb[ix + 1] = v1; }
                if (Chb) {
                    size_t ixo = (size_t)row * ldco + col;
                    bf16 hh, ll;
                    split_hl(v0, hh, ll); Chb[ixo] = hh; Clb[ixo] = ll;
                    split_hl(v1, hh, ll); Chb[ixo + 1] = hh; Clb[ixo + 1] = ll;
                }
            }
        }
    }
}

// ===========================================================================
// Fused flash MHSA (unchanged — verified)
// ===========================================================================
#define QPITCH 72
#define VPITCH 136
#define FL_SMEM ((4 * 128 * QPITCH + 2 * 64 * VPITCH) * 2)

__global__ void __launch_bounds__(256)
flash_mhsa(const bf16* __restrict__ Qhp, const bf16* __restrict__ Qlp,
           const bf16* __restrict__ Khp, const bf16* __restrict__ Klp,
           const bf16* __restrict__ VThp, const bf16* __restrict__ VTlp,
           bf16* __restrict__ Ohi, bf16* __restrict__ Olo)
{
    extern __shared__ char sm[];
    bf16* sQh = (bf16*)sm;
    bf16* sQl = sQh + 128 * QPITCH;
    bf16* sKh = sQl + 128 * QPITCH;
    bf16* sKl = sKh + 128 * QPITCH;
    bf16* sVh = sKl + 128 * QPITCH;
    bf16* sVl = sVh + 64 * VPITCH;

    const int bh = blockIdx.x;
    const int mb = blockIdx.y;
    const int tid = threadIdx.x, lane = tid & 31, wid = tid >> 5;

    const size_t qoff = (size_t)bh * 768 * 64 + (size_t)mb * 128 * 64;
    const size_t koff = (size_t)bh * 768 * 64;
    const size_t voff = (size_t)bh * 64 * 768;

    for (int i = tid; i < 1024; i += 256) {
        int r = i >> 3, c = (i & 7) * 8;
        *(uint4*)&sQh[r * QPITCH + c] = *(const uint4*)(Qhp + qoff + (size_t)r * 64 + c);
        *(uint4*)&sQl[r * QPITCH + c] = *(const uint4*)(Qlp + qoff + (size_t)r * 64 + c);
    }

    const uint32_t uQ = smem_u32(sQh);
    const uint32_t uK = smem_u32(sKh);
    const uint32_t uV = smem_u32(sVh);
    const uint32_t QHALF = 128 * QPITCH * 2;
    const uint32_t VHALF = 64 * VPITCH * 2;

    float m_r[2] = {-1e30f, -1e30f};
    float l_r[2] = {0.0f, 0.0f};
    float oacc[8][4];
    #pragma unroll
    for (int j = 0; j < 8; ++j)
        #pragma unroll
        for (int q = 0; q < 4; ++q) oacc[j][q] = 0.0f;

    for (int it = 0; it < 6; ++it) {
        for (int i = tid; i < 1024; i += 256) {
            int r = i >> 3, c = (i & 7) * 8;
            *(uint4*)&sKh[r * QPITCH + c] =
                *(const uint4*)(Khp + koff + (size_t)(it * 128 + r) * 64 + c);
            *(uint4*)&sKl[r * QPITCH + c] =
                *(const uint4*)(Klp + koff + (size_t)(it * 128 + r) * 64 + c);
        }
        for (int i = tid; i < 1024; i += 256) {
            int r = i >> 4, c = (i & 15) * 8;
            *(uint4*)&sVh[r * VPITCH + c] =
                *(const uint4*)(VThp + voff + (size_t)r * 768 + it * 128 + c);
            *(uint4*)&sVl[r * VPITCH + c] =
                *(const uint4*)(VTlp + voff + (size_t)r * 768 + it * 128 + c);
        }
        __syncthreads();

        float sacc[16][4];
        #pragma unroll
        for (int g = 0; g < 16; ++g)
            #pragma unroll
            for (int q = 0; q < 4; ++q) sacc[g][q] = 0.0f;

        #pragma unroll
        for (int kk = 0; kk < 4; ++kk) {
            uint32_t ah[4], al[4];
            uint32_t addr = uQ + ((wid * 16 + (lane & 15)) * QPITCH
                                  + kk * 16 + (lane >> 4) * 8) * 2;
            ldsm4(ah, addr);
            ldsm4(al, addr + QHALF);
            #pragma unroll
            for (int g = 0; g < 8; ++g) {
                uint32_t bh4[4], bl4[4];
                int q = lane >> 3;
                int row = g * 16 + ((q >> 1) << 3) + (lane & 7);
                int kc  = kk * 16 + (q & 1) * 8;
                uint32_t ba = uK + (row * QPITCH + kc) * 2;
                ldsm4(bh4, ba);
                ldsm4(bl4, ba + QHALF);
                mma16816(sacc[g * 2 + 0], ah, bh4 + 0);
                mma16816(sacc[g * 2 + 0], ah, bl4 + 0);
                mma16816(sacc[g * 2 + 0], al, bh4 + 0);
                mma16816(sacc[g * 2 + 1], ah, bh4 + 2);
                mma16816(sacc[g * 2 + 1], ah, bl4 + 2);
                mma16816(sacc[g * 2 + 1], al, bh4 + 2);
            }
        }

        float mx0 = -1e30f, mx1 = -1e30f;
        #pragma unroll
        for (int g = 0; g < 16; ++g) {
            sacc[g][0] *= 0.125f; sacc[g][1] *= 0.125f;
            sacc[g][2] *= 0.125f; sacc[g][3] *= 0.125f;
            mx0 = fmaxf(mx0, fmaxf(sacc[g][0], sacc[g][1]));
            mx1 = fmaxf(mx1, fmaxf(sacc[g][2], sacc[g][3]));
        }
        #pragma unroll
        for (int d = 1; d <= 2; d <<= 1) {
            mx0 = fmaxf(mx0, __shfl_xor_sync(0xffffffffu, mx0, d));
            mx1 = fmaxf(mx1, __shfl_xor_sync(0xffffffffu, mx1, d));
        }
        float mn0 = fmaxf(m_r[0], mx0), mn1 = fmaxf(m_r[1], mx1);
        float al0 = __expf(m_r[0] - mn0), al1 = __expf(m_r[1] - mn1);
        float sum0 = 0.0f, sum1 = 0.0f;
        #pragma unroll
        for (int g = 0; g < 16; ++g) {
            sacc[g][0] = __expf(sacc[g][0] - mn0);
            sacc[g][1] = __expf(sacc[g][1] - mn0);
            sacc[g][2] = __expf(sacc[g][2] - mn1);
            sacc[g][3] = __expf(sacc[g][3] - mn1);
            sum0 += sacc[g][0] + sacc[g][1];
            sum1 += sacc[g][2] + sacc[g][3];
        }
        #pragma unroll
        for (int d = 1; d <= 2; d <<= 1) {
            sum0 += __shfl_xor_sync(0xffffffffu, sum0, d);
            sum1 += __shfl_xor_sync(0xffffffffu, sum1, d);
        }
        l_r[0] = l_r[0] * al0 + sum0;
        l_r[1] = l_r[1] * al1 + sum1;
        m_r[0] = mn0; m_r[1] = mn1;
        #pragma unroll
        for (int j = 0; j < 8; ++j) {
            oacc[j][0] *= al0; oacc[j][1] *= al0;
            oacc[j][2] *= al1; oacc[j][3] *= al1;
        }

        #pragma unroll
        for (int s = 0; s < 8; ++s) {
            uint32_t pah[4], pal[4];
            {
                bf16 h0, l0, h1, l1;
                split_hl(sacc[2*s][0], h0, l0); split_hl(sacc[2*s][1], h1, l1);
                pah[0] = packb(h0, h1); pal[0] = packb(l0, l1);
                split_hl(sacc[2*s][2], h0, l0); split_hl(sacc[2*s][3], h1, l1);
                pah[1] = packb(h0, h1); pal[1] = packb(l0, l1);
                split_hl(sacc[2*s+1][0], h0, l0); split_hl(sacc[2*s+1][1], h1, l1);
                pah[2] = packb(h0, h1); pal[2] = packb(l0, l1);
                split_hl(sacc[2*s+1][2], h0, l0); split_hl(sacc[2*s+1][3], h1, l1);
                pah[3] = packb(h0, h1); pal[3] = packb(l0, l1);
            }
            #pragma unroll
            for (int g = 0; g < 4; ++g) {
                uint32_t bh4[4], bl4[4];
                int q = lane >> 3;
                int row = g * 16 + ((q >> 1) << 3) + (lane & 7);
                int kc  = s * 16 + (q & 1) * 8;
                uint32_t ba = uV + (row * VPITCH + kc) * 2;
                ldsm4(bh4, ba);
                ldsm4(bl4, ba + VHALF);
                mma16816(oacc[g * 2 + 0], pah, bh4 + 0);
                mma16816(oacc[g * 2 + 0], pah, bl4 + 0);
                mma16816(oacc[g * 2 + 0], pal, bh4 + 0);
                mma16816(oacc[g * 2 + 1], pah, bh4 + 2);
                mma16816(oacc[g * 2 + 1], pah, bl4 + 2);
                mma16816(oacc[g * 2 + 1], pal, bh4 + 2);
            }
        }
        __syncthreads();
    }

    const float inv0 = 1.0f / l_r[0], inv1 = 1.0f / l_r[1];
    const int b = bh >> 3, h = bh & 7;
    const int n0g = mb * 128 + wid * 16 + (lane >> 2);
    #pragma unroll
    for (int j = 0; j < 8; ++j) {
        const int d = j * 8 + (lane & 3) * 2;
        {
            size_t ix = ((size_t)(b * 768 + n0g) * 512) + h * 64 + d;
            bf16 h0, l0, h1, l1;
            split_hl(oacc[j][0] * inv0, h0, l0);
            split_hl(oacc[j][1] * inv0, h1, l1);
            *(uint32_t*)(Ohi + ix) = packb(h0, h1);
            *(uint32_t*)(Olo + ix) = packb(l0, l1);
        }
        {
            size_t ix = ((size_t)(b * 768 + n0g + 8) * 512) + h * 64 + d;
            bf16 h0, l0, h1, l1;
            split_hl(oacc[j][2] * inv1, h0, l0);
            split_hl(oacc[j][3] * inv1, h1, l1);
            *(uint32_t*)(Ohi + ix) = packb(h0, h1);
            *(uint32_t*)(Olo + ix) = packb(l0, l1);
        }
    }
}

// ===========================================================================
// Conversion / transform kernels
// ===========================================================================
__global__ void conv_hilo(const float* __restrict__ src, int lds,
                          bf16* __restrict__ hi, bf16* __restrict__ lo, int ldd,
                          int R, int C)
{
    long long i = (long long)blockIdx.x * blockDim.x + threadIdx.x;
    int c4 = C / 4;
    if (i >= (long long)R * c4) return;
    int r = (int)(i / c4), c = (int)(i % c4) * 4;
    float4 v = *(const float4*)(src + (size_t)r * lds + c);
    bf16 h0, h1, h2, h3, l0, l1, l2, l3;
    split_hl(v.x, h0, l0); split_hl(v.y, h1, l1);
    split_hl(v.z, h2, l2); split_hl(v.w, h3, l3);
    size_t o = (size_t)r * ldd + c;
    hi[o] = h0; hi[o+1] = h1; hi[o+2] = h2; hi[o+3] = h3;
    lo[o] = l0; lo[o+1] = l1; lo[o+2] = l2; lo[o+3] = l3;
}

// Batched fp32 transpose+split for all weights (R=512 rows each).
struct TTable {
    const float* src[8];
    bf16* hi[8];
    bf16* lo[8];
    int lds[8];
    int ldd[8];
    int C[8];
};

__global__ void tconv_batch(TTable tt)
{
    __shared__ float t[32][33];
    const int e = blockIdx.z;
    const int c0 = blockIdx.x * 32;
    if (c0 >= tt.C[e]) return;
    const float* s = tt.src[e];
    const int lds = tt.lds[e], ldd = tt.ldd[e];
    const int r0 = blockIdx.y * 32;
    int tx = threadIdx.x, ty = threadIdx.y;
    #pragma unroll
    for (int i = 0; i < 32; i += 8) {
        int r = r0 + ty + i, c = c0 + tx;
        t[ty + i][tx] = s[(size_t)r * lds + c];
    }
    __syncthreads();
    bf16* hb = tt.hi[e];
    bf16* lb = tt.lo[e];
    #pragma unroll
    for (int i = 0; i < 32; i += 8) {
        int c = c0 + ty + i, r = r0 + tx;
        bf16 h, l; split_hl(t[tx][ty + i], h, l);
        hb[(size_t)c * ldd + r] = h;
        lb[(size_t)c * ldd + r] = l;
    }
}

// bf16 hi/lo plane transpose
__global__ void tconv_bf(const bf16* __restrict__ sh, const bf16* __restrict__ sl,
                         int lds, long long sS,
                         bf16* __restrict__ dh, bf16* __restrict__ dl,
                         int ldd, long long sD, int R, int C)
{
    __shared__ uint32_t t[32][33];
    const bf16* ph = sh + blockIdx.z * sS;
    const bf16* pl = sl + blockIdx.z * sS;
    int r0 = blockIdx.y * 32, c0 = blockIdx.x * 32;
    int tx = threadIdx.x, ty = threadIdx.y;
    #pragma unroll
    for (int i = 0; i < 32; i += 8) {
        int r = r0 + ty + i, c = c0 + tx;
        t[ty + i][tx] = packb(ph[(size_t)r * lds + c], pl[(size_t)r * lds + c]);
    }
    __syncthreads();
    bf16* hb = dh + blockIdx.z * sD;
    bf16* lb = dl + blockIdx.z * sD;
    #pragma unroll
    for (int i = 0; i < 32; i += 8) {
        int c = c0 + ty + i, r = r0 + tx;
        uint32_t u = t[tx][ty + i];
        __nv_bfloat162 p = *(__nv_bfloat162*)&u;
        hb[(size_t)c * ldd + r] = p.x;
        lb[(size_t)c * ldd + r] = p.y;
    }
}

// register-cached softmax (L <= 768, 256 threads)
__global__ void __launch_bounds__(256)
softmax_hilo(const float* __restrict__ src, bf16* __restrict__ hi, bf16* __restrict__ lo, int L)
{
    __shared__ float red[256];
    const float* p = src + (size_t)blockIdx.x * L;
    bf16* ph = hi + (size_t)blockIdx.x * L;
    bf16* pl = lo + (size_t)blockIdx.x * L;
    const int t = threadIdx.x;
    const int nv = L >> 8;          // 1 or 3

    float v[3];
    float mx = -1e30f;
    for (int j = 0; j < nv; ++j) {
        v[j] = p[t + (j << 8)];
        mx = fmaxf(mx, v[j]);
    }
    red[t] = mx; __syncthreads();
    for (int s = 128; s > 0; s >>= 1) { if (t < s) red[t] = fmaxf(red[t], red[t + s]); __syncthreads(); }
    mx = red[0]; __syncthreads();

    float e[3];
    float sum = 0.0f;
    for (int j = 0; j < nv; ++j) {
        e[j] = __expf(v[j] - mx);
        sum += e[j];
    }
    red[t] = sum; __syncthreads();
    for (int s = 128; s > 0; s >>= 1) { if (t < s) red[t] += red[t + s]; __syncthreads(); }
    const float inv = 1.0f / red[0];
    for (int j = 0; j < nv; ++j) {
        float w = e[j] * inv;
        bf16 h, l; split_hl(w, h, l);
        ph[t + (j << 8)] = h; pl[t + (j << 8)] = l;
    }
}

// ===========================================================================
// Host side
// ===========================================================================
static void tcg(int M, int N, int K,
                const bf16* Ah, const bf16* Al, int lda, long long sA,
                const bf16* Bh, const bf16* Bl, int ldb, long long sB,
                float* C, int ldc, long long sC, int batch,
                float alpha, const float* bias, int beta, int act,
                bf16* Chi, bf16* Clo, int wr_f32,
                const float* Gz = nullptr, const float* Gf = nullptr, int qkv = 0,
                int ldco = -1, long long sCo = -1)
{
    if (ldco < 0) ldco = ldc;
    if (sCo < 0) sCo = sC;
    dim3 grid((N + 127) / 128, M / 128, batch);
    mma_gemm<<<grid, 256, GEMM_SMEM>>>(M, N, K, Ah, Al, lda, sA, Bh, Bl, ldb, sB,
                                       C, ldc, sC, alpha, bias, beta, act, Chi, Clo,
                                       wr_f32, Gz, Gf, qkv, ldco, sCo);
}

extern "C" void kernel_launch(void* const* d_in, const int* in_sizes, int n_in,
                              void* d_out, int out_size)
{
    (void)in_sizes; (void)n_in; (void)out_size;

    cudaFuncSetAttribute(flash_mhsa, cudaFuncAttributeMaxDynamicSharedMemorySize, FL_SMEM);
    cudaFuncSetAttribute(mma_gemm, cudaFuncAttributeMaxDynamicSharedMemorySize, GEMM_SMEM);

    float* F = nullptr; bf16* Bf = nullptr;
    cudaGetSymbolAddress((void**)&F, g_f32);
    cudaGetSymbolAddress((void**)&Bf, g_bf);

    const float* x1     = (const float*)d_in[0];
    const float* x2     = (const float*)d_in[1];
    const float* zb     = (const float*)d_in[2];
    const float* Wqkv_i = (const float*)d_in[3];
    const float* Wqkv_j = (const float*)d_in[4];
    const float* Wqkv_b = (const float*)d_in[5];
    const float* W_f    = (const float*)d_in[6];
    const float* b_f    = (const float*)d_in[7];
    const float* W_m    = (const float*)d_in[8];
    const float* b_m    = (const float*)d_in[9];
    const float* W_QKV  = (const float*)d_in[10];
    const float* W_proj = (const float*)d_in[11];
    const float* b_proj = (const float*)d_in[12];
    float* out = (float*)d_out;

    const float scale = 0.044194173824159216f;   // 512^-0.5
    const int   BN    = BB * NN_;                // 12288

    #define HI(X) (Bf + (X))
    #define LO(X, SZ) (Bf + (X) + (SZ))

    bf16* QKVH = Bf + B_QKVH;
    bf16* VT   = Bf + B_VT;

    // ---- input conversions (x2 goes straight into CAT cols 512..1023) ----
    {
        long long n = 12288LL * 512 / 4;
        conv_hilo<<<(unsigned)((n + 255) / 256), 256>>>(x1, 512, HI(B_X1), LO(B_X1, SZ_X1), 512, 12288, 512);
        conv_hilo<<<(unsigned)((n + 255) / 256), 256>>>(x2, 512, HI(B_CAT) + 512, LO(B_CAT, SZ_CAT) + 512, 1024, 12288, 512);
        long long nz = 256LL * 512 / 4;
        conv_hilo<<<(unsigned)((nz + 255) / 256), 256>>>(zb, 512, HI(B_ZB), LO(B_ZB, SZ_ZB), 512, 256, 512);
    }

    // ---- all weight transposes in ONE batched launch ----
    {
        TTable tt;
        tt.src[0] = Wqkv_b;           tt.hi[0] = HI(B_WB);        tt.lo[0] = LO(B_WB, SZ_WB);         tt.lds[0] = 1536; tt.ldd[0] = 512;  tt.C[0] = 1536;
        tt.src[1] = Wqkv_i + 512;     tt.hi[1] = HI(B_WI);        tt.lo[1] = LO(B_WI, SZ_WI);         tt.lds[1] = 1536; tt.ldd[1] = 512;  tt.C[1] = 1024;
        tt.src[2] = Wqkv_j;           tt.hi[2] = HI(B_WJ);        tt.lo[2] = LO(B_WJ, SZ_WJ);         tt.lds[2] = 1536; tt.ldd[2] = 512;  tt.C[2] = 512;
        tt.src[3] = W_f;              tt.hi[3] = HI(B_WFC);       tt.lo[3] = LO(B_WFC, SZ_WFC);       tt.lds[3] = 512;  tt.ldd[3] = 1024; tt.C[3] = 512;
        tt.src[4] = W_f + 512LL*512;  tt.hi[4] = HI(B_WFC) + 512; tt.lo[4] = LO(B_WFC, SZ_WFC) + 512; tt.lds[4] = 512;  tt.ldd[4] = 1024; tt.C[4] = 512;
        tt.src[5] = W_m;              tt.hi[5] = HI(B_WM);        tt.lo[5] = LO(B_WM, SZ_WM);         tt.lds[5] = 512;  tt.ldd[5] = 512;  tt.C[5] = 512;
        tt.src[6] = W_QKV;            tt.hi[6] = HI(B_WQ);        tt.lo[6] = LO(B_WQ, SZ_WQ);         tt.lds[6] = 1536; tt.ldd[6] = 512;  tt.C[6] = 1536;
        tt.src[7] = W_proj;           tt.hi[7] = HI(B_WP);        tt.lo[7] = LO(B_WP, SZ_WP);         tt.lds[7] = 512;  tt.ldd[7] = 512;  tt.C[7] = 512;
        tconv_batch<<<dim3(1536/32, 512/32, 8), dim3(32, 8)>>>(tt);
    }

    dim3 tb(32, 8);

    // ---- G1 ----
    tcg(256, 1536, 512, HI(B_ZB), LO(B_ZB, SZ_ZB), 512, 0, HI(B_WB), LO(B_WB, SZ_WB), 512, 0,
        F, 1536, 0, 1, 0.2f, nullptr, 0, 0, HI(B_QKVB), LO(B_QKVB, SZ_QKVB), 0);
    // ---- G2 ----
    tcg(BN, 1024, 512, HI(B_X1), LO(B_X1, SZ_X1), 512, 0, HI(B_WI), LO(B_WI, SZ_WI), 512, 0,
        F, 1024, 0, 1, 1.0f, nullptr, 0, 0, HI(B_KVI), LO(B_KVI, SZ_KVI), 0);
    // ---- G3: A = x2 hi/lo from CAT cols 512.. (lda=1024) ----
    tcg(BN, 512, 512, HI(B_CAT) + 512, LO(B_CAT, SZ_CAT) + 512, 1024, 0,
        HI(B_WJ), LO(B_WJ, SZ_WJ), 512, 0,
        F, 512, 0, 1, 1.0f, nullptr, 0, 0, HI(B_QJ), LO(B_QJ, SZ_QJ), 0);
    // ---- transposes of v_b, v_i ----
    tconv_bf<<<dim3(512/32, 256/32, 1), tb>>>(HI(B_QKVB) + 1024, LO(B_QKVB, SZ_QKVB) + 1024, 1536, 0,
        HI(B_VBT), LO(B_VBT, SZ_VBT), 256, 0, 256, 512);
    tconv_bf<<<dim3(512/32, 768/32, BB), tb>>>(HI(B_KVI) + 512, LO(B_KVI, SZ_KVI) + 512, 1024, 768LL*1024,
        HI(B_VIT), LO(B_VIT, SZ_VIT), 768, 512LL*768, 768, 512);

    // ---- G4 + softmax ----
    tcg(256, 768, 512, HI(B_QKVB), LO(B_QKVB, SZ_QKVB), 1536, 0,
        HI(B_KVI), LO(B_KVI, SZ_KVI), 1024, 768LL*1024,
        F + F_S1, 768, 256LL*768, BB, scale, nullptr, 0, 0, nullptr, nullptr, 1);
    softmax_hilo<<<BB*256, 256>>>(F + F_S1, HI(B_S1), LO(B_S1, SZ_S1), 768);

    // ---- G5 ----
    tcg(256, 512, 768, HI(B_S1), LO(B_S1, SZ_S1), 768, 256LL*768,
        HI(B_VIT), LO(B_VIT, SZ_VIT), 768, 512LL*768,
        F, 512, 256LL*512, BB, 1.0f, nullptr, 0, 0, HI(B_AIB1), LO(B_AIB1, SZ_AIB1), 0);
    tconv_bf<<<dim3(512/32, 256/32, BB), tb>>>(HI(B_AIB1), LO(B_AIB1, SZ_AIB1), 512, 256LL*512,
        HI(B_AIB1T), LO(B_AIB1T, SZ_AIB1T), 256, 512LL*256, 256, 512);

    // ---- G6 + softmax ----
    tcg(768, 256, 512, HI(B_QJ), LO(B_QJ, SZ_QJ), 512, 768LL*512,
        HI(B_QKVB) + 512, LO(B_QKVB, SZ_QKVB) + 512, 1536, 0,
        F + F_S2, 256, 768LL*256, BB, scale, nullptr, 0, 0, nullptr, nullptr, 1);
    softmax_hilo<<<BB*768, 256>>>(F + F_S2, HI(B_S2), LO(B_S2, SZ_S2), 256);

    // ---- G7: 0.5*abj -> F_AIJ ----
    tcg(768, 512, 256, HI(B_S2), LO(B_S2, SZ_S2), 256, 768LL*256,
        HI(B_VBT), LO(B_VBT, SZ_VBT), 256, 0,
        F + F_AIJ, 512, 768LL*512, BB, 0.5f, nullptr, 0, 0, nullptr, nullptr, 1);

    // ---- G8 + softmax ----
    tcg(768, 256, 512, HI(B_X1), LO(B_X1, SZ_X1), 512, 768LL*512,
        HI(B_AIB1), LO(B_AIB1, SZ_AIB1), 512, 256LL*512,
        F + F_S3, 256, 768LL*256, BB, scale, nullptr, 0, 0, nullptr, nullptr, 1);
    softmax_hilo<<<BB*768, 256>>>(F + F_S3, HI(B_S3), LO(B_S3, SZ_S3), 256);

    // ---- G9: aij = 0.5*S3@aib1 + F_AIJ -> hi/lo into CAT columns 0..511 ----
    tcg(768, 512, 256, HI(B_S3), LO(B_S3, SZ_S3), 256, 768LL*256,
        HI(B_AIB1T), LO(B_AIB1T, SZ_AIB1T), 256, 512LL*256,
        F + F_AIJ, 512, 768LL*512, BB, 0.5f, nullptr, 1, 0,
        HI(B_CAT), LO(B_CAT, SZ_CAT), 0, nullptr, nullptr, 0, 1024, 768LL*1024);

    // ---- G10 (fused): f = sigmoid([aij|x2] @ [Wf1;Wf2] + b_f), K=1024 ----
    tcg(BN, 512, 1024, HI(B_CAT), LO(B_CAT, SZ_CAT), 1024, 0, HI(B_WFC), LO(B_WFC, SZ_WFC), 1024, 0,
        F + F_FG, 512, 0, 1, 1.0f, b_f, 0, 1, nullptr, nullptr, 1);

    // ---- G12: h = relu(x1 + (aij@W_m + b_m)*f) (act=2) ----
    tcg(BN, 512, 512, HI(B_CAT), LO(B_CAT, SZ_CAT), 1024, 0, HI(B_WM), LO(B_WM, SZ_WM), 512, 0,
        F + F_FG, 512, 0, 1, 1.0f, b_m, 0, 2, HI(B_HB), LO(B_HB, SZ_HB), 0, x1, F + F_FG);

    // ---- G13: QKV -> head-split planes ----
    tcg(BN, 1536, 512, HI(B_HB), LO(B_HB, SZ_HB), 512, 0, HI(B_WQ), LO(B_WQ, SZ_WQ), 512, 0,
        F, 1536, 0, 1, 1.0f, nullptr, 0, 0, QKVH, nullptr, 0, nullptr, nullptr, 1);

    // ---- V^T per head ----
    tconv_bf<<<dim3(64/32, 768/32, BB*HH), tb>>>(QKVH + 4*PS, QKVH + 5*PS, 64, 768LL*64,
        VT, VT + PS, 768, 64LL*768, 768, 64);

    // ---- fused flash MHSA ----
    flash_mhsa<<<dim3(BB*HH, NN_/128), 256, FL_SMEM>>>(
        QKVH, QKVH + PS, QKVH + 2*PS, QKVH + 3*PS,
        VT, VT + PS, HI(B_HC), LO(B_HC, SZ_HC));

    // ---- G16 ----
    tcg(BN, 512, 512, HI(B_HC), LO(B_HC, SZ_HC), 512, 0, HI(B_WP), LO(B_WP, SZ_WP), 512, 0,
        out, 512, 0, 1, 1.0f, b_proj, 0, 0, nullptr, nullptr, 1);
}

// round 13
// speedup vs baseline: 2.6875x; 1.0636x over previous
#include <cuda_runtime.h>
#include <cuda_bf16.h>
#include <math.h>
#include <stdint.h>

// Problem constants
#define BB   16
#define NN_  768
#define FF   512
#define NBB  256
#define HH   8
#define DD   64

typedef __nv_bfloat16 bf16;

__device__ __forceinline__ uint32_t smem_u32(const void* p) {
    uint32_t a;
    asm("{ .reg .u64 t; cvta.to.shared.u64 t, %1; cvt.u32.u64 %0, t; }" : "=r"(a) : "l"(p));
    return a;
}

__device__ __forceinline__ void ldsm4(uint32_t* r, uint32_t addr) {
    asm volatile("ldmatrix.sync.aligned.m8n8.x4.shared.b16 {%0,%1,%2,%3}, [%4];"
        : "=r"(r[0]), "=r"(r[1]), "=r"(r[2]), "=r"(r[3]) : "r"(addr));
}

__device__ __forceinline__ void mma16816(float* c, const uint32_t* a, const uint32_t* b) {
    asm volatile(
        "mma.sync.aligned.m16n8k16.row.col.f32.bf16.bf16.f32 "
        "{%0,%1,%2,%3}, {%4,%5,%6,%7}, {%8,%9}, {%0,%1,%2,%3};"
        : "+f"(c[0]), "+f"(c[1]), "+f"(c[2]), "+f"(c[3])
        : "r"(a[0]), "r"(a[1]), "r"(a[2]), "r"(a[3]), "r"(b[0]), "r"(b[1]));
}

__device__ __forceinline__ void split_hl(float v, bf16& h, bf16& l) {
    h = __float2bfloat16(v);
    l = __float2bfloat16(v - __bfloat162float(h));
}

__device__ __forceinline__ uint32_t packb(bf16 lo16, bf16 hi16) {
    __nv_bfloat162 t; t.x = lo16; t.y = hi16;
    return *(uint32_t*)&t;
}

__device__ __forceinline__ void cp16(uint32_t d, const void* s) {
    asm volatile("cp.async.cg.shared.global [%0], [%1], 16;" :: "r"(d), "l"(s));
}
#define CP_COMMIT() asm volatile("cp.async.commit_group;" ::: "memory")
#define CP_WAIT0()  asm volatile("cp.async.wait_group 0;" ::: "memory")
#define CP_WAIT1()  asm volatile("cp.async.wait_group 1;" ::: "memory")

// ===========================================================================
// Scratch buffers
// ===========================================================================
static const long long F_S1   = 0;
static const long long F_S2   = F_S1  + 16LL*256*768;
static const long long F_S3   = F_S2  + 16LL*768*256;
static const long long F_AIJ  = F_S3  + 16LL*768*256;
static const long long F_FG   = F_AIJ + 12288LL*512;
static const long long F_TOT  = F_FG  + 12288LL*512;

__device__ float g_f32[F_TOT];

#define PS 6291456LL

static const long long B_X1    = 0;                             static const long long SZ_X1    = 12288LL*512;
static const long long B_ZB    = B_X1    + 2*SZ_X1;             static const long long SZ_ZB    = 256LL*512;
static const long long B_WB    = B_ZB    + 2*SZ_ZB;             static const long long SZ_WB    = 1536LL*512;
static const long long B_WI    = B_WB    + 2*SZ_WB;             static const long long SZ_WI    = 1024LL*512;
static const long long B_WJ    = B_WI    + 2*SZ_WI;             static const long long SZ_WJ    = 512LL*512;
static const long long B_WFC   = B_WJ    + 2*SZ_WJ;             static const long long SZ_WFC   = 512LL*1024;
static const long long B_WM    = B_WFC   + 2*SZ_WFC;            static const long long SZ_WM    = 512LL*512;
static const long long B_WQ    = B_WM    + 2*SZ_WM;             static const long long SZ_WQ    = 1536LL*512;
static const long long B_WP    = B_WQ    + 2*SZ_WQ;             static const long long SZ_WP    = 512LL*512;
static const long long B_QKVB  = B_WP    + 2*SZ_WP;             static const long long SZ_QKVB  = 256LL*1536;
static const long long B_KVI   = B_QKVB  + 2*SZ_QKVB;           static const long long SZ_KVI   = 12288LL*1024;
static const long long B_QJ    = B_KVI   + 2*SZ_KVI;            static const long long SZ_QJ    = 12288LL*512;
static const long long B_S1    = B_QJ    + 2*SZ_QJ;             static const long long SZ_S1    = 16LL*256*768;
static const long long B_VIT   = B_S1    + 2*SZ_S1;             static const long long SZ_VIT   = 16LL*512*768;
static const long long B_AIB1  = B_VIT   + 2*SZ_VIT;            static const long long SZ_AIB1  = 16LL*256*512;
static const long long B_AIB1T = B_AIB1  + 2*SZ_AIB1;           static const long long SZ_AIB1T = 16LL*512*256;
static const long long B_VBT   = B_AIB1T + 2*SZ_AIB1T;          static const long long SZ_VBT   = 512LL*256;
static const long long B_S2    = B_VBT   + 2*SZ_VBT;            static const long long SZ_S2    = 16LL*768*256;
static const long long B_S3    = B_S2    + 2*SZ_S2;             static const long long SZ_S3    = 16LL*768*256;
static const long long B_CAT   = B_S3    + 2*SZ_S3;             static const long long SZ_CAT   = 12288LL*1024;
static const long long B_HB    = B_CAT   + 2*SZ_CAT;            static const long long SZ_HB    = 12288LL*512;
static const long long B_QKVH  = B_HB    + 2*SZ_HB;
static const long long B_VT    = B_QKVH  + 6*PS;
static const long long B_HC    = B_VT    + 2*PS;                static const long long SZ_HC    = 12288LL*512;
static const long long B_TOT   = B_HC    + 2*SZ_HC;

__device__ bf16 g_bf[B_TOT];

// ===========================================================================
// GEMM descriptor + multi-GEMM dispatch (wave packing)
// ===========================================================================
#define KT 32
#define SMP 40
#define HALFB  (128 * SMP * 2)
#define STGB   (4 * HALFB)
#define GEMM_SMEM (2 * STGB)

struct GDesc {
    const bf16 *Ahi, *Alo, *Bhi, *Blo;
    int lda, ldb;
    long long sA, sB;
    float* C; int ldc; long long sC;
    float alpha; const float* bias;
    int beta, act;
    bf16 *Chi, *Clo; int wr_f32;
    const float *Gz, *Gf; int qkv;
    int ldco; long long sCo;
    int M, N, K, gx, gy, batch;
};

__device__ __forceinline__ void gemm_body(const GDesc& d, int bxi, int byi, int bzi,
                                          bf16* smbuf, int tid)
{
    const uint32_t sbase = smem_u32(smbuf);
    const int lane = tid & 31, wid = tid >> 5;
    const int m0 = byi * 128, n0 = bxi * 128;
    const int wm = wid & 3, wn = wid >> 2;
    const int m0w = wm * 32, n0w = wn * 64;

    const bf16* Ah = d.Ahi + bzi * d.sA + (size_t)m0 * d.lda;
    const bf16* Al = d.Alo + bzi * d.sA + (size_t)m0 * d.lda;
    const bf16* Bh = d.Bhi + bzi * d.sB + (size_t)n0 * d.ldb;
    const bf16* Bl = d.Blo + bzi * d.sB + (size_t)n0 * d.ldb;

    float acc[2][8][4];
    #pragma unroll
    for (int i = 0; i < 2; ++i)
        #pragma unroll
        for (int j = 0; j < 8; ++j)
            #pragma unroll
            for (int q = 0; q < 4; ++q) acc[i][j][q] = 0.0f;

    const int nk = d.K / KT;
    const int lda = d.lda, ldb = d.ldb;

    auto load_stage = [&](int st, int k0) {
        const uint32_t sb0 = sbase + st * STGB;
        #pragma unroll
        for (int it = 0; it < 2; ++it) {
            int cid = tid + it * 256;
            int row = cid >> 2;
            int c   = (cid & 3) * 8;
            uint32_t off = (uint32_t)(row * SMP + c) * 2;
            cp16(sb0 + off,              Ah + (size_t)row * lda + k0 + c);
            cp16(sb0 + HALFB + off,      Al + (size_t)row * lda + k0 + c);
            cp16(sb0 + 2 * HALFB + off,  Bh + (size_t)row * ldb + k0 + c);
            cp16(sb0 + 3 * HALFB + off,  Bl + (size_t)row * ldb + k0 + c);
        }
    };

    load_stage(0, 0);
    CP_COMMIT();

    for (int i = 0; i < nk; ++i) {
        if (i + 1 < nk) { load_stage((i + 1) & 1, (i + 1) * KT); CP_COMMIT(); }
        if (i + 1 < nk) CP_WAIT1(); else CP_WAIT0();
        __syncthreads();

        const uint32_t sa  = sbase + (i & 1) * STGB;
        const uint32_t sbm = sa + 2 * HALFB;

        #pragma unroll
        for (int kk = 0; kk < 2; ++kk) {
            uint32_t ah[2][4], al[2][4];
            #pragma unroll
            for (int mi = 0; mi < 2; ++mi) {
                uint32_t addr = sa + ((m0w + mi * 16 + (lane & 15)) * SMP
                                      + kk * 16 + (lane >> 4) * 8) * 2;
                ldsm4(ah[mi], addr);
                ldsm4(al[mi], addr + HALFB);
            }
            #pragma unroll
            for (int g = 0; g < 4; ++g) {
                uint32_t bh[4], bl[4];
                int q = lane >> 3;
                int row = n0w + g * 16 + ((q >> 1) << 3) + (lane & 7);
                int kc  = kk * 16 + (q & 1) * 8;
                uint32_t addr = sbm + (row * SMP + kc) * 2;
                ldsm4(bh, addr);
                ldsm4(bl, addr + HALFB);
                #pragma unroll
                for (int mi = 0; mi < 2; ++mi) {
                    mma16816(acc[mi][g * 2 + 0], ah[mi], bh + 0);
                    mma16816(acc[mi][g * 2 + 0], ah[mi], bl + 0);
                    mma16816(acc[mi][g * 2 + 0], al[mi], bh + 0);
                    mma16816(acc[mi][g * 2 + 1], ah[mi], bh + 2);
                    mma16816(acc[mi][g * 2 + 1], ah[mi], bl + 2);
                    mma16816(acc[mi][g * 2 + 1], al[mi], bh + 2);
                }
            }
        }
        __syncthreads();
    }

    const int rb = m0 + m0w + (lane >> 2);
    const int cb = n0 + n0w + (lane & 3) * 2;

    if (d.qkv) {
        #pragma unroll
        for (int mi = 0; mi < 2; ++mi) {
            #pragma unroll
            for (int ni = 0; ni < 8; ++ni) {
                const int col = cb + ni * 8;
                const int t = col >> 9, cw = col & 511;
                const int hh2 = cw >> 6, dd2 = cw & 63;
                bf16* ph = d.Chi + (long long)t * 2 * PS;
                #pragma unroll
                for (int h2 = 0; h2 < 2; ++h2) {
                    const int row = rb + mi * 16 + h2 * 8;
                    const int b2 = row / 768, n2 = row - b2 * 768;
                    size_t ix = ((size_t)((b2 * 8 + hh2) * 768 + n2)) * 64 + dd2;
                    float v0 = acc[mi][ni][h2 * 2 + 0] * d.alpha;
                    float v1 = acc[mi][ni][h2 * 2 + 1] * d.alpha;
                    bf16 h0, l0, h1, l1;
                    split_hl(v0, h0, l0); split_hl(v1, h1, l1);
                    *(uint32_t*)(ph + ix) = packb(h0, h1);
                    *(uint32_t*)(ph + PS + ix) = packb(l0, l1);
                }
            }
        }
        return;
    }

    float* Cb = d.C + bzi * d.sC;
    bf16* Chb = d.Chi ? d.Chi + bzi * d.sCo : nullptr;
    bf16* Clb = d.Clo ? d.Clo + bzi * d.sCo : nullptr;

    #pragma unroll
    for (int mi = 0; mi < 2; ++mi) {
        #pragma unroll
        for (int ni = 0; ni < 8; ++ni) {
            const int col = cb + ni * 8;
            if (col >= d.N) continue;
            float b0 = d.bias ? d.bias[col] : 0.0f;
            float b1 = d.bias ? d.bias[col + 1] : 0.0f;
            #pragma unroll
            for (int h = 0; h < 2; ++h) {
                const int row = rb + mi * 16 + h * 8;
                size_t ix = (size_t)row * d.ldc + col;
                float v0 = acc[mi][ni][h * 2 + 0] * d.alpha + b0;
                float v1 = acc[mi][ni][h * 2 + 1] * d.alpha + b1;
                if (d.beta) { v0 += Cb[ix]; v1 += Cb[ix + 1]; }
                if (d.act == 1) {
                    v0 = 1.0f / (1.0f + __expf(-v0));
                    v1 = 1.0f / (1.0f + __expf(-v1));
                } else if (d.act == 2) {
                    v0 = fmaxf(0.0f, d.Gz[ix] + v0 * d.Gf[ix]);
                    v1 = fmaxf(0.0f, d.Gz[ix + 1] + v1 * d.Gf[ix + 1]);
                }
                if (d.wr_f32) { Cb[ix] = v0; Cb[ix + 1] = v1; }
                if (Chb) {
                    size_t ixo = (size_t)row * d.ldco + col;
                    bf16 hh, ll;
                    split_hl(v0, hh, ll); Chb[ixo] = hh; Clb[ixo] = ll;
                    split_hl(v1, hh, ll); Chb[ixo + 1] = hh; Clb[ixo + 1] = ll;
                }
            }
        }
    }
}

__global__ void __launch_bounds__(256, 2)
mma_multi(GDesc d0, GDesc d1, GDesc d2, int n1, int n2)
{
    extern __shared__ bf16 smbuf[];
    const GDesc& d = (blockIdx.x < (unsigned)n1) ? d0
                   : ((blockIdx.x < (unsigned)n2) ? d1 : d2);
    int local = (blockIdx.x < (unsigned)n1) ? blockIdx.x
              : ((blockIdx.x < (unsigned)n2) ? blockIdx.x - n1 : blockIdx.x - n2);
    int per = d.gx * d.gy;
    int bzi = local / per;
    int rem = local - bzi * per;
    int byi = rem / d.gx;
    int bxi = rem - byi * d.gx;
    gemm_body(d, bxi, byi, bzi, smbuf, threadIdx.x);
}

// ===========================================================================
// Fused flash MHSA (unchanged — verified)
// ===========================================================================
#define QPITCH 72
#define VPITCH 136
#define FL_SMEM ((4 * 128 * QPITCH + 2 * 64 * VPITCH) * 2)

__global__ void __launch_bounds__(256)
flash_mhsa(const bf16* __restrict__ Qhp, const bf16* __restrict__ Qlp,
           const bf16* __restrict__ Khp, const bf16* __restrict__ Klp,
           const bf16* __restrict__ VThp, const bf16* __restrict__ VTlp,
           bf16* __restrict__ Ohi, bf16* __restrict__ Olo)
{
    extern __shared__ char sm[];
    bf16* sQh = (bf16*)sm;
    bf16* sQl = sQh + 128 * QPITCH;
    bf16* sKh = sQl + 128 * QPITCH;
    bf16* sKl = sKh + 128 * QPITCH;
    bf16* sVh = sKl + 128 * QPITCH;
    bf16* sVl = sVh + 64 * VPITCH;

    const int bh = blockIdx.x;
    const int mb = blockIdx.y;
    const int tid = threadIdx.x, lane = tid & 31, wid = tid >> 5;

    const size_t qoff = (size_t)bh * 768 * 64 + (size_t)mb * 128 * 64;
    const size_t koff = (size_t)bh * 768 * 64;
    const size_t voff = (size_t)bh * 64 * 768;

    for (int i = tid; i < 1024; i += 256) {
        int r = i >> 3, c = (i & 7) * 8;
        *(uint4*)&sQh[r * QPITCH + c] = *(const uint4*)(Qhp + qoff + (size_t)r * 64 + c);
        *(uint4*)&sQl[r * QPITCH + c] = *(const uint4*)(Qlp + qoff + (size_t)r * 64 + c);
    }

    const uint32_t uQ = smem_u32(sQh);
    const uint32_t uK = smem_u32(sKh);
    const uint32_t uV = smem_u32(sVh);
    const uint32_t QHALF = 128 * QPITCH * 2;
    const uint32_t VHALF = 64 * VPITCH * 2;

    float m_r[2] = {-1e30f, -1e30f};
    float l_r[2] = {0.0f, 0.0f};
    float oacc[8][4];
    #pragma unroll
    for (int j = 0; j < 8; ++j)
        #pragma unroll
        for (int q = 0; q < 4; ++q) oacc[j][q] = 0.0f;

    for (int it = 0; it < 6; ++it) {
        for (int i = tid; i < 1024; i += 256) {
            int r = i >> 3, c = (i & 7) * 8;
            *(uint4*)&sKh[r * QPITCH + c] =
                *(const uint4*)(Khp + koff + (size_t)(it * 128 + r) * 64 + c);
            *(uint4*)&sKl[r * QPITCH + c] =
                *(const uint4*)(Klp + koff + (size_t)(it * 128 + r) * 64 + c);
        }
        for (int i = tid; i < 1024; i += 256) {
            int r = i >> 4, c = (i & 15) * 8;
            *(uint4*)&sVh[r * VPITCH + c] =
                *(const uint4*)(VThp + voff + (size_t)r * 768 + it * 128 + c);
            *(uint4*)&sVl[r * VPITCH + c] =
                *(const uint4*)(VTlp + voff + (size_t)r * 768 + it * 128 + c);
        }
        __syncthreads();

        float sacc[16][4];
        #pragma unroll
        for (int g = 0; g < 16; ++g)
            #pragma unroll
            for (int q = 0; q < 4; ++q) sacc[g][q] = 0.0f;

        #pragma unroll
        for (int kk = 0; kk < 4; ++kk) {
            uint32_t ah[4], al[4];
            uint32_t addr = uQ + ((wid * 16 + (lane & 15)) * QPITCH
                                  + kk * 16 + (lane >> 4) * 8) * 2;
            ldsm4(ah, addr);
            ldsm4(al, addr + QHALF);
            #pragma unroll
            for (int g = 0; g < 8; ++g) {
                uint32_t bh4[4], bl4[4];
                int q = lane >> 3;
                int row = g * 16 + ((q >> 1) << 3) + (lane & 7);
                int kc  = kk * 16 + (q & 1) * 8;
                uint32_t ba = uK + (row * QPITCH + kc) * 2;
                ldsm4(bh4, ba);
                ldsm4(bl4, ba + QHALF);
                mma16816(sacc[g * 2 + 0], ah, bh4 + 0);
                mma16816(sacc[g * 2 + 0], ah, bl4 + 0);
                mma16816(sacc[g * 2 + 0], al, bh4 + 0);
                mma16816(sacc[g * 2 + 1], ah, bh4 + 2);
                mma16816(sacc[g * 2 + 1], ah, bl4 + 2);
                mma16816(sacc[g * 2 + 1], al, bh4 + 2);
            }
        }

        float mx0 = -1e30f, mx1 = -1e30f;
        #pragma unroll
        for (int g = 0; g < 16; ++g) {
            sacc[g][0] *= 0.125f; sacc[g][1] *= 0.125f;
            sacc[g][2] *= 0.125f; sacc[g][3] *= 0.125f;
            mx0 = fmaxf(mx0, fmaxf(sacc[g][0], sacc[g][1]));
            mx1 = fmaxf(mx1, fmaxf(sacc[g][2], sacc[g][3]));
        }
        #pragma unroll
        for (int d = 1; d <= 2; d <<= 1) {
            mx0 = fmaxf(mx0, __shfl_xor_sync(0xffffffffu, mx0, d));
            mx1 = fmaxf(mx1, __shfl_xor_sync(0xffffffffu, mx1, d));
        }
        float mn0 = fmaxf(m_r[0], mx0), mn1 = fmaxf(m_r[1], mx1);
        float al0 = __expf(m_r[0] - mn0), al1 = __expf(m_r[1] - mn1);
        float sum0 = 0.0f, sum1 = 0.0f;
        #pragma unroll
        for (int g = 0; g < 16; ++g) {
            sacc[g][0] = __expf(sacc[g][0] - mn0);
            sacc[g][1] = __expf(sacc[g][1] - mn0);
            sacc[g][2] = __expf(sacc[g][2] - mn1);
            sacc[g][3] = __expf(sacc[g][3] - mn1);
            sum0 += sacc[g][0] + sacc[g][1];
            sum1 += sacc[g][2] + sacc[g][3];
        }
        #pragma unroll
        for (int d = 1; d <= 2; d <<= 1) {
            sum0 += __shfl_xor_sync(0xffffffffu, sum0, d);
            sum1 += __shfl_xor_sync(0xffffffffu, sum1, d);
        }
        l_r[0] = l_r[0] * al0 + sum0;
        l_r[1] = l_r[1] * al1 + sum1;
        m_r[0] = mn0; m_r[1] = mn1;
        #pragma unroll
        for (int j = 0; j < 8; ++j) {
            oacc[j][0] *= al0; oacc[j][1] *= al0;
            oacc[j][2] *= al1; oacc[j][3] *= al1;
        }

        #pragma unroll
        for (int s = 0; s < 8; ++s) {
            uint32_t pah[4], pal[4];
            {
                bf16 h0, l0, h1, l1;
                split_hl(sacc[2*s][0], h0, l0); split_hl(sacc[2*s][1], h1, l1);
                pah[0] = packb(h0, h1); pal[0] = packb(l0, l1);
                split_hl(sacc[2*s][2], h0, l0); split_hl(sacc[2*s][3], h1, l1);
                pah[1] = packb(h0, h1); pal[1] = packb(l0, l1);
                split_hl(sacc[2*s+1][0], h0, l0); split_hl(sacc[2*s+1][1], h1, l1);
                pah[2] = packb(h0, h1); pal[2] = packb(l0, l1);
                split_hl(sacc[2*s+1][2], h0, l0); split_hl(sacc[2*s+1][3], h1, l1);
                pah[3] = packb(h0, h1); pal[3] = packb(l0, l1);
            }
            #pragma unroll
            for (int g = 0; g < 4; ++g) {
                uint32_t bh4[4], bl4[4];
                int q = lane >> 3;
                int row = g * 16 + ((q >> 1) << 3) + (lane & 7);
                int kc  = s * 16 + (q & 1) * 8;
                uint32_t ba = uV + (row * VPITCH + kc) * 2;
                ldsm4(bh4, ba);
                ldsm4(bl4, ba + VHALF);
                mma16816(oacc[g * 2 + 0], pah, bh4 + 0);
                mma16816(oacc[g * 2 + 0], pah, bl4 + 0);
                mma16816(oacc[g * 2 + 0], pal, bh4 + 0);
                mma16816(oacc[g * 2 + 1], pah, bh4 + 2);
                mma16816(oacc[g * 2 + 1], pah, bl4 + 2);
                mma16816(oacc[g * 2 + 1], pal, bh4 + 2);
            }
        }
        __syncthreads();
    }

    const float inv0 = 1.0f / l_r[0], inv1 = 1.0f / l_r[1];
    const int b = bh >> 3, h = bh & 7;
    const int n0g = mb * 128 + wid * 16 + (lane >> 2);
    #pragma unroll
    for (int j = 0; j < 8; ++j) {
        const int d = j * 8 + (lane & 3) * 2;
        {
            size_t ix = ((size_t)(b * 768 + n0g) * 512) + h * 64 + d;
            bf16 h0, l0, h1, l1;
            split_hl(oacc[j][0] * inv0, h0, l0);
            split_hl(oacc[j][1] * inv0, h1, l1);
            *(uint32_t*)(Ohi + ix) = packb(h0, h1);
            *(uint32_t*)(Olo + ix) = packb(l0, l1);
        }
        {
            size_t ix = ((size_t)(b * 768 + n0g + 8) * 512) + h * 64 + d;
            bf16 h0, l0, h1, l1;
            split_hl(oacc[j][2] * inv1, h0, l0);
            split_hl(oacc[j][3] * inv1, h1, l1);
            *(uint32_t*)(Ohi + ix) = packb(h0, h1);
            *(uint32_t*)(Olo + ix) = packb(l0, l1);
        }
    }
}

// ===========================================================================
// Conversion / transform kernels
// ===========================================================================
// batched fp32 -> hi/lo split (3 entries)
struct CTable {
    const float* src[3];
    bf16* hi[3];
    bf16* lo[3];
    int lds[3], ldd[3], C[3];
    long long n1, n2;   // flat boundaries (in float4 units)
};

__global__ void conv_batch(CTable ct)
{
    long long i = (long long)blockIdx.x * blockDim.x + threadIdx.x;
    int e; long long local;
    if (i < ct.n1) { e = 0; local = i; }
    else if (i < ct.n2) { e = 1; local = i - ct.n1; }
    else { e = 2; local = i - ct.n2; }
    int c4 = ct.C[e] / 4;
    int r = (int)(local / c4), c = (int)(local % c4) * 4;
    float4 v = *(const float4*)(ct.src[e] + (size_t)r * ct.lds[e] + c);
    bf16 h0, h1, h2, h3, l0, l1, l2, l3;
    split_hl(v.x, h0, l0); split_hl(v.y, h1, l1);
    split_hl(v.z, h2, l2); split_hl(v.w, h3, l3);
    size_t o = (size_t)r * ct.ldd[e] + c;
    bf16* hi = ct.hi[e]; bf16* lo = ct.lo[e];
    hi[o] = h0; hi[o+1] = h1; hi[o+2] = h2; hi[o+3] = h3;
    lo[o] = l0; lo[o+1] = l1; lo[o+2] = l2; lo[o+3] = l3;
}

struct TTable {
    const float* src[8];
    bf16* hi[8];
    bf16* lo[8];
    int lds[8];
    int ldd[8];
    int C[8];
};

__global__ void tconv_batch(TTable tt)
{
    __shared__ float t[32][33];
    const int e = blockIdx.z;
    const int c0 = blockIdx.x * 32;
    if (c0 >= tt.C[e]) return;
    const float* s = tt.src[e];
    const int lds = tt.lds[e], ldd = tt.ldd[e];
    const int r0 = blockIdx.y * 32;
    int tx = threadIdx.x, ty = threadIdx.y;
    #pragma unroll
    for (int i = 0; i < 32; i += 8) {
        int r = r0 + ty + i, c = c0 + tx;
        t[ty + i][tx] = s[(size_t)r * lds + c];
    }
    __syncthreads();
    bf16* hb = tt.hi[e];
    bf16* lb = tt.lo[e];
    #pragma unroll
    for (int i = 0; i < 32; i += 8) {
        int c = c0 + ty + i, r = r0 + tx;
        bf16 h, l; split_hl(t[tx][ty + i], h, l);
        hb[(size_t)c * ldd + r] = h;
        lb[(size_t)c * ldd + r] = l;
    }
}

__global__ void tconv_bf(const bf16* __restrict__ sh, const bf16* __restrict__ sl,
                         int lds, long long sS,
                         bf16* __restrict__ dh, bf16* __restrict__ dl,
                         int ldd, long long sD, int R, int C)
{
    __shared__ uint32_t t[32][33];
    const bf16* ph = sh + blockIdx.z * sS;
    const bf16* pl = sl + blockIdx.z * sS;
    int r0 = blockIdx.y * 32, c0 = blockIdx.x * 32;
    int tx = threadIdx.x, ty = threadIdx.y;
    #pragma unroll
    for (int i = 0; i < 32; i += 8) {
        int r = r0 + ty + i, c = c0 + tx;
        t[ty + i][tx] = packb(ph[(size_t)r * lds + c], pl[(size_t)r * lds + c]);
    }
    __syncthreads();
    bf16* hb = dh + blockIdx.z * sD;
    bf16* lb = dl + blockIdx.z * sD;
    #pragma unroll
    for (int i = 0; i < 32; i += 8) {
        int c = c0 + ty + i, r = r0 + tx;
        uint32_t u = t[tx][ty + i];
        __nv_bfloat162 p = *(__nv_bfloat162*)&u;
        hb[(size_t)c * ldd + r] = p.x;
        lb[(size_t)c * ldd + r] = p.y;
    }
}

__global__ void __launch_bounds__(256)
softmax_hilo(const float* __restrict__ src, bf16* __restrict__ hi, bf16* __restrict__ lo, int L)
{
    __shared__ float red[256];
    const float* p = src + (size_t)blockIdx.x * L;
    bf16* ph = hi + (size_t)blockIdx.x * L;
    bf16* pl = lo + (size_t)blockIdx.x * L;
    const int t = threadIdx.x;
    const int nv = L >> 8;

    float v[3];
    float mx = -1e30f;
    for (int j = 0; j < nv; ++j) {
        v[j] = p[t + (j << 8)];
        mx = fmaxf(mx, v[j]);
    }
    red[t] = mx; __syncthreads();
    for (int s = 128; s > 0; s >>= 1) { if (t < s) red[t] = fmaxf(red[t], red[t + s]); __syncthreads(); }
    mx = red[0]; __syncthreads();

    float e[3];
    float sum = 0.0f;
    for (int j = 0; j < nv; ++j) {
        e[j] = __expf(v[j] - mx);
        sum += e[j];
    }
    red[t] = sum; __syncthreads();
    for (int s = 128; s > 0; s >>= 1) { if (t < s) red[t] += red[t + s]; __syncthreads(); }
    const float inv = 1.0f / red[0];
    for (int j = 0; j < nv; ++j) {
        float w = e[j] * inv;
        bf16 h, l; split_hl(w, h, l);
        ph[t + (j << 8)] = h; pl[t + (j << 8)] = l;
    }
}

// ===========================================================================
// Host side
// ===========================================================================
static GDesc mk(int M, int N, int K,
                const bf16* Ah, const bf16* Al, int lda, long long sA,
                const bf16* Bh, const bf16* Bl, int ldb, long long sB,
                float* C, int ldc, long long sC, int batch,
                float alpha, const float* bias, int beta, int act,
                bf16* Chi, bf16* Clo, int wr_f32,
                const float* Gz = nullptr, const float* Gf = nullptr, int qkv = 0,
                int ldco = -1, long long sCo = -1)
{
    GDesc d;
    d.Ahi = Ah; d.Alo = Al; d.Bhi = Bh; d.Blo = Bl;
    d.lda = lda; d.ldb = ldb; d.sA = sA; d.sB = sB;
    d.C = C; d.ldc = ldc; d.sC = sC;
    d.alpha = alpha; d.bias = bias; d.beta = beta; d.act = act;
    d.Chi = Chi; d.Clo = Clo; d.wr_f32 = wr_f32;
    d.Gz = Gz; d.Gf = Gf; d.qkv = qkv;
    d.ldco = (ldco < 0) ? ldc : ldco;
    d.sCo = (sCo < 0) ? sC : sCo;
    d.M = M; d.N = N; d.K = K;
    d.gx = (N + 127) / 128; d.gy = M / 128; d.batch = batch;
    return d;
}
static inline int nblk(const GDesc& d) { return d.gx * d.gy * d.batch; }

static void launch1(const GDesc& a) {
    int n = nblk(a);
    mma_multi<<<n, 256, GEMM_SMEM>>>(a, a, a, n, n);
}
static void launch2(const GDesc& a, const GDesc& b) {
    int na = nblk(a), nb = nblk(b);
    mma_multi<<<na + nb, 256, GEMM_SMEM>>>(a, b, b, na, na + nb);
}
static void launch3(const GDesc& a, const GDesc& b, const GDesc& c) {
    int na = nblk(a), nb = nblk(b), nc = nblk(c);
    mma_multi<<<na + nb + nc, 256, GEMM_SMEM>>>(a, b, c, na, na + nb);
}

extern "C" void kernel_launch(void* const* d_in, const int* in_sizes, int n_in,
                              void* d_out, int out_size)
{
    (void)in_sizes; (void)n_in; (void)out_size;

    cudaFuncSetAttribute(flash_mhsa, cudaFuncAttributeMaxDynamicSharedMemorySize, FL_SMEM);
    cudaFuncSetAttribute(mma_multi, cudaFuncAttributeMaxDynamicSharedMemorySize, GEMM_SMEM);

    float* F = nullptr; bf16* Bf = nullptr;
    cudaGetSymbolAddress((void**)&F, g_f32);
    cudaGetSymbolAddress((void**)&Bf, g_bf);

    const float* x1     = (const float*)d_in[0];
    const float* x2     = (const float*)d_in[1];
    const float* zb     = (const float*)d_in[2];
    const float* Wqkv_i = (const float*)d_in[3];
    const float* Wqkv_j = (const float*)d_in[4];
    const float* Wqkv_b = (const float*)d_in[5];
    const float* W_f    = (const float*)d_in[6];
    const float* b_f    = (const float*)d_in[7];
    const float* W_m    = (const float*)d_in[8];
    const float* b_m    = (const float*)d_in[9];
    const float* W_QKV  = (const float*)d_in[10];
    const float* W_proj = (const float*)d_in[11];
    const float* b_proj = (const float*)d_in[12];
    float* out = (float*)d_out;

    const float scale = 0.044194173824159216f;
    const int   BN    = BB * NN_;

    #define HI(X) (Bf + (X))
    #define LO(X, SZ) (Bf + (X) + (SZ))

    bf16* QKVH = Bf + B_QKVH;
    bf16* VT   = Bf + B_VT;

    // ---- input conversions (one batched launch) ----
    {
        CTable ct;
        ct.src[0] = x1; ct.hi[0] = HI(B_X1);        ct.lo[0] = LO(B_X1, SZ_X1);        ct.lds[0] = 512; ct.ldd[0] = 512;  ct.C[0] = 512;
        ct.src[1] = x2; ct.hi[1] = HI(B_CAT) + 512; ct.lo[1] = LO(B_CAT, SZ_CAT) + 512; ct.lds[1] = 512; ct.ldd[1] = 1024; ct.C[1] = 512;
        ct.src[2] = zb; ct.hi[2] = HI(B_ZB);        ct.lo[2] = LO(B_ZB, SZ_ZB);        ct.lds[2] = 512; ct.ldd[2] = 512;  ct.C[2] = 512;
        ct.n1 = 12288LL * 128;               // x1 float4 count
        ct.n2 = ct.n1 + 12288LL * 128;       // + x2
        long long tot = ct.n2 + 256LL * 128; // + zb
        conv_batch<<<(unsigned)((tot + 255) / 256), 256>>>(ct);
    }

    // ---- all weight transposes in ONE batched launch ----
    {
        TTable tt;
        tt.src[0] = Wqkv_b;           tt.hi[0] = HI(B_WB);        tt.lo[0] = LO(B_WB, SZ_WB);         tt.lds[0] = 1536; tt.ldd[0] = 512;  tt.C[0] = 1536;
        tt.src[1] = Wqkv_i + 512;     tt.hi[1] = HI(B_WI);        tt.lo[1] = LO(B_WI, SZ_WI);         tt.lds[1] = 1536; tt.ldd[1] = 512;  tt.C[1] = 1024;
        tt.src[2] = Wqkv_j;           tt.hi[2] = HI(B_WJ);        tt.lo[2] = LO(B_WJ, SZ_WJ);         tt.lds[2] = 1536; tt.ldd[2] = 512;  tt.C[2] = 512;
        tt.src[3] = W_f;              tt.hi[3] = HI(B_WFC);       tt.lo[3] = LO(B_WFC, SZ_WFC);       tt.lds[3] = 512;  tt.ldd[3] = 1024; tt.C[3] = 512;
        tt.src[4] = W_f + 512LL*512;  tt.hi[4] = HI(B_WFC) + 512; tt.lo[4] = LO(B_WFC, SZ_WFC) + 512; tt.lds[4] = 512;  tt.ldd[4] = 1024; tt.C[4] = 512;
        tt.src[5] = W_m;              tt.hi[5] = HI(B_WM);        tt.lo[5] = LO(B_WM, SZ_WM);         tt.lds[5] = 512;  tt.ldd[5] = 512;  tt.C[5] = 512;
        tt.src[6] = W_QKV;            tt.hi[6] = HI(B_WQ);        tt.lo[6] = LO(B_WQ, SZ_WQ);         tt.lds[6] = 1536; tt.ldd[6] = 512;  tt.C[6] = 1536;
        tt.src[7] = W_proj;           tt.hi[7] = HI(B_WP);        tt.lo[7] = LO(B_WP, SZ_WP);         tt.lds[7] = 512;  tt.ldd[7] = 512;  tt.C[7] = 512;
        tconv_batch<<<dim3(1536/32, 512/32, 8), dim3(32, 8)>>>(tt);
    }

    dim3 tb(32, 8);

    // ---- Group A: G1 + G2 + G3 (independent) ----
    GDesc g1 = mk(256, 1536, 512, HI(B_ZB), LO(B_ZB, SZ_ZB), 512, 0, HI(B_WB), LO(B_WB, SZ_WB), 512, 0,
                  F, 1536, 0, 1, 0.2f, nullptr, 0, 0, HI(B_QKVB), LO(B_QKVB, SZ_QKVB), 0);
    GDesc g2 = mk(BN, 1024, 512, HI(B_X1), LO(B_X1, SZ_X1), 512, 0, HI(B_WI), LO(B_WI, SZ_WI), 512, 0,
                  F, 1024, 0, 1, 1.0f, nullptr, 0, 0, HI(B_KVI), LO(B_KVI, SZ_KVI), 0);
    GDesc g3 = mk(BN, 512, 512, HI(B_CAT) + 512, LO(B_CAT, SZ_CAT) + 512, 1024, 0,
                  HI(B_WJ), LO(B_WJ, SZ_WJ), 512, 0,
                  F, 512, 0, 1, 1.0f, nullptr, 0, 0, HI(B_QJ), LO(B_QJ, SZ_QJ), 0);
    launch3(g2, g3, g1);

    // ---- transposes of v_b, v_i ----
    tconv_bf<<<dim3(512/32, 256/32, 1), tb>>>(HI(B_QKVB) + 1024, LO(B_QKVB, SZ_QKVB) + 1024, 1536, 0,
        HI(B_VBT), LO(B_VBT, SZ_VBT), 256, 0, 256, 512);
    tconv_bf<<<dim3(512/32, 768/32, BB), tb>>>(HI(B_KVI) + 512, LO(B_KVI, SZ_KVI) + 512, 1024, 768LL*1024,
        HI(B_VIT), LO(B_VIT, SZ_VIT), 768, 512LL*768, 768, 512);

    // ---- Group B: G4 + G6 (both ready after Group A) ----
    GDesc g4 = mk(256, 768, 512, HI(B_QKVB), LO(B_QKVB, SZ_QKVB), 1536, 0,
                  HI(B_KVI), LO(B_KVI, SZ_KVI), 1024, 768LL*1024,
                  F + F_S1, 768, 256LL*768, BB, scale, nullptr, 0, 0, nullptr, nullptr, 1);
    GDesc g6 = mk(768, 256, 512, HI(B_QJ), LO(B_QJ, SZ_QJ), 512, 768LL*512,
                  HI(B_QKVB) + 512, LO(B_QKVB, SZ_QKVB) + 512, 1536, 0,
                  F + F_S2, 256, 768LL*256, BB, scale, nullptr, 0, 0, nullptr, nullptr, 1);
    launch2(g4, g6);

    softmax_hilo<<<BB*256, 256>>>(F + F_S1, HI(B_S1), LO(B_S1, SZ_S1), 768);
    softmax_hilo<<<BB*768, 256>>>(F + F_S2, HI(B_S2), LO(B_S2, SZ_S2), 256);

    // ---- Group C: G5 + G7 ----
    GDesc g5 = mk(256, 512, 768, HI(B_S1), LO(B_S1, SZ_S1), 768, 256LL*768,
                  HI(B_VIT), LO(B_VIT, SZ_VIT), 768, 512LL*768,
                  F, 512, 256LL*512, BB, 1.0f, nullptr, 0, 0, HI(B_AIB1), LO(B_AIB1, SZ_AIB1), 0);
    GDesc g7 = mk(768, 512, 256, HI(B_S2), LO(B_S2, SZ_S2), 256, 768LL*256,
                  HI(B_VBT), LO(B_VBT, SZ_VBT), 256, 0,
                  F + F_AIJ, 512, 768LL*512, BB, 0.5f, nullptr, 0, 0, nullptr, nullptr, 1);
    launch2(g5, g7);

    tconv_bf<<<dim3(512/32, 256/32, BB), tb>>>(HI(B_AIB1), LO(B_AIB1, SZ_AIB1), 512, 256LL*512,
        HI(B_AIB1T), LO(B_AIB1T, SZ_AIB1T), 256, 512LL*256, 256, 512);

    // ---- G8 + softmax ----
    launch1(mk(768, 256, 512, HI(B_X1), LO(B_X1, SZ_X1), 512, 768LL*512,
               HI(B_AIB1), LO(B_AIB1, SZ_AIB1), 512, 256LL*512,
               F + F_S3, 256, 768LL*256, BB, scale, nullptr, 0, 0, nullptr, nullptr, 1));
    softmax_hilo<<<BB*768, 256>>>(F + F_S3, HI(B_S3), LO(B_S3, SZ_S3), 256);

    // ---- G9 ----
    launch1(mk(768, 512, 256, HI(B_S3), LO(B_S3, SZ_S3), 256, 768LL*256,
               HI(B_AIB1T), LO(B_AIB1T, SZ_AIB1T), 256, 512LL*256,
               F + F_AIJ, 512, 768LL*512, BB, 0.5f, nullptr, 1, 0,
               HI(B_CAT), LO(B_CAT, SZ_CAT), 0, nullptr, nullptr, 0, 1024, 768LL*1024));

    // ---- G10 (fused K=1024) ----
    launch1(mk(BN, 512, 1024, HI(B_CAT), LO(B_CAT, SZ_CAT), 1024, 0,
               HI(B_WFC), LO(B_WFC, SZ_WFC), 1024, 0,
               F + F_FG, 512, 0, 1, 1.0f, b_f, 0, 1, nullptr, nullptr, 1));

    // ---- G12 (act=2) ----
    launch1(mk(BN, 512, 512, HI(B_CAT), LO(B_CAT, SZ_CAT), 1024, 0,
               HI(B_WM), LO(B_WM, SZ_WM), 512, 0,
               F + F_FG, 512, 0, 1, 1.0f, b_m, 0, 2, HI(B_HB), LO(B_HB, SZ_HB), 0,
               x1, F + F_FG));

    // ---- G13: QKV -> head-split planes ----
    launch1(mk(BN, 1536, 512, HI(B_HB), LO(B_HB, SZ_HB), 512, 0,
               HI(B_WQ), LO(B_WQ, SZ_WQ), 512, 0,
               F, 1536, 0, 1, 1.0f, nullptr, 0, 0, QKVH, nullptr, 0, nullptr, nullptr, 1));

    // ---- V^T per head ----
    tconv_bf<<<dim3(64/32, 768/32, BB*HH), tb>>>(QKVH + 4*PS, QKVH + 5*PS, 64, 768LL*64,
        VT, VT + PS, 768, 64LL*768, 768, 64);

    // ---- fused flash MHSA ----
    flash_mhsa<<<dim3(BB*HH, NN_/128), 256, FL_SMEM>>>(
        QKVH, QKVH + PS, QKVH + 2*PS, QKVH + 3*PS,
        VT, VT + PS, HI(B_HC), LO(B_HC, SZ_HC));

    // ---- G16 ----
    launch1(mk(BN, 512, 512, HI(B_HC), LO(B_HC, SZ_HC), 512, 0,
               HI(B_WP), LO(B_WP, SZ_WP), 512, 0,
               out, 512, 0, 1, 1.0f, b_proj, 0, 0, nullptr, nullptr, 1));
}

// round 14
// speedup vs baseline: 2.8379x; 1.0559x over previous
#include <cuda_runtime.h>
#include <cuda_bf16.h>
#include <math.h>
#include <stdint.h>

// Problem constants
#define BB   16
#define NN_  768
#define FF   512
#define NBB  256
#define HH   8
#define DD   64

typedef __nv_bfloat16 bf16;

__device__ __forceinline__ uint32_t smem_u32(const void* p) {
    uint32_t a;
    asm("{ .reg .u64 t; cvta.to.shared.u64 t, %1; cvt.u32.u64 %0, t; }" : "=r"(a) : "l"(p));
    return a;
}

__device__ __forceinline__ void ldsm4(uint32_t* r, uint32_t addr) {
    asm volatile("ldmatrix.sync.aligned.m8n8.x4.shared.b16 {%0,%1,%2,%3}, [%4];"
        : "=r"(r[0]), "=r"(r[1]), "=r"(r[2]), "=r"(r[3]) : "r"(addr));
}

__device__ __forceinline__ void mma16816(float* c, const uint32_t* a, const uint32_t* b) {
    asm volatile(
        "mma.sync.aligned.m16n8k16.row.col.f32.bf16.bf16.f32 "
        "{%0,%1,%2,%3}, {%4,%5,%6,%7}, {%8,%9}, {%0,%1,%2,%3};"
        : "+f"(c[0]), "+f"(c[1]), "+f"(c[2]), "+f"(c[3])
        : "r"(a[0]), "r"(a[1]), "r"(a[2]), "r"(a[3]), "r"(b[0]), "r"(b[1]));
}

__device__ __forceinline__ void split_hl(float v, bf16& h, bf16& l) {
    h = __float2bfloat16(v);
    l = __float2bfloat16(v - __bfloat162float(h));
}

__device__ __forceinline__ uint32_t packb(bf16 lo16, bf16 hi16) {
    __nv_bfloat162 t; t.x = lo16; t.y = hi16;
    return *(uint32_t*)&t;
}

__device__ __forceinline__ void cp16(uint32_t d, const void* s) {
    asm volatile("cp.async.cg.shared.global [%0], [%1], 16;" :: "r"(d), "l"(s));
}
#define CP_COMMIT() asm volatile("cp.async.commit_group;" ::: "memory")
#define CP_WAIT0()  asm volatile("cp.async.wait_group 0;" ::: "memory")
#define CP_WAIT1()  asm volatile("cp.async.wait_group 1;" ::: "memory")

// ===========================================================================
// Scratch buffers
// ===========================================================================
static const long long F_S1   = 0;
static const long long F_S2   = F_S1  + 16LL*256*768;
static const long long F_S3   = F_S2  + 16LL*768*256;
static const long long F_AIJ  = F_S3  + 16LL*768*256;
static const long long F_FG   = F_AIJ + 12288LL*512;
static const long long F_TOT  = F_FG  + 12288LL*512;

__device__ float g_f32[F_TOT];

#define PS 6291456LL

static const long long B_X1    = 0;                             static const long long SZ_X1    = 12288LL*512;
static const long long B_ZB    = B_X1    + 2*SZ_X1;             static const long long SZ_ZB    = 256LL*512;
static const long long B_WB    = B_ZB    + 2*SZ_ZB;             static const long long SZ_WB    = 1536LL*512;
static const long long B_WI    = B_WB    + 2*SZ_WB;             static const long long SZ_WI    = 1024LL*512;
static const long long B_WJ    = B_WI    + 2*SZ_WI;             static const long long SZ_WJ    = 512LL*512;
static const long long B_WFC   = B_WJ    + 2*SZ_WJ;             static const long long SZ_WFC   = 512LL*1024;
static const long long B_WM    = B_WFC   + 2*SZ_WFC;            static const long long SZ_WM    = 512LL*512;
static const long long B_WQ    = B_WM    + 2*SZ_WM;             static const long long SZ_WQ    = 1536LL*512;
static const long long B_WP    = B_WQ    + 2*SZ_WQ;             static const long long SZ_WP    = 512LL*512;
static const long long B_QKVB  = B_WP    + 2*SZ_WP;             static const long long SZ_QKVB  = 256LL*1536;
static const long long B_KVI   = B_QKVB  + 2*SZ_QKVB;           static const long long SZ_KVI   = 12288LL*1024;
static const long long B_QJ    = B_KVI   + 2*SZ_KVI;            static const long long SZ_QJ    = 12288LL*512;
static const long long B_S1    = B_QJ    + 2*SZ_QJ;             static const long long SZ_S1    = 16LL*256*768;
static const long long B_VIT   = B_S1    + 2*SZ_S1;             static const long long SZ_VIT   = 16LL*512*768;
static const long long B_AIB1  = B_VIT   + 2*SZ_VIT;            static const long long SZ_AIB1  = 16LL*256*512;
static const long long B_AIB1T = B_AIB1  + 2*SZ_AIB1;           static const long long SZ_AIB1T = 16LL*512*256;
static const long long B_VBT   = B_AIB1T + 2*SZ_AIB1T;          static const long long SZ_VBT   = 512LL*256;
static const long long B_S2    = B_VBT   + 2*SZ_VBT;            static const long long SZ_S2    = 16LL*768*256;
static const long long B_S3    = B_S2    + 2*SZ_S2;             static const long long SZ_S3    = 16LL*768*256;
static const long long B_CAT   = B_S3    + 2*SZ_S3;             static const long long SZ_CAT   = 12288LL*1024;
static const long long B_HB    = B_CAT   + 2*SZ_CAT;            static const long long SZ_HB    = 12288LL*512;
static const long long B_QKVH  = B_HB    + 2*SZ_HB;
static const long long B_VT    = B_QKVH  + 6*PS;
static const long long B_HC    = B_VT    + 2*PS;                static const long long SZ_HC    = 12288LL*512;
static const long long B_TOT   = B_HC    + 2*SZ_HC;

__device__ bf16 g_bf[B_TOT];

// ===========================================================================
// GEMM descriptor + multi-GEMM dispatch (wave packing)
// ===========================================================================
#define KT 32
#define SMP 40
#define HALFB  (128 * SMP * 2)
#define STGB   (4 * HALFB)
#define GEMM_SMEM (2 * STGB)

struct GDesc {
    const bf16 *Ahi, *Alo, *Bhi, *Blo;
    int lda, ldb;
    long long sA, sB;
    float* C; int ldc; long long sC;
    float alpha; const float* bias;
    int beta, act;
    bf16 *Chi, *Clo; int wr_f32;
    const float *Gz, *Gf; int qkv;
    int ldco; long long sCo;
    int M, N, K, gx, gy, batch;
};

__device__ __forceinline__ void gemm_body(const GDesc& d, int bxi, int byi, int bzi,
                                          bf16* smbuf, int tid)
{
    const uint32_t sbase = smem_u32(smbuf);
    const int lane = tid & 31, wid = tid >> 5;
    const int m0 = byi * 128, n0 = bxi * 128;
    const int wm = wid & 3, wn = wid >> 2;
    const int m0w = wm * 32, n0w = wn * 64;

    const bf16* Ah = d.Ahi + bzi * d.sA + (size_t)m0 * d.lda;
    const bf16* Al = d.Alo + bzi * d.sA + (size_t)m0 * d.lda;
    const bf16* Bh = d.Bhi + bzi * d.sB + (size_t)n0 * d.ldb;
    const bf16* Bl = d.Blo + bzi * d.sB + (size_t)n0 * d.ldb;

    float acc[2][8][4];
    #pragma unroll
    for (int i = 0; i < 2; ++i)
        #pragma unroll
        for (int j = 0; j < 8; ++j)
            #pragma unroll
            for (int q = 0; q < 4; ++q) acc[i][j][q] = 0.0f;

    const int nk = d.K / KT;
    const int lda = d.lda, ldb = d.ldb;

    auto load_stage = [&](int st, int k0) {
        const uint32_t sb0 = sbase + st * STGB;
        #pragma unroll
        for (int it = 0; it < 2; ++it) {
            int cid = tid + it * 256;
            int row = cid >> 2;
            int c   = (cid & 3) * 8;
            uint32_t off = (uint32_t)(row * SMP + c) * 2;
            cp16(sb0 + off,              Ah + (size_t)row * lda + k0 + c);
            cp16(sb0 + HALFB + off,      Al + (size_t)row * lda + k0 + c);
            cp16(sb0 + 2 * HALFB + off,  Bh + (size_t)row * ldb + k0 + c);
            cp16(sb0 + 3 * HALFB + off,  Bl + (size_t)row * ldb + k0 + c);
        }
    };

    load_stage(0, 0);
    CP_COMMIT();

    for (int i = 0; i < nk; ++i) {
        if (i + 1 < nk) { load_stage((i + 1) & 1, (i + 1) * KT); CP_COMMIT(); }
        if (i + 1 < nk) CP_WAIT1(); else CP_WAIT0();
        __syncthreads();

        const uint32_t sa  = sbase + (i & 1) * STGB;
        const uint32_t sbm = sa + 2 * HALFB;

        #pragma unroll
        for (int kk = 0; kk < 2; ++kk) {
            uint32_t ah[2][4], al[2][4];
            #pragma unroll
            for (int mi = 0; mi < 2; ++mi) {
                uint32_t addr = sa + ((m0w + mi * 16 + (lane & 15)) * SMP
                                      + kk * 16 + (lane >> 4) * 8) * 2;
                ldsm4(ah[mi], addr);
                ldsm4(al[mi], addr + HALFB);
            }
            #pragma unroll
            for (int g = 0; g < 4; ++g) {
                uint32_t bh[4], bl[4];
                int q = lane >> 3;
                int row = n0w + g * 16 + ((q >> 1) << 3) + (lane & 7);
                int kc  = kk * 16 + (q & 1) * 8;
                uint32_t addr = sbm + (row * SMP + kc) * 2;
                ldsm4(bh, addr);
                ldsm4(bl, addr + HALFB);
                #pragma unroll
                for (int mi = 0; mi < 2; ++mi) {
                    mma16816(acc[mi][g * 2 + 0], ah[mi], bh + 0);
                    mma16816(acc[mi][g * 2 + 0], ah[mi], bl + 0);
                    mma16816(acc[mi][g * 2 + 0], al[mi], bh + 0);
                    mma16816(acc[mi][g * 2 + 1], ah[mi], bh + 2);
                    mma16816(acc[mi][g * 2 + 1], ah[mi], bl + 2);
                    mma16816(acc[mi][g * 2 + 1], al[mi], bh + 2);
                }
            }
        }
        __syncthreads();
    }

    const int rb = m0 + m0w + (lane >> 2);
    const int cb = n0 + n0w + (lane & 3) * 2;

    if (d.qkv) {
        #pragma unroll
        for (int mi = 0; mi < 2; ++mi) {
            #pragma unroll
            for (int ni = 0; ni < 8; ++ni) {
                const int col = cb + ni * 8;
                const int t = col >> 9, cw = col & 511;
                const int hh2 = cw >> 6, dd2 = cw & 63;
                bf16* ph = d.Chi + (long long)t * 2 * PS;
                #pragma unroll
                for (int h2 = 0; h2 < 2; ++h2) {
                    const int row = rb + mi * 16 + h2 * 8;
                    const int b2 = row / 768, n2 = row - b2 * 768;
                    size_t ix = ((size_t)((b2 * 8 + hh2) * 768 + n2)) * 64 + dd2;
                    float v0 = acc[mi][ni][h2 * 2 + 0] * d.alpha;
                    float v1 = acc[mi][ni][h2 * 2 + 1] * d.alpha;
                    bf16 h0, l0, h1, l1;
                    split_hl(v0, h0, l0); split_hl(v1, h1, l1);
                    *(uint32_t*)(ph + ix) = packb(h0, h1);
                    *(uint32_t*)(ph + PS + ix) = packb(l0, l1);
                }
            }
        }
        return;
    }

    float* Cb = d.C + bzi * d.sC;
    bf16* Chb = d.Chi ? d.Chi + bzi * d.sCo : nullptr;
    bf16* Clb = d.Clo ? d.Clo + bzi * d.sCo : nullptr;

    #pragma unroll
    for (int mi = 0; mi < 2; ++mi) {
        #pragma unroll
        for (int ni = 0; ni < 8; ++ni) {
            const int col = cb + ni * 8;
            if (col >= d.N) continue;
            float b0 = d.bias ? d.bias[col] : 0.0f;
            float b1 = d.bias ? d.bias[col + 1] : 0.0f;
            #pragma unroll
            for (int h = 0; h < 2; ++h) {
                const int row = rb + mi * 16 + h * 8;
                size_t ix = (size_t)row * d.ldc + col;
                float v0 = acc[mi][ni][h * 2 + 0] * d.alpha + b0;
                float v1 = acc[mi][ni][h * 2 + 1] * d.alpha + b1;
                if (d.beta) { v0 += Cb[ix]; v1 += Cb[ix + 1]; }
                if (d.act == 1) {
                    v0 = 1.0f / (1.0f + __expf(-v0));
                    v1 = 1.0f / (1.0f + __expf(-v1));
                } else if (d.act == 2) {
                    v0 = fmaxf(0.0f, d.Gz[ix] + v0 * d.Gf[ix]);
                    v1 = fmaxf(0.0f, d.Gz[ix + 1] + v1 * d.Gf[ix + 1]);
                }
                if (d.wr_f32) { Cb[ix] = v0; Cb[ix + 1] = v1; }
                if (Chb) {
                    size_t ixo = (size_t)row * d.ldco + col;
                    bf16 hh, ll;
                    split_hl(v0, hh, ll); Chb[ixo] = hh; Clb[ixo] = ll;
                    split_hl(v1, hh, ll); Chb[ixo + 1] = hh; Clb[ixo + 1] = ll;
                }
            }
        }
    }
}

__global__ void __launch_bounds__(256, 2)
mma_multi(GDesc d0, GDesc d1, GDesc d2, int n1, int n2)
{
    extern __shared__ bf16 smbuf[];
    const GDesc& d = (blockIdx.x < (unsigned)n1) ? d0
                   : ((blockIdx.x < (unsigned)n2) ? d1 : d2);
    int local = (blockIdx.x < (unsigned)n1) ? blockIdx.x
              : ((blockIdx.x < (unsigned)n2) ? blockIdx.x - n1 : blockIdx.x - n2);
    int per = d.gx * d.gy;
    int bzi = local / per;
    int rem = local - bzi * per;
    int byi = rem / d.gx;
    int bxi = rem - byi * d.gx;
    gemm_body(d, bxi, byi, bzi, smbuf, threadIdx.x);
}

// ===========================================================================
// Fused flash MHSA — cp.async double-buffered K/V stages
// ===========================================================================
#define QPITCH 72
#define VPITCH 136
#define QPL (128 * QPITCH)            // elements per K/Q plane
#define VPL (64 * VPITCH)             // elements per V plane
#define FL_SMEM ((6 * QPL + 4 * VPL) * 2)   // 180224 bytes

__global__ void __launch_bounds__(256)
flash_mhsa(const bf16* __restrict__ Qhp, const bf16* __restrict__ Qlp,
           const bf16* __restrict__ Khp, const bf16* __restrict__ Klp,
           const bf16* __restrict__ VThp, const bf16* __restrict__ VTlp,
           bf16* __restrict__ Ohi, bf16* __restrict__ Olo)
{
    extern __shared__ char sm[];
    const uint32_t base = smem_u32(sm);
    const uint32_t uQ = base;                                 // Qh | Ql
    const uint32_t uK0 = base + 2 * QPL * 2;                  // K stage 0: Kh | Kl
    const uint32_t uV0 = base + 6 * QPL * 2;                  // V stage 0: Vh | Vl
    const uint32_t KSTG = 2 * QPL * 2;
    const uint32_t VSTG = 2 * VPL * 2;
    const uint32_t QHALF = QPL * 2;
    const uint32_t VHALF = VPL * 2;

    const int bh = blockIdx.x;
    const int mb = blockIdx.y;
    const int tid = threadIdx.x, lane = tid & 31, wid = tid >> 5;

    const size_t qoff = (size_t)bh * 768 * 64 + (size_t)mb * 128 * 64;
    const size_t koff = (size_t)bh * 768 * 64;
    const size_t voff = (size_t)bh * 64 * 768;

    auto load_kv = [&](int st, int it) {
        const uint32_t uk = uK0 + st * KSTG;
        const uint32_t uv = uV0 + st * VSTG;
        for (int i = tid; i < 1024; i += 256) {
            int r = i >> 3, c = (i & 7) * 8;
            uint32_t dst = uk + (uint32_t)(r * QPITCH + c) * 2;
            cp16(dst,          Khp + koff + (size_t)(it * 128 + r) * 64 + c);
            cp16(dst + QHALF,  Klp + koff + (size_t)(it * 128 + r) * 64 + c);
        }
        for (int i = tid; i < 1024; i += 256) {
            int r = i >> 4, c = (i & 15) * 8;
            uint32_t dst = uv + (uint32_t)(r * VPITCH + c) * 2;
            cp16(dst,          VThp + voff + (size_t)r * 768 + it * 128 + c);
            cp16(dst + VHALF,  VTlp + voff + (size_t)r * 768 + it * 128 + c);
        }
    };

    // Q + first K/V stage in one async group
    for (int i = tid; i < 1024; i += 256) {
        int r = i >> 3, c = (i & 7) * 8;
        uint32_t dst = uQ + (uint32_t)(r * QPITCH + c) * 2;
        cp16(dst,          Qhp + qoff + (size_t)r * 64 + c);
        cp16(dst + QHALF,  Qlp + qoff + (size_t)r * 64 + c);
    }
    load_kv(0, 0);
    CP_COMMIT();

    float m_r[2] = {-1e30f, -1e30f};
    float l_r[2] = {0.0f, 0.0f};
    float oacc[8][4];
    #pragma unroll
    for (int j = 0; j < 8; ++j)
        #pragma unroll
        for (int q = 0; q < 4; ++q) oacc[j][q] = 0.0f;

    for (int it = 0; it < 6; ++it) {
        if (it + 1 < 6) { load_kv((it + 1) & 1, it + 1); CP_COMMIT(); }
        if (it + 1 < 6) CP_WAIT1(); else CP_WAIT0();
        __syncthreads();

        const uint32_t uK = uK0 + (it & 1) * KSTG;
        const uint32_t uV = uV0 + (it & 1) * VSTG;

        float sacc[16][4];
        #pragma unroll
        for (int g = 0; g < 16; ++g)
            #pragma unroll
            for (int q = 0; q < 4; ++q) sacc[g][q] = 0.0f;

        #pragma unroll
        for (int kk = 0; kk < 4; ++kk) {
            uint32_t ah[4], al[4];
            uint32_t addr = uQ + ((wid * 16 + (lane & 15)) * QPITCH
                                  + kk * 16 + (lane >> 4) * 8) * 2;
            ldsm4(ah, addr);
            ldsm4(al, addr + QHALF);
            #pragma unroll
            for (int g = 0; g < 8; ++g) {
                uint32_t bh4[4], bl4[4];
                int q = lane >> 3;
                int row = g * 16 + ((q >> 1) << 3) + (lane & 7);
                int kc  = kk * 16 + (q & 1) * 8;
                uint32_t ba = uK + (row * QPITCH + kc) * 2;
                ldsm4(bh4, ba);
                ldsm4(bl4, ba + QHALF);
                mma16816(sacc[g * 2 + 0], ah, bh4 + 0);
                mma16816(sacc[g * 2 + 0], ah, bl4 + 0);
                mma16816(sacc[g * 2 + 0], al, bh4 + 0);
                mma16816(sacc[g * 2 + 1], ah, bh4 + 2);
                mma16816(sacc[g * 2 + 1], ah, bl4 + 2);
                mma16816(sacc[g * 2 + 1], al, bh4 + 2);
            }
        }

        float mx0 = -1e30f, mx1 = -1e30f;
        #pragma unroll
        for (int g = 0; g < 16; ++g) {
            sacc[g][0] *= 0.125f; sacc[g][1] *= 0.125f;
            sacc[g][2] *= 0.125f; sacc[g][3] *= 0.125f;
            mx0 = fmaxf(mx0, fmaxf(sacc[g][0], sacc[g][1]));
            mx1 = fmaxf(mx1, fmaxf(sacc[g][2], sacc[g][3]));
        }
        #pragma unroll
        for (int d = 1; d <= 2; d <<= 1) {
            mx0 = fmaxf(mx0, __shfl_xor_sync(0xffffffffu, mx0, d));
            mx1 = fmaxf(mx1, __shfl_xor_sync(0xffffffffu, mx1, d));
        }
        float mn0 = fmaxf(m_r[0], mx0), mn1 = fmaxf(m_r[1], mx1);
        float al0 = __expf(m_r[0] - mn0), al1 = __expf(m_r[1] - mn1);
        float sum0 = 0.0f, sum1 = 0.0f;
        #pragma unroll
        for (int g = 0; g < 16; ++g) {
            sacc[g][0] = __expf(sacc[g][0] - mn0);
            sacc[g][1] = __expf(sacc[g][1] - mn0);
            sacc[g][2] = __expf(sacc[g][2] - mn1);
            sacc[g][3] = __expf(sacc[g][3] - mn1);
            sum0 += sacc[g][0] + sacc[g][1];
            sum1 += sacc[g][2] + sacc[g][3];
        }
        #pragma unroll
        for (int d = 1; d <= 2; d <<= 1) {
            sum0 += __shfl_xor_sync(0xffffffffu, sum0, d);
            sum1 += __shfl_xor_sync(0xffffffffu, sum1, d);
        }
        l_r[0] = l_r[0] * al0 + sum0;
        l_r[1] = l_r[1] * al1 + sum1;
        m_r[0] = mn0; m_r[1] = mn1;
        #pragma unroll
        for (int j = 0; j < 8; ++j) {
            oacc[j][0] *= al0; oacc[j][1] *= al0;
            oacc[j][2] *= al1; oacc[j][3] *= al1;
        }

        #pragma unroll
        for (int s = 0; s < 8; ++s) {
            uint32_t pah[4], pal[4];
            {
                bf16 h0, l0, h1, l1;
                split_hl(sacc[2*s][0], h0, l0); split_hl(sacc[2*s][1], h1, l1);
                pah[0] = packb(h0, h1); pal[0] = packb(l0, l1);
                split_hl(sacc[2*s][2], h0, l0); split_hl(sacc[2*s][3], h1, l1);
                pah[1] = packb(h0, h1); pal[1] = packb(l0, l1);
                split_hl(sacc[2*s+1][0], h0, l0); split_hl(sacc[2*s+1][1], h1, l1);
                pah[2] = packb(h0, h1); pal[2] = packb(l0, l1);
                split_hl(sacc[2*s+1][2], h0, l0); split_hl(sacc[2*s+1][3], h1, l1);
                pah[3] = packb(h0, h1); pal[3] = packb(l0, l1);
            }
            #pragma unroll
            for (int g = 0; g < 4; ++g) {
                uint32_t bh4[4], bl4[4];
                int q = lane >> 3;
                int row = g * 16 + ((q >> 1) << 3) + (lane & 7);
                int kc  = s * 16 + (q & 1) * 8;
                uint32_t ba = uV + (row * VPITCH + kc) * 2;
                ldsm4(bh4, ba);
                ldsm4(bl4, ba + VHALF);
                mma16816(oacc[g * 2 + 0], pah, bh4 + 0);
                mma16816(oacc[g * 2 + 0], pah, bl4 + 0);
                mma16816(oacc[g * 2 + 0], pal, bh4 + 0);
                mma16816(oacc[g * 2 + 1], pah, bh4 + 2);
                mma16816(oacc[g * 2 + 1], pah, bl4 + 2);
                mma16816(oacc[g * 2 + 1], pal, bh4 + 2);
            }
        }
        __syncthreads();
    }

    const float inv0 = 1.0f / l_r[0], inv1 = 1.0f / l_r[1];
    const int b = bh >> 3, h = bh & 7;
    const int n0g = mb * 128 + wid * 16 + (lane >> 2);
    #pragma unroll
    for (int j = 0; j < 8; ++j) {
        const int d = j * 8 + (lane & 3) * 2;
        {
            size_t ix = ((size_t)(b * 768 + n0g) * 512) + h * 64 + d;
            bf16 h0, l0, h1, l1;
            split_hl(oacc[j][0] * inv0, h0, l0);
            split_hl(oacc[j][1] * inv0, h1, l1);
            *(uint32_t*)(Ohi + ix) = packb(h0, h1);
            *(uint32_t*)(Olo + ix) = packb(l0, l1);
        }
        {
            size_t ix = ((size_t)(b * 768 + n0g + 8) * 512) + h * 64 + d;
            bf16 h0, l0, h1, l1;
            split_hl(oacc[j][2] * inv1, h0, l0);
            split_hl(oacc[j][3] * inv1, h1, l1);
            *(uint32_t*)(Ohi + ix) = packb(h0, h1);
            *(uint32_t*)(Olo + ix) = packb(l0, l1);
        }
    }
}

// ===========================================================================
// Conversion / transform kernels
// ===========================================================================
struct CTable {
    const float* src[3];
    bf16* hi[3];
    bf16* lo[3];
    int lds[3], ldd[3], C[3];
    long long n1, n2;
};

__global__ void conv_batch(CTable ct)
{
    long long i = (long long)blockIdx.x * blockDim.x + threadIdx.x;
    int e; long long local;
    if (i < ct.n1) { e = 0; local = i; }
    else if (i < ct.n2) { e = 1; local = i - ct.n1; }
    else { e = 2; local = i - ct.n2; }
    int c4 = ct.C[e] / 4;
    int r = (int)(local / c4), c = (int)(local % c4) * 4;
    float4 v = *(const float4*)(ct.src[e] + (size_t)r * ct.lds[e] + c);
    bf16 h0, h1, h2, h3, l0, l1, l2, l3;
    split_hl(v.x, h0, l0); split_hl(v.y, h1, l1);
    split_hl(v.z, h2, l2); split_hl(v.w, h3, l3);
    size_t o = (size_t)r * ct.ldd[e] + c;
    bf16* hi = ct.hi[e]; bf16* lo = ct.lo[e];
    hi[o] = h0; hi[o+1] = h1; hi[o+2] = h2; hi[o+3] = h3;
    lo[o] = l0; lo[o+1] = l1; lo[o+2] = l2; lo[o+3] = l3;
}

struct TTable {
    const float* src[8];
    bf16* hi[8];
    bf16* lo[8];
    int lds[8];
    int ldd[8];
    int C[8];
};

__global__ void tconv_batch(TTable tt)
{
    __shared__ float t[32][33];
    const int e = blockIdx.z;
    const int c0 = blockIdx.x * 32;
    if (c0 >= tt.C[e]) return;
    const float* s = tt.src[e];
    const int lds = tt.lds[e], ldd = tt.ldd[e];
    const int r0 = blockIdx.y * 32;
    int tx = threadIdx.x, ty = threadIdx.y;
    #pragma unroll
    for (int i = 0; i < 32; i += 8) {
        int r = r0 + ty + i, c = c0 + tx;
        t[ty + i][tx] = s[(size_t)r * lds + c];
    }
    __syncthreads();
    bf16* hb = tt.hi[e];
    bf16* lb = tt.lo[e];
    #pragma unroll
    for (int i = 0; i < 32; i += 8) {
        int c = c0 + ty + i, r = r0 + tx;
        bf16 h, l; split_hl(t[tx][ty + i], h, l);
        hb[(size_t)c * ldd + r] = h;
        lb[(size_t)c * ldd + r] = l;
    }
}

__global__ void tconv_bf(const bf16* __restrict__ sh, const bf16* __restrict__ sl,
                         int lds, long long sS,
                         bf16* __restrict__ dh, bf16* __restrict__ dl,
                         int ldd, long long sD, int R, int C)
{
    __shared__ uint32_t t[32][33];
    const bf16* ph = sh + blockIdx.z * sS;
    const bf16* pl = sl + blockIdx.z * sS;
    int r0 = blockIdx.y * 32, c0 = blockIdx.x * 32;
    int tx = threadIdx.x, ty = threadIdx.y;
    #pragma unroll
    for (int i = 0; i < 32; i += 8) {
        int r = r0 + ty + i, c = c0 + tx;
        t[ty + i][tx] = packb(ph[(size_t)r * lds + c], pl[(size_t)r * lds + c]);
    }
    __syncthreads();
    bf16* hb = dh + blockIdx.z * sD;
    bf16* lb = dl + blockIdx.z * sD;
    #pragma unroll
    for (int i = 0; i < 32; i += 8) {
        int c = c0 + ty + i, r = r0 + tx;
        uint32_t u = t[tx][ty + i];
        __nv_bfloat162 p = *(__nv_bfloat162*)&u;
        hb[(size_t)c * ldd + r] = p.x;
        lb[(size_t)c * ldd + r] = p.y;
    }
}

// merged v_i (z=0..15) + v_b (z=16) transpose
__global__ void tconv_vbvi(const bf16* __restrict__ kvi_h, const bf16* __restrict__ kvi_l,
                           bf16* __restrict__ vit_h, bf16* __restrict__ vit_l,
                           const bf16* __restrict__ qkvb_h, const bf16* __restrict__ qkvb_l,
                           bf16* __restrict__ vbt_h, bf16* __restrict__ vbt_l)
{
    __shared__ uint32_t t[32][33];
    const int z = blockIdx.z;
    const bf16 *ph, *pl; bf16 *hb, *lb;
    int lds, ldd, R;
    if (z < 16) {
        ph = kvi_h + (size_t)z * 768 * 1024; pl = kvi_l + (size_t)z * 768 * 1024;
        hb = vit_h + (size_t)z * 512 * 768;  lb = vit_l + (size_t)z * 512 * 768;
        lds = 1024; ldd = 768; R = 768;
    } else {
        ph = qkvb_h; pl = qkvb_l;
        hb = vbt_h;  lb = vbt_l;
        lds = 1536; ldd = 256; R = 256;
    }
    int r0 = blockIdx.y * 32, c0 = blockIdx.x * 32;
    if (r0 >= R) return;
    int tx = threadIdx.x, ty = threadIdx.y;
    #pragma unroll
    for (int i = 0; i < 32; i += 8) {
        int r = r0 + ty + i, c = c0 + tx;
        t[ty + i][tx] = packb(ph[(size_t)r * lds + c], pl[(size_t)r * lds + c]);
    }
    __syncthreads();
    #pragma unroll
    for (int i = 0; i < 32; i += 8) {
        int c = c0 + ty + i, r = r0 + tx;
        uint32_t u = t[tx][ty + i];
        __nv_bfloat162 p = *(__nv_bfloat162*)&u;
        hb[(size_t)c * ldd + r] = p.x;
        lb[(size_t)c * ldd + r] = p.y;
    }
}

__device__ __forceinline__ void softmax_body(const float* p, bf16* ph, bf16* pl, int L, int t)
{
    __shared__ float red[256];
    const int nv = L >> 8;
    float v[3];
    float mx = -1e30f;
    for (int j = 0; j < nv; ++j) {
        v[j] = p[t + (j << 8)];
        mx = fmaxf(mx, v[j]);
    }
    red[t] = mx; __syncthreads();
    for (int s = 128; s > 0; s >>= 1) { if (t < s) red[t] = fmaxf(red[t], red[t + s]); __syncthreads(); }
    mx = red[0]; __syncthreads();

    float e[3];
    float sum = 0.0f;
    for (int j = 0; j < nv; ++j) {
        e[j] = __expf(v[j] - mx);
        sum += e[j];
    }
    red[t] = sum; __syncthreads();
    for (int s = 128; s > 0; s >>= 1) { if (t < s) red[t] += red[t + s]; __syncthreads(); }
    const float inv = 1.0f / red[0];
    for (int j = 0; j < nv; ++j) {
        float w = e[j] * inv;
        bf16 h, l; split_hl(w, h, l);
        ph[t + (j << 8)] = h; pl[t + (j << 8)] = l;
    }
}

__global__ void __launch_bounds__(256)
softmax_hilo(const float* __restrict__ src, bf16* __restrict__ hi, bf16* __restrict__ lo, int L)
{
    softmax_body(src + (size_t)blockIdx.x * L, hi + (size_t)blockIdx.x * L,
                 lo + (size_t)blockIdx.x * L, L, threadIdx.x);
}

// merged softmax over two tensors
__global__ void __launch_bounds__(256)
softmax2(const float* __restrict__ s1, bf16* __restrict__ h1, bf16* __restrict__ l1,
         int L1, int nb1,
         const float* __restrict__ s2, bf16* __restrict__ h2, bf16* __restrict__ l2, int L2)
{
    if (blockIdx.x < (unsigned)nb1) {
        size_t o = (size_t)blockIdx.x * L1;
        softmax_body(s1 + o, h1 + o, l1 + o, L1, threadIdx.x);
    } else {
        size_t o = (size_t)(blockIdx.x - nb1) * L2;
        softmax_body(s2 + o, h2 + o, l2 + o, L2, threadIdx.x);
    }
}

// ===========================================================================
// Host side
// ===========================================================================
static GDesc mk(int M, int N, int K,
                const bf16* Ah, const bf16* Al, int lda, long long sA,
                const bf16* Bh, const bf16* Bl, int ldb, long long sB,
                float* C, int ldc, long long sC, int batch,
                float alpha, const float* bias, int beta, int act,
                bf16* Chi, bf16* Clo, int wr_f32,
                const float* Gz = nullptr, const float* Gf = nullptr, int qkv = 0,
                int ldco = -1, long long sCo = -1)
{
    GDesc d;
    d.Ahi = Ah; d.Alo = Al; d.Bhi = Bh; d.Blo = Bl;
    d.lda = lda; d.ldb = ldb; d.sA = sA; d.sB = sB;
    d.C = C; d.ldc = ldc; d.sC = sC;
    d.alpha = alpha; d.bias = bias; d.beta = beta; d.act = act;
    d.Chi = Chi; d.Clo = Clo; d.wr_f32 = wr_f32;
    d.Gz = Gz; d.Gf = Gf; d.qkv = qkv;
    d.ldco = (ldco < 0) ? ldc : ldco;
    d.sCo = (sCo < 0) ? sC : sCo;
    d.M = M; d.N = N; d.K = K;
    d.gx = (N + 127) / 128; d.gy = M / 128; d.batch = batch;
    return d;
}
static inline int nblk(const GDesc& d) { return d.gx * d.gy * d.batch; }

static void launch1(const GDesc& a) {
    int n = nblk(a);
    mma_multi<<<n, 256, GEMM_SMEM>>>(a, a, a, n, n);
}
static void launch2(const GDesc& a, const GDesc& b) {
    int na = nblk(a), nb = nblk(b);
    mma_multi<<<na + nb, 256, GEMM_SMEM>>>(a, b, b, na, na + nb);
}
static void launch3(const GDesc& a, const GDesc& b, const GDesc& c) {
    int na = nblk(a), nb = nblk(b), nc = nblk(c);
    mma_multi<<<na + nb + nc, 256, GEMM_SMEM>>>(a, b, c, na, na + nb);
}

extern "C" void kernel_launch(void* const* d_in, const int* in_sizes, int n_in,
                              void* d_out, int out_size)
{
    (void)in_sizes; (void)n_in; (void)out_size;

    cudaFuncSetAttribute(flash_mhsa, cudaFuncAttributeMaxDynamicSharedMemorySize, FL_SMEM);
    cudaFuncSetAttribute(mma_multi, cudaFuncAttributeMaxDynamicSharedMemorySize, GEMM_SMEM);

    float* F = nullptr; bf16* Bf = nullptr;
    cudaGetSymbolAddress((void**)&F, g_f32);
    cudaGetSymbolAddress((void**)&Bf, g_bf);

    const float* x1     = (const float*)d_in[0];
    const float* x2     = (const float*)d_in[1];
    const float* zb     = (const float*)d_in[2];
    const float* Wqkv_i = (const float*)d_in[3];
    const float* Wqkv_j = (const float*)d_in[4];
    const float* Wqkv_b = (const float*)d_in[5];
    const float* W_f    = (const float*)d_in[6];
    const float* b_f    = (const float*)d_in[7];
    const float* W_m    = (const float*)d_in[8];
    const float* b_m    = (const float*)d_in[9];
    const float* W_QKV  = (const float*)d_in[10];
    const float* W_proj = (const float*)d_in[11];
    const float* b_proj = (const float*)d_in[12];
    float* out = (float*)d_out;

    const float scale = 0.044194173824159216f;
    const int   BN    = BB * NN_;

    #define HI(X) (Bf + (X))
    #define LO(X, SZ) (Bf + (X) + (SZ))

    bf16* QKVH = Bf + B_QKVH;
    bf16* VT   = Bf + B_VT;

    // ---- input conversions ----
    {
        CTable ct;
        ct.src[0] = x1; ct.hi[0] = HI(B_X1);        ct.lo[0] = LO(B_X1, SZ_X1);        ct.lds[0] = 512; ct.ldd[0] = 512;  ct.C[0] = 512;
        ct.src[1] = x2; ct.hi[1] = HI(B_CAT) + 512; ct.lo[1] = LO(B_CAT, SZ_CAT) + 512; ct.lds[1] = 512; ct.ldd[1] = 1024; ct.C[1] = 512;
        ct.src[2] = zb; ct.hi[2] = HI(B_ZB);        ct.lo[2] = LO(B_ZB, SZ_ZB);        ct.lds[2] = 512; ct.ldd[2] = 512;  ct.C[2] = 512;
        ct.n1 = 12288LL * 128;
        ct.n2 = ct.n1 + 12288LL * 128;
        long long tot = ct.n2 + 256LL * 128;
        conv_batch<<<(unsigned)((tot + 255) / 256), 256>>>(ct);
    }

    // ---- all weight transposes in ONE batched launch ----
    {
        TTable tt;
        tt.src[0] = Wqkv_b;           tt.hi[0] = HI(B_WB);        tt.lo[0] = LO(B_WB, SZ_WB);         tt.lds[0] = 1536; tt.ldd[0] = 512;  tt.C[0] = 1536;
        tt.src[1] = Wqkv_i + 512;     tt.hi[1] = HI(B_WI);        tt.lo[1] = LO(B_WI, SZ_WI);         tt.lds[1] = 1536; tt.ldd[1] = 512;  tt.C[1] = 1024;
        tt.src[2] = Wqkv_j;           tt.hi[2] = HI(B_WJ);        tt.lo[2] = LO(B_WJ, SZ_WJ);         tt.lds[2] = 1536; tt.ldd[2] = 512;  tt.C[2] = 512;
        tt.src[3] = W_f;              tt.hi[3] = HI(B_WFC);       tt.lo[3] = LO(B_WFC, SZ_WFC);       tt.lds[3] = 512;  tt.ldd[3] = 1024; tt.C[3] = 512;
        tt.src[4] = W_f + 512LL*512;  tt.hi[4] = HI(B_WFC) + 512; tt.lo[4] = LO(B_WFC, SZ_WFC) + 512; tt.lds[4] = 512;  tt.ldd[4] = 1024; tt.C[4] = 512;
        tt.src[5] = W_m;              tt.hi[5] = HI(B_WM);        tt.lo[5] = LO(B_WM, SZ_WM);         tt.lds[5] = 512;  tt.ldd[5] = 512;  tt.C[5] = 512;
        tt.src[6] = W_QKV;            tt.hi[6] = HI(B_WQ);        tt.lo[6] = LO(B_WQ, SZ_WQ);         tt.lds[6] = 1536; tt.ldd[6] = 512;  tt.C[6] = 1536;
        tt.src[7] = W_proj;           tt.hi[7] = HI(B_WP);        tt.lo[7] = LO(B_WP, SZ_WP);         tt.lds[7] = 512;  tt.ldd[7] = 512;  tt.C[7] = 512;
        tconv_batch<<<dim3(1536/32, 512/32, 8), dim3(32, 8)>>>(tt);
    }

    dim3 tb(32, 8);

    // ---- Group A: G1 + G2 + G3 ----
    GDesc g1 = mk(256, 1536, 512, HI(B_ZB), LO(B_ZB, SZ_ZB), 512, 0, HI(B_WB), LO(B_WB, SZ_WB), 512, 0,
                  F, 1536, 0, 1, 0.2f, nullptr, 0, 0, HI(B_QKVB), LO(B_QKVB, SZ_QKVB), 0);
    GDesc g2 = mk(BN, 1024, 512, HI(B_X1), LO(B_X1, SZ_X1), 512, 0, HI(B_WI), LO(B_WI, SZ_WI), 512, 0,
                  F, 1024, 0, 1, 1.0f, nullptr, 0, 0, HI(B_KVI), LO(B_KVI, SZ_KVI), 0);
    GDesc g3 = mk(BN, 512, 512, HI(B_CAT) + 512, LO(B_CAT, SZ_CAT) + 512, 1024, 0,
                  HI(B_WJ), LO(B_WJ, SZ_WJ), 512, 0,
                  F, 512, 0, 1, 1.0f, nullptr, 0, 0, HI(B_QJ), LO(B_QJ, SZ_QJ), 0);
    launch3(g2, g3, g1);

    // ---- merged v_b + v_i transposes ----
    tconv_vbvi<<<dim3(16, 24, 17), tb>>>(
        HI(B_KVI) + 512, LO(B_KVI, SZ_KVI) + 512, HI(B_VIT), LO(B_VIT, SZ_VIT),
        HI(B_QKVB) + 1024, LO(B_QKVB, SZ_QKVB) + 1024, HI(B_VBT), LO(B_VBT, SZ_VBT));

    // ---- Group B: G4 + G6 ----
    GDesc g4 = mk(256, 768, 512, HI(B_QKVB), LO(B_QKVB, SZ_QKVB), 1536, 0,
                  HI(B_KVI), LO(B_KVI, SZ_KVI), 1024, 768LL*1024,
                  F + F_S1, 768, 256LL*768, BB, scale, nullptr, 0, 0, nullptr, nullptr, 1);
    GDesc g6 = mk(768, 256, 512, HI(B_QJ), LO(B_QJ, SZ_QJ), 512, 768LL*512,
                  HI(B_QKVB) + 512, LO(B_QKVB, SZ_QKVB) + 512, 1536, 0,
                  F + F_S2, 256, 768LL*256, BB, scale, nullptr, 0, 0, nullptr, nullptr, 1);
    launch2(g4, g6);

    // ---- merged softmax S1 + S2 ----
    softmax2<<<BB*256 + BB*768, 256>>>(
        F + F_S1, HI(B_S1), LO(B_S1, SZ_S1), 768, BB*256,
        F + F_S2, HI(B_S2), LO(B_S2, SZ_S2), 256);

    // ---- Group C: G5 + G7 ----
    GDesc g5 = mk(256, 512, 768, HI(B_S1), LO(B_S1, SZ_S1), 768, 256LL*768,
                  HI(B_VIT), LO(B_VIT, SZ_VIT), 768, 512LL*768,
                  F, 512, 256LL*512, BB, 1.0f, nullptr, 0, 0, HI(B_AIB1), LO(B_AIB1, SZ_AIB1), 0);
    GDesc g7 = mk(768, 512, 256, HI(B_S2), LO(B_S2, SZ_S2), 256, 768LL*256,
                  HI(B_VBT), LO(B_VBT, SZ_VBT), 256, 0,
                  F + F_AIJ, 512, 768LL*512, BB, 0.5f, nullptr, 0, 0, nullptr, nullptr, 1);
    launch2(g5, g7);

    tconv_bf<<<dim3(512/32, 256/32, BB), tb>>>(HI(B_AIB1), LO(B_AIB1, SZ_AIB1), 512, 256LL*512,
        HI(B_AIB1T), LO(B_AIB1T, SZ_AIB1T), 256, 512LL*256, 256, 512);

    // ---- G8 + softmax ----
    launch1(mk(768, 256, 512, HI(B_X1), LO(B_X1, SZ_X1), 512, 768LL*512,
               HI(B_AIB1), LO(B_AIB1, SZ_AIB1), 512, 256LL*512,
               F + F_S3, 256, 768LL*256, BB, scale, nullptr, 0, 0, nullptr, nullptr, 1));
    softmax_hilo<<<BB*768, 256>>>(F + F_S3, HI(B_S3), LO(B_S3, SZ_S3), 256);

    // ---- G9 ----
    launch1(mk(768, 512, 256, HI(B_S3), LO(B_S3, SZ_S3), 256, 768LL*256,
               HI(B_AIB1T), LO(B_AIB1T, SZ_AIB1T), 256, 512LL*256,
               F + F_AIJ, 512, 768LL*512, BB, 0.5f, nullptr, 1, 0,
               HI(B_CAT), LO(B_CAT, SZ_CAT), 0, nullptr, nullptr, 0, 1024, 768LL*1024));

    // ---- G10 (fused K=1024) ----
    launch1(mk(BN, 512, 1024, HI(B_CAT), LO(B_CAT, SZ_CAT), 1024, 0,
               HI(B_WFC), LO(B_WFC, SZ_WFC), 1024, 0,
               F + F_FG, 512, 0, 1, 1.0f, b_f, 0, 1, nullptr, nullptr, 1));

    // ---- G12 (act=2) ----
    launch1(mk(BN, 512, 512, HI(B_CAT), LO(B_CAT, SZ_CAT), 1024, 0,
               HI(B_WM), LO(B_WM, SZ_WM), 512, 0,
               F + F_FG, 512, 0, 1, 1.0f, b_m, 0, 2, HI(B_HB), LO(B_HB, SZ_HB), 0,
               x1, F + F_FG));

    // ---- G13: QKV -> head-split planes ----
    launch1(mk(BN, 1536, 512, HI(B_HB), LO(B_HB, SZ_HB), 512, 0,
               HI(B_WQ), LO(B_WQ, SZ_WQ), 512, 0,
               F, 1536, 0, 1, 1.0f, nullptr, 0, 0, QKVH, nullptr, 0, nullptr, nullptr, 1));

    // ---- V^T per head ----
    tconv_bf<<<dim3(64/32, 768/32, BB*HH), tb>>>(QKVH + 4*PS, QKVH + 5*PS, 64, 768LL*64,
        VT, VT + PS, 768, 64LL*768, 768, 64);

    // ---- fused flash MHSA (cp.async pipelined) ----
    flash_mhsa<<<dim3(BB*HH, NN_/128), 256, FL_SMEM>>>(
        QKVH, QKVH + PS, QKVH + 2*PS, QKVH + 3*PS,
        VT, VT + PS, HI(B_HC), LO(B_HC, SZ_HC));

    // ---- G16 ----
    launch1(mk(BN, 512, 512, HI(B_HC), LO(B_HC, SZ_HC), 512, 0,
               HI(B_WP), LO(B_WP, SZ_WP), 512, 0,
               out, 512, 0, 1, 1.0f, b_proj, 0, 0, nullptr, nullptr, 1));
}